// round 7
// baseline (speedup 1.0000x reference)
#include <cuda_runtime.h>
#include <cstdint>

constexpr int BB  = 8;
constexpr int CC  = 512;
constexpr int LL  = 64;
constexpr int NHW = 4096;

#define GAIN_IN 0.04419417382415922f
#define GAIN_O  0.125f

// -------- device scratch --------
__device__ float g_qhi[BB * NHW * LL];
__device__ float g_qlo[BB * NHW * LL];
__device__ float g_khi[BB * NHW * LL];
__device__ float g_klo[BB * NHW * LL];
__device__ float g_gv [BB * LL * NHW];
__device__ float g_lat[BB * NHW * LL];
__device__ float g_sa [BB * CC * NHW];
__device__ float g_enc[BB * LL * NHW];
__device__ float g_lat2[BB * NHW * LL];

extern __shared__ char dyn_smem[];

// ============================================================
// helpers
// ============================================================
__device__ __forceinline__ uint32_t smem_u32(const void* p) {
    uint32_t r;
    asm("{ .reg .u64 t; cvta.to.shared.u64 t, %1; cvt.u32.u64 %0, t; }" : "=r"(r) : "l"(p));
    return r;
}
__device__ __forceinline__ void cp16(uint32_t dst, const void* src) {
    asm volatile("cp.async.cg.shared.global [%0], [%1], 16;" :: "r"(dst), "l"(src));
}
#define CP_COMMIT() asm volatile("cp.async.commit_group;" ::: "memory")
#define CP_WAIT(n)  asm volatile("cp.async.wait_group %0;" :: "n"(n) : "memory")

__device__ __forceinline__ float tf32hi(float v) {
    float h;
    asm("cvt.rna.tf32.f32 %0, %1;" : "=f"(h) : "f"(v));
    return h;
}
__device__ __forceinline__ void mma168(float* d, const uint32_t* a, uint32_t b0, uint32_t b1) {
    asm volatile(
        "mma.sync.aligned.m16n8k8.row.col.f32.tf32.tf32.f32 "
        "{%0,%1,%2,%3}, {%4,%5,%6,%7}, {%8,%9}, {%0,%1,%2,%3};"
        : "+f"(d[0]), "+f"(d[1]), "+f"(d[2]), "+f"(d[3])
        : "r"(a[0]), "r"(a[1]), "r"(a[2]), "r"(a[3]), "r"(b0), "r"(b1));
}

// ============================================================
// flash attention via mma.sync tf32 — 256 threads, 8 warps,
// 16 q rows per warp (2 warps per SMSP for tensor/MUFU overlap)
// ============================================================
constexpr int PAD = 68;
constexpr int QTILE_F = 128 * PAD;
constexpr int KVROW_F = 64 * PAD;
constexpr int OFF_QH = 0;
constexpr int OFF_QL = QTILE_F;
constexpr int OFF_KV = 2 * QTILE_F;
constexpr int SLOT_F = 3 * KVROW_F;
#define FT_SMEM ((2 * QTILE_F + 2 * SLOT_F) * 4)

__device__ __forceinline__ void prefetch_kv(
    uint32_t slot_base, const float* Khi, const float* Klo, const float* Vg,
    int b, int m0, int tid)
{
    const uint32_t kh = slot_base;
    const uint32_t kl = slot_base + KVROW_F * 4;
    const uint32_t vt = slot_base + 2 * KVROW_F * 4;
    const size_t krow0 = (size_t)(b * NHW + m0);
#pragma unroll
    for (int j = 0; j < 4; j++) {
        int idx = j * 256 + tid;          // 0..1023
        int r = idx >> 4, c4 = idx & 15;
        uint32_t doff = (uint32_t)(r * PAD * 4 + c4 * 16);
        size_t ksrc = (krow0 + r) * 64 + c4 * 4;
        cp16(kh + doff, Khi + ksrc);
        cp16(kl + doff, Klo + ksrc);
        cp16(vt + doff, Vg + ((size_t)(b * LL + r)) * NHW + m0 + c4 * 4);
    }
}

__global__ __launch_bounds__(256, 1) void flash_mma_kernel(
    const float* __restrict__ Qhi, const float* __restrict__ Qlo,
    const float* __restrict__ Khi, const float* __restrict__ Klo,
    const float* __restrict__ Vg,  float* __restrict__ Og)
{
    float* smem = (float*)dyn_smem;
    const uint32_t sb = smem_u32(dyn_smem);
    const int tid  = threadIdx.x;
    const int warp = tid >> 5;        // 0..7
    const int lane = tid & 31;
    const int g    = lane >> 2;
    const int tig  = lane & 3;
    const int b  = blockIdx.y;
    const int n0 = blockIdx.x * 128;
    const int NT = 64;

    // ---- prologue: Q (hi/lo) + KV tile 0 ----
    {
        const size_t qr0 = (size_t)(b * NHW + n0);
#pragma unroll
        for (int j = 0; j < 8; j++) {
            int idx = j * 256 + tid;      // 0..2047
            int r = idx >> 4, c4 = idx & 15;
            uint32_t doff = (uint32_t)(r * PAD * 4 + c4 * 16);
            size_t src = (qr0 + r) * 64 + c4 * 4;
            cp16(sb + OFF_QH * 4 + doff, Qhi + src);
            cp16(sb + OFF_QL * 4 + doff, Qlo + src);
        }
        prefetch_kv(sb + OFF_KV * 4, Khi, Klo, Vg, b, 0, tid);
        CP_COMMIT();
    }

    const uint32_t* Qh = (const uint32_t*)(smem + OFF_QH);
    const uint32_t* Ql = (const uint32_t*)(smem + OFF_QL);

    float Oa[8][4];
    float lsum[2] = {0.f, 0.f};
#pragma unroll
    for (int c = 0; c < 8; c++)
#pragma unroll
        for (int r = 0; r < 4; r++) Oa[c][r] = 0.f;

    const int q0 = warp * 16;         // warp's 16 q rows

    for (int i = 0; i < NT; i++) {
        __syncthreads();
        if (i + 1 < NT)
            prefetch_kv(sb + (OFF_KV + ((i + 1) & 1) * SLOT_F) * 4, Khi, Klo, Vg, b, (i + 1) * 64, tid);
        CP_COMMIT();
        if (i + 1 < NT) { CP_WAIT(1); } else { CP_WAIT(0); }
        __syncthreads();

        const float* slot = smem + OFF_KV + (i & 1) * SLOT_F;
        const uint32_t* Kh = (const uint32_t*)slot;
        const uint32_t* Kl = (const uint32_t*)(slot + KVROW_F);
        const uint32_t* Vt = (const uint32_t*)(slot + 2 * KVROW_F);

        // ---- S = Q K^T, 3x tf32 split ----
        float S[8][4];
#pragma unroll
        for (int n = 0; n < 8; n++)
#pragma unroll
            for (int r = 0; r < 4; r++) S[n][r] = 0.f;

#pragma unroll
        for (int k = 0; k < 8; k++) {
            uint32_t Ah[4], Al[4];
            Ah[0] = Qh[(q0 + g) * PAD + 8 * k + tig];
            Ah[1] = Qh[(q0 + 8 + g) * PAD + 8 * k + tig];
            Ah[2] = Qh[(q0 + g) * PAD + 8 * k + tig + 4];
            Ah[3] = Qh[(q0 + 8 + g) * PAD + 8 * k + tig + 4];
            Al[0] = Ql[(q0 + g) * PAD + 8 * k + tig];
            Al[1] = Ql[(q0 + 8 + g) * PAD + 8 * k + tig];
            Al[2] = Ql[(q0 + g) * PAD + 8 * k + tig + 4];
            Al[3] = Ql[(q0 + 8 + g) * PAD + 8 * k + tig + 4];
#pragma unroll
            for (int n = 0; n < 8; n++) {
                const int krow = 8 * n + g;
                uint32_t bh0 = Kh[krow * PAD + 8 * k + tig];
                uint32_t bh1 = Kh[krow * PAD + 8 * k + tig + 4];
                uint32_t bl0 = Kl[krow * PAD + 8 * k + tig];
                uint32_t bl1 = Kl[krow * PAD + 8 * k + tig + 4];
                mma168(S[n], Ah, bh0, bh1);
                mma168(S[n], Ah, bl0, bl1);
                mma168(S[n], Al, bh0, bh1);
            }
        }

        // ---- P = exp(S), accumulate row sums ----
        {
            float s0 = 0.f, s1 = 0.f;
#pragma unroll
            for (int n = 0; n < 8; n++) {
                float p0 = __expf(S[n][0]);
                float p1 = __expf(S[n][1]);
                float p2 = __expf(S[n][2]);
                float p3 = __expf(S[n][3]);
                S[n][0] = p0; S[n][1] = p1; S[n][2] = p2; S[n][3] = p3;
                s0 += p0 + p1; s1 += p2 + p3;
            }
            lsum[0] += s0; lsum[1] += s1;
        }

        // ---- O += P V : D-frag -> A-frag via shuffles ----
        const int base = lane & ~3;
        const int srcA = base | (tig >> 1);
        const int srcB = srcA + 2;
        const bool odd = (tig & 1);
#pragma unroll
        for (int n = 0; n < 8; n++) {
            uint32_t Ap[4];
            {
                float e0  = __shfl_sync(0xffffffffu, S[n][0], srcA);
                float e1  = __shfl_sync(0xffffffffu, S[n][1], srcA);
                float e2  = __shfl_sync(0xffffffffu, S[n][2], srcA);
                float e3  = __shfl_sync(0xffffffffu, S[n][3], srcA);
                float f0  = __shfl_sync(0xffffffffu, S[n][0], srcB);
                float f1  = __shfl_sync(0xffffffffu, S[n][1], srcB);
                float f2  = __shfl_sync(0xffffffffu, S[n][2], srcB);
                float f3  = __shfl_sync(0xffffffffu, S[n][3], srcB);
                Ap[0] = __float_as_uint(odd ? e1 : e0);
                Ap[1] = __float_as_uint(odd ? e3 : e2);
                Ap[2] = __float_as_uint(odd ? f1 : f0);
                Ap[3] = __float_as_uint(odd ? f3 : f2);
            }
#pragma unroll
            for (int c = 0; c < 8; c++) {
                uint32_t b0 = Vt[(8 * c + g) * PAD + 8 * n + tig];
                uint32_t b1 = Vt[(8 * c + g) * PAD + 8 * n + tig + 4];
                mma168(Oa[c], Ap, b0, b1);
            }
        }
    }

    // ---- epilogue ----
#pragma unroll
    for (int h = 0; h < 2; h++) {
        lsum[h] += __shfl_xor_sync(0xffffffffu, lsum[h], 1);
        lsum[h] += __shfl_xor_sync(0xffffffffu, lsum[h], 2);
        lsum[h] = 1.f / lsum[h];
    }

    const int r0 = n0 + q0 + g;
#pragma unroll
    for (int c = 0; c < 8; c++) {
        float2 v0 = make_float2(Oa[c][0] * lsum[0], Oa[c][1] * lsum[0]);
        float2 v1 = make_float2(Oa[c][2] * lsum[1], Oa[c][3] * lsum[1]);
        *(float2*)&Og[((size_t)(b * NHW) + r0)     * 64 + 8 * c + 2 * tig] = v0;
        *(float2*)&Og[((size_t)(b * NHW) + r0 + 8) * 64 + 8 * c + 2 * tig] = v1;
    }
}

// ============================================================
// proj via mma.sync, 3x tf32 split (unchanged from R6)
// ============================================================
constexpr int WCH = 64 * 68;
constexpr int XCH = 64 * 132;
#define PROJ_SMEM ((2 * WCH + 2 * XCH) * 4)

__device__ __forceinline__ void proj_load_chunk(
    uint32_t sb, int s, const float* X, const float* W, int b, int n0, int c0, int tid)
{
    const uint32_t wdst = sb + (uint32_t)(s * WCH) * 4;
#pragma unroll
    for (int j = 0; j < 4; j++) {
        int idx = tid + j * 256;
        int o = idx >> 4, c4 = (idx & 15) << 2;
        cp16(wdst + (uint32_t)(o * 68 + c4) * 4, W + o * CC + c0 + c4);
    }
    const uint32_t xdst = sb + (uint32_t)(2 * WCH + s * XCH) * 4;
#pragma unroll
    for (int j = 0; j < 8; j++) {
        int idx = tid + j * 256;
        int cl = idx >> 5, n4 = (idx & 31) << 2;
        cp16(xdst + (uint32_t)(cl * 132 + n4) * 4,
             X + ((size_t)(b * CC + c0 + cl)) * NHW + n0 + n4);
    }
}

__global__ __launch_bounds__(256) void proj_mma0_kernel(
    const float* __restrict__ X, const float* __restrict__ W,
    float* __restrict__ out, float gain)
{
    float* smem = (float*)dyn_smem;
    const uint32_t sb = smem_u32(dyn_smem);
    const int tid  = threadIdx.x;
    const int warp = tid >> 5;
    const int lane = tid & 31;
    const int g    = lane >> 2;
    const int tig  = lane & 3;
    const int b  = blockIdx.y;
    const int n0 = blockIdx.x * 128;

    proj_load_chunk(sb, 0, X, W, b, n0, 0, tid);
    CP_COMMIT();

    float acc[4][2][4];
#pragma unroll
    for (int m = 0; m < 4; m++)
#pragma unroll
        for (int t = 0; t < 2; t++)
#pragma unroll
            for (int r = 0; r < 4; r++) acc[m][t][r] = 0.f;

    for (int kc = 0; kc < 8; kc++) {
        __syncthreads();
        if (kc + 1 < 8) proj_load_chunk(sb, (kc + 1) & 1, X, W, b, n0, (kc + 1) * 64, tid);
        CP_COMMIT();
        if (kc + 1 < 8) { CP_WAIT(1); } else { CP_WAIT(0); }
        __syncthreads();

        const float* Wc = smem + (kc & 1) * WCH;
        const float* Xc = smem + 2 * WCH + (kc & 1) * XCH;

#pragma unroll
        for (int kk = 0; kk < 8; kk++) {
            uint32_t Ah[4][4], Al[4][4];
#pragma unroll
            for (int m = 0; m < 4; m++) {
                float w0 = Wc[(16 * m + g) * 68 + 8 * kk + tig];
                float w1 = Wc[(16 * m + 8 + g) * 68 + 8 * kk + tig];
                float w2 = Wc[(16 * m + g) * 68 + 8 * kk + tig + 4];
                float w3 = Wc[(16 * m + 8 + g) * 68 + 8 * kk + tig + 4];
                float h0 = tf32hi(w0), h1 = tf32hi(w1), h2 = tf32hi(w2), h3 = tf32hi(w3);
                Ah[m][0] = __float_as_uint(h0); Ah[m][1] = __float_as_uint(h1);
                Ah[m][2] = __float_as_uint(h2); Ah[m][3] = __float_as_uint(h3);
                Al[m][0] = __float_as_uint(w0 - h0); Al[m][1] = __float_as_uint(w1 - h1);
                Al[m][2] = __float_as_uint(w2 - h2); Al[m][3] = __float_as_uint(w3 - h3);
            }
            uint32_t Bh[2][2], Bl[2][2];
#pragma unroll
            for (int t = 0; t < 2; t++) {
                float x0 = Xc[(8 * kk + tig) * 132 + 16 * warp + 8 * t + g];
                float x1 = Xc[(8 * kk + tig + 4) * 132 + 16 * warp + 8 * t + g];
                float h0 = tf32hi(x0), h1 = tf32hi(x1);
                Bh[t][0] = __float_as_uint(h0); Bh[t][1] = __float_as_uint(h1);
                Bl[t][0] = __float_as_uint(x0 - h0); Bl[t][1] = __float_as_uint(x1 - h1);
            }
#pragma unroll
            for (int m = 0; m < 4; m++)
#pragma unroll
                for (int t = 0; t < 2; t++) {
                    mma168(acc[m][t], Ah[m], Bh[t][0], Bh[t][1]);
                    mma168(acc[m][t], Ah[m], Bl[t][0], Bl[t][1]);
                    mma168(acc[m][t], Al[m], Bh[t][0], Bh[t][1]);
                }
        }
    }

#pragma unroll
    for (int m = 0; m < 4; m++)
#pragma unroll
        for (int t = 0; t < 2; t++) {
            const int o = 16 * m + g;
            const int n = n0 + 16 * warp + 8 * t + 2 * tig;
            *(float2*)&out[((size_t)(b * LL + o)) * NHW + n] =
                make_float2(acc[m][t][0] * gain, acc[m][t][1] * gain);
            *(float2*)&out[((size_t)(b * LL + o + 8)) * NHW + n] =
                make_float2(acc[m][t][2] * gain, acc[m][t][3] * gain);
        }
}

__global__ __launch_bounds__(256) void proj_mma1_kernel(
    const float* __restrict__ X, const float* __restrict__ W,
    float* __restrict__ ohi, float* __restrict__ olo, float gain)
{
    float* smem = (float*)dyn_smem;
    const uint32_t sb = smem_u32(dyn_smem);
    const int tid  = threadIdx.x;
    const int warp = tid >> 5;
    const int lane = tid & 31;
    const int g    = lane >> 2;
    const int tig  = lane & 3;
    const int b  = blockIdx.y;
    const int n0 = blockIdx.x * 128;
    const int m0 = 16 * warp;

    proj_load_chunk(sb, 0, X, W, b, n0, 0, tid);
    CP_COMMIT();

    float acc[8][4];
#pragma unroll
    for (int nc = 0; nc < 8; nc++)
#pragma unroll
        for (int r = 0; r < 4; r++) acc[nc][r] = 0.f;

    for (int kc = 0; kc < 8; kc++) {
        __syncthreads();
        if (kc + 1 < 8) proj_load_chunk(sb, (kc + 1) & 1, X, W, b, n0, (kc + 1) * 64, tid);
        CP_COMMIT();
        if (kc + 1 < 8) { CP_WAIT(1); } else { CP_WAIT(0); }
        __syncthreads();

        const float* Wc = smem + (kc & 1) * WCH;
        const float* Xc = smem + 2 * WCH + (kc & 1) * XCH;

#pragma unroll
        for (int kk = 0; kk < 8; kk++) {
            float x0 = Xc[(8 * kk + tig) * 132 + m0 + g];
            float x1 = Xc[(8 * kk + tig) * 132 + m0 + 8 + g];
            float x2 = Xc[(8 * kk + tig + 4) * 132 + m0 + g];
            float x3 = Xc[(8 * kk + tig + 4) * 132 + m0 + 8 + g];
            float h0 = tf32hi(x0), h1 = tf32hi(x1), h2 = tf32hi(x2), h3 = tf32hi(x3);
            uint32_t Ah[4] = {__float_as_uint(h0), __float_as_uint(h1),
                              __float_as_uint(h2), __float_as_uint(h3)};
            uint32_t Al[4] = {__float_as_uint(x0 - h0), __float_as_uint(x1 - h1),
                              __float_as_uint(x2 - h2), __float_as_uint(x3 - h3)};
#pragma unroll
            for (int nc = 0; nc < 8; nc++) {
                float w0 = Wc[(8 * nc + g) * 68 + 8 * kk + tig];
                float w1 = Wc[(8 * nc + g) * 68 + 8 * kk + tig + 4];
                float wh0 = tf32hi(w0), wh1 = tf32hi(w1);
                uint32_t bh0 = __float_as_uint(wh0), bh1 = __float_as_uint(wh1);
                uint32_t bl0 = __float_as_uint(w0 - wh0), bl1 = __float_as_uint(w1 - wh1);
                mma168(acc[nc], Ah, bh0, bh1);
                mma168(acc[nc], Ah, bl0, bl1);
                mma168(acc[nc], Al, bh0, bh1);
            }
        }
    }

#pragma unroll
    for (int nc = 0; nc < 8; nc++) {
        const int o = 8 * nc + 2 * tig;
        const size_t r0 = (size_t)(b * NHW + n0 + m0 + g);
        const size_t r1 = r0 + 8;
        float v0 = acc[nc][0] * gain, v1 = acc[nc][1] * gain;
        float v2 = acc[nc][2] * gain, v3 = acc[nc][3] * gain;
        float h0 = tf32hi(v0), h1 = tf32hi(v1), h2 = tf32hi(v2), h3 = tf32hi(v3);
        *(float2*)&ohi[r0 * 64 + o] = make_float2(h0, h1);
        *(float2*)&olo[r0 * 64 + o] = make_float2(v0 - h0, v1 - h1);
        *(float2*)&ohi[r1 * 64 + o] = make_float2(h2, h3);
        *(float2*)&olo[r1 * 64 + o] = make_float2(v2 - h2, v3 - h3);
    }
}

// ============================================================
// conv_o via mma.sync (1x tf32) + residual (unchanged from R6)
// ============================================================
#define CONV_SMEM ((512 * 68 + 64 * 68) * 4)
__global__ __launch_bounds__(256, 1) void conv_mma_kernel(
    const float* __restrict__ lat, const float* __restrict__ Wo,
    const float* __restrict__ addsrc, const float* __restrict__ gamma,
    float* __restrict__ out)
{
    float* smem = (float*)dyn_smem;
    const uint32_t sb = smem_u32(dyn_smem);
    float* Wos = smem;
    float* Ls  = smem + 512 * 68;

    const int tid  = threadIdx.x;
    const int warp = tid >> 5;
    const int lane = tid & 31;
    const int g    = lane >> 2;
    const int tig  = lane & 3;
    const int b  = blockIdx.y;
    const int n0 = blockIdx.x * 64;

#pragma unroll
    for (int j = 0; j < 32; j++) {
        int idx = tid + j * 256;
        int oc = idx >> 4, l4 = (idx & 15) << 2;
        cp16(sb + (uint32_t)(oc * 68 + l4) * 4, Wo + oc * LL + l4);
    }
#pragma unroll
    for (int j = 0; j < 4; j++) {
        int idx = tid + j * 256;
        int cl = idx >> 4, n4 = (idx & 15) << 2;
        cp16(sb + (uint32_t)(512 * 68 + cl * 68 + n4) * 4,
             lat + ((size_t)(b * LL + cl)) * NHW + n0 + n4);
    }
    CP_COMMIT();
    CP_WAIT(0);
    __syncthreads();

    float acc[4][8][4];
#pragma unroll
    for (int m = 0; m < 4; m++)
#pragma unroll
        for (int nc = 0; nc < 8; nc++)
#pragma unroll
            for (int r = 0; r < 4; r++) acc[m][nc][r] = 0.f;

    const uint32_t* Wu = (const uint32_t*)Wos;
    const uint32_t* Lu = (const uint32_t*)Ls;

#pragma unroll
    for (int kk = 0; kk < 8; kk++) {
        uint32_t A[4][4];
#pragma unroll
        for (int m = 0; m < 4; m++) {
            const int oc = 64 * warp + 16 * m;
            A[m][0] = Wu[(oc + g) * 68 + 8 * kk + tig];
            A[m][1] = Wu[(oc + 8 + g) * 68 + 8 * kk + tig];
            A[m][2] = Wu[(oc + g) * 68 + 8 * kk + tig + 4];
            A[m][3] = Wu[(oc + 8 + g) * 68 + 8 * kk + tig + 4];
        }
#pragma unroll
        for (int nc = 0; nc < 8; nc++) {
            uint32_t b0 = Lu[(8 * kk + tig) * 68 + 8 * nc + g];
            uint32_t b1 = Lu[(8 * kk + tig + 4) * 68 + 8 * nc + g];
#pragma unroll
            for (int m = 0; m < 4; m++) mma168(acc[m][nc], A[m], b0, b1);
        }
    }

    const float coeff = gamma[0] * GAIN_O;
#pragma unroll
    for (int m = 0; m < 4; m++)
#pragma unroll
        for (int nc = 0; nc < 8; nc++) {
            const int oc = 64 * warp + 16 * m + g;
            const int n  = n0 + 8 * nc + 2 * tig;
            const size_t base0 = ((size_t)(b * CC + oc)) * NHW + n;
            const size_t base1 = base0 + (size_t)8 * NHW;
            float2 a0 = *(const float2*)&addsrc[base0];
            float2 a1 = *(const float2*)&addsrc[base1];
            *(float2*)&out[base0] = make_float2(coeff * acc[m][nc][0] + a0.x,
                                                coeff * acc[m][nc][1] + a0.y);
            *(float2*)&out[base1] = make_float2(coeff * acc[m][nc][2] + a1.x,
                                                coeff * acc[m][nc][3] + a1.y);
        }
}

// ============================================================
// MoCA attention (unchanged FFMA)
// ============================================================
#define MOCA_SMEM 223232
__global__ __launch_bounds__(256) void moca_kernel(
    const float* __restrict__ E, const float* __restrict__ Cpt, float* __restrict__ O)
{
    float* smem = (float*)dyn_smem;
    float* Ct = smem;
    float* Cs = Ct + 64 * 260;
    float* Es = Cs + 256 * 68;
    float* Pt = Es + 64 * 68;

    const int tid = threadIdx.x;
    const int b  = blockIdx.y;
    const int n0 = blockIdx.x * 64;
    const int ty = tid >> 4;
    const int tx = tid & 15;

    {
        const int c4 = (tid & 15) << 2;
#pragma unroll
        for (int p2 = 0; p2 < 16; p2++) {
            const int p = (tid >> 4) + p2 * 16;
            float4 v = *(const float4*)&Cpt[p * 64 + c4];
            *(float4*)&Cs[p * 68 + c4] = v;
            Ct[(c4 + 0) * 260 + p] = v.x; Ct[(c4 + 1) * 260 + p] = v.y;
            Ct[(c4 + 2) * 260 + p] = v.z; Ct[(c4 + 3) * 260 + p] = v.w;
        }
    }
    {
        const int nn = (tid & 15) << 2;
#pragma unroll
        for (int p2 = 0; p2 < 4; p2++) {
            const int c = (tid >> 4) + p2 * 16;
            *(float4*)&Es[c * 68 + nn] =
                *(const float4*)&E[(size_t)b * LL * NHW + (size_t)c * NHW + n0 + nn];
        }
    }
    __syncthreads();

    float s[4][16];
#pragma unroll
    for (int i = 0; i < 4; i++)
#pragma unroll
        for (int j = 0; j < 16; j++) s[i][j] = 0.f;

#pragma unroll 4
    for (int c = 0; c < 64; c++) {
        float4 q = *(float4*)&Es[c * 68 + (ty << 2)];
        float qv[4] = {q.x, q.y, q.z, q.w};
#pragma unroll
        for (int kk = 0; kk < 4; kk++) {
            float4 k = *(float4*)&Ct[c * 260 + (tx << 4) + (kk << 2)];
            float kv[4] = {k.x, k.y, k.z, k.w};
#pragma unroll
            for (int i = 0; i < 4; i++)
#pragma unroll
                for (int w = 0; w < 4; w++) s[i][(kk << 2) + w] += qv[i] * kv[w];
        }
    }

#pragma unroll
    for (int i = 0; i < 4; i++) {
        float mx = -1e30f;
#pragma unroll
        for (int j = 0; j < 16; j++) mx = fmaxf(mx, s[i][j]);
        mx = fmaxf(mx, __shfl_xor_sync(0xffffffffu, mx, 1, 16));
        mx = fmaxf(mx, __shfl_xor_sync(0xffffffffu, mx, 2, 16));
        mx = fmaxf(mx, __shfl_xor_sync(0xffffffffu, mx, 4, 16));
        mx = fmaxf(mx, __shfl_xor_sync(0xffffffffu, mx, 8, 16));
        float rs = 0.f;
#pragma unroll
        for (int j = 0; j < 16; j++) { float p = __expf(s[i][j] - mx); s[i][j] = p; rs += p; }
        rs += __shfl_xor_sync(0xffffffffu, rs, 1, 16);
        rs += __shfl_xor_sync(0xffffffffu, rs, 2, 16);
        rs += __shfl_xor_sync(0xffffffffu, rs, 4, 16);
        rs += __shfl_xor_sync(0xffffffffu, rs, 8, 16);
        const float inv = 1.f / rs;
#pragma unroll
        for (int j = 0; j < 16; j++) s[i][j] *= inv;
    }

#pragma unroll
    for (int pp = 0; pp < 16; pp++) {
        const int p = (tx << 4) + pp;
        *(float4*)&Pt[p * 68 + (ty << 2)] = make_float4(s[0][pp], s[1][pp], s[2][pp], s[3][pp]);
    }
    __syncthreads();

    float o_acc[4][4];
#pragma unroll
    for (int i = 0; i < 4; i++)
#pragma unroll
        for (int j = 0; j < 4; j++) o_acc[i][j] = 0.f;

#pragma unroll 8
    for (int p = 0; p < 256; p++) {
        float4 pr = *(float4*)&Pt[p * 68 + (ty << 2)];
        float4 v  = *(float4*)&Cs[p * 68 + (tx << 2)];
        float pv[4] = {pr.x, pr.y, pr.z, pr.w};
        float vv[4] = {v.x, v.y, v.z, v.w};
#pragma unroll
        for (int i = 0; i < 4; i++)
#pragma unroll
            for (int j = 0; j < 4; j++) o_acc[i][j] += pv[i] * vv[j];
    }
#pragma unroll
    for (int i = 0; i < 4; i++) {
        const int n = n0 + (ty << 2) + i;
        *(float4*)&O[(size_t)b * NHW * LL + (size_t)n * LL + (tx << 2)] =
            make_float4(o_acc[i][0], o_acc[i][1], o_acc[i][2], o_acc[i][3]);
    }
}

// ============================================================
extern "C" void kernel_launch(void* const* d_in, const int* in_sizes, int n_in,
                              void* d_out, int out_size)
{
    (void)in_sizes; (void)n_in; (void)out_size;
    const float* fm         = (const float*)d_in[0];
    const float* concepts   = (const float*)d_in[1];
    const float* w_theta    = (const float*)d_in[2];
    const float* w_phi      = (const float*)d_in[3];
    const float* w_g        = (const float*)d_in[4];
    const float* w_o        = (const float*)d_in[5];
    const float* gamma_sa   = (const float*)d_in[6];
    const float* gamma_moca = (const float*)d_in[7];
    float* out = (float*)d_out;

    float *qhi, *qlo, *khi, *klo, *gv, *lat, *sa, *enc, *lat2;
    cudaGetSymbolAddress((void**)&qhi, g_qhi);
    cudaGetSymbolAddress((void**)&qlo, g_qlo);
    cudaGetSymbolAddress((void**)&khi, g_khi);
    cudaGetSymbolAddress((void**)&klo, g_klo);
    cudaGetSymbolAddress((void**)&gv,  g_gv);
    cudaGetSymbolAddress((void**)&lat, g_lat);
    cudaGetSymbolAddress((void**)&sa,  g_sa);
    cudaGetSymbolAddress((void**)&enc, g_enc);
    cudaGetSymbolAddress((void**)&lat2, g_lat2);

    cudaFuncSetAttribute(flash_mma_kernel, cudaFuncAttributeMaxDynamicSharedMemorySize, FT_SMEM);
    cudaFuncSetAttribute(proj_mma0_kernel, cudaFuncAttributeMaxDynamicSharedMemorySize, PROJ_SMEM);
    cudaFuncSetAttribute(proj_mma1_kernel, cudaFuncAttributeMaxDynamicSharedMemorySize, PROJ_SMEM);
    cudaFuncSetAttribute(conv_mma_kernel,  cudaFuncAttributeMaxDynamicSharedMemorySize, CONV_SMEM);
    cudaFuncSetAttribute(moca_kernel,      cudaFuncAttributeMaxDynamicSharedMemorySize, MOCA_SMEM);

    const dim3 pgrid(32, 8);
    proj_mma1_kernel<<<pgrid, 256, PROJ_SMEM>>>(fm, w_theta, qhi, qlo, GAIN_IN);
    proj_mma1_kernel<<<pgrid, 256, PROJ_SMEM>>>(fm, w_phi,   khi, klo, GAIN_IN);
    proj_mma0_kernel<<<pgrid, 256, PROJ_SMEM>>>(fm, w_g,     gv,  GAIN_IN);
    flash_mma_kernel<<<dim3(32, 8), 256, FT_SMEM>>>(qhi, qlo, khi, klo, gv, lat);
    conv_mma_kernel<<<dim3(64, 8), 256, CONV_SMEM>>>(lat, w_o, fm, gamma_sa, sa);
    proj_mma0_kernel<<<pgrid, 256, PROJ_SMEM>>>(sa, w_theta, enc, GAIN_IN);
    moca_kernel<<<dim3(64, 8), 256, MOCA_SMEM>>>(enc, concepts, lat2);
    conv_mma_kernel<<<dim3(64, 8), 256, CONV_SMEM>>>(lat2, w_o, sa, gamma_moca, out);
}

// round 8
// speedup vs baseline: 1.0916x; 1.0916x over previous
#include <cuda_runtime.h>
#include <cstdint>

constexpr int BB  = 8;
constexpr int CC  = 512;
constexpr int LL  = 64;
constexpr int NHW = 4096;

#define GAIN_IN 0.04419417382415922f
#define GAIN_O  0.125f

// -------- device scratch --------
__device__ float g_qhi[BB * NHW * LL];
__device__ float g_qlo[BB * NHW * LL];
__device__ float g_khi[BB * NHW * LL];
__device__ float g_klo[BB * NHW * LL];
__device__ float g_gv [BB * LL * NHW];
__device__ float g_lat[BB * NHW * LL];
__device__ float g_sa [BB * CC * NHW];
__device__ float g_enc[BB * LL * NHW];
__device__ float g_lat2[BB * NHW * LL];

extern __shared__ char dyn_smem[];

// ============================================================
// helpers
// ============================================================
__device__ __forceinline__ uint32_t smem_u32(const void* p) {
    uint32_t r;
    asm("{ .reg .u64 t; cvta.to.shared.u64 t, %1; cvt.u32.u64 %0, t; }" : "=r"(r) : "l"(p));
    return r;
}
__device__ __forceinline__ void cp16(uint32_t dst, const void* src) {
    asm volatile("cp.async.cg.shared.global [%0], [%1], 16;" :: "r"(dst), "l"(src));
}
#define CP_COMMIT() asm volatile("cp.async.commit_group;" ::: "memory")
#define CP_WAIT(n)  asm volatile("cp.async.wait_group %0;" :: "n"(n) : "memory")

__device__ __forceinline__ float tf32hi(float v) {
    float h;
    asm("cvt.rna.tf32.f32 %0, %1;" : "=f"(h) : "f"(v));
    return h;
}
__device__ __forceinline__ void mma168(float* d, const uint32_t* a, uint32_t b0, uint32_t b1) {
    asm volatile(
        "mma.sync.aligned.m16n8k8.row.col.f32.tf32.tf32.f32 "
        "{%0,%1,%2,%3}, {%4,%5,%6,%7}, {%8,%9}, {%0,%1,%2,%3};"
        : "+f"(d[0]), "+f"(d[1]), "+f"(d[2]), "+f"(d[3])
        : "r"(a[0]), "r"(a[1]), "r"(a[2]), "r"(a[3]), "r"(b0), "r"(b1));
}

// ============================================================
// flash attention via mma.sync tf32
// 256 threads / 8 warps, 32 q rows per warp -> 256 q rows per CTA.
// Grid (16, 8) = 128 CTAs = single wave.
// K double-buffered, V single-buffered (latency hidden behind S+softmax).
// ============================================================
constexpr int PAD = 68;
constexpr int QROWS   = 256;
constexpr int QT_F    = QROWS * PAD;          // 17408 floats per Q array
constexpr int OFF_QH  = 0;
constexpr int OFF_QL  = QT_F;                 // 17408
constexpr int OFF_K   = 2 * QT_F;             // 34816 ; slot = Kh+Kl = 2*64*68
constexpr int KSLOT_F = 2 * 64 * PAD;         // 8704
constexpr int OFF_V   = OFF_K + 2 * KSLOT_F;  // 52224
#define FT_SMEM ((OFF_V + 64 * PAD) * 4)      // 226304 bytes

__device__ __forceinline__ void loadK2(uint32_t dst, const float* Khi, const float* Klo,
                                       int b, int m0, int tid) {
    const size_t row0 = (size_t)(b * NHW + m0);
#pragma unroll
    for (int j = 0; j < 4; j++) {
        int idx = j * 256 + tid;            // 0..1023
        int r = idx >> 4, c4 = idx & 15;
        uint32_t doff = (uint32_t)(r * PAD * 4 + c4 * 16);
        size_t src = (row0 + r) * 64 + c4 * 4;
        cp16(dst + doff, Khi + src);
        cp16(dst + (uint32_t)(64 * PAD * 4) + doff, Klo + src);
    }
}
__device__ __forceinline__ void loadV2(uint32_t dst, const float* Vg, int b, int m0, int tid) {
#pragma unroll
    for (int j = 0; j < 4; j++) {
        int idx = j * 256 + tid;
        int r = idx >> 4, c4 = idx & 15;
        cp16(dst + (uint32_t)(r * PAD * 4 + c4 * 16),
             Vg + ((size_t)(b * LL + r)) * NHW + m0 + c4 * 4);
    }
}

__global__ __launch_bounds__(256, 1) void flash_mma_kernel(
    const float* __restrict__ Qhi, const float* __restrict__ Qlo,
    const float* __restrict__ Khi, const float* __restrict__ Klo,
    const float* __restrict__ Vg,  float* __restrict__ Og)
{
    float* smem = (float*)dyn_smem;
    const uint32_t sb = smem_u32(dyn_smem);
    const int tid  = threadIdx.x;
    const int warp = tid >> 5;        // 0..7
    const int lane = tid & 31;
    const int g    = lane >> 2;
    const int tig  = lane & 3;
    const int b  = blockIdx.y;
    const int n0 = blockIdx.x * QROWS;
    const int NT = 64;

    // ---- prologue: Q (hi/lo, 256 rows) + K tile 0 ----
    {
        const size_t qr0 = (size_t)(b * NHW + n0);
#pragma unroll
        for (int j = 0; j < 16; j++) {
            int idx = j * 256 + tid;          // 0..4095
            int r = idx >> 4, c4 = idx & 15;
            uint32_t doff = (uint32_t)(r * PAD * 4 + c4 * 16);
            size_t src = (qr0 + r) * 64 + c4 * 4;
            cp16(sb + OFF_QH * 4 + doff, Qhi + src);
            cp16(sb + OFF_QL * 4 + doff, Qlo + src);
        }
        loadK2(sb + OFF_K * 4, Khi, Klo, b, 0, tid);
        CP_COMMIT();                          // group: Q + K0
    }

    const uint32_t* Qh = (const uint32_t*)(smem + OFF_QH);
    const uint32_t* Ql = (const uint32_t*)(smem + OFF_QL);
    const uint32_t* Vt = (const uint32_t*)(smem + OFF_V);

    float Oa[2][8][4];
    float lsum[2][2];
#pragma unroll
    for (int m = 0; m < 2; m++) {
        lsum[m][0] = 0.f; lsum[m][1] = 0.f;
#pragma unroll
        for (int c = 0; c < 8; c++)
#pragma unroll
            for (int r = 0; r < 4; r++) Oa[m][c][r] = 0.f;
    }

    const int q0 = warp * 32;

    for (int i = 0; i < NT; i++) {
        __syncthreads();                       // V buffer + K slot reuse safety
        loadV2(sb + OFF_V * 4, Vg, b, i * 64, tid);
        CP_COMMIT();                           // group: V(i)
        if (i + 1 < NT)
            loadK2(sb + (uint32_t)(OFF_K + ((i + 1) & 1) * KSLOT_F) * 4, Khi, Klo, b, (i + 1) * 64, tid);
        CP_COMMIT();                           // group: K(i+1) (possibly empty)
        CP_WAIT(2);                            // K(i) + everything older complete
        __syncthreads();

        const uint32_t* Kh = (const uint32_t*)(smem + OFF_K + (i & 1) * KSLOT_F);
        const uint32_t* Kl = Kh + 64 * PAD;

        // ---- S = Q K^T, 3x tf32 split ----
        float S[2][8][4];
#pragma unroll
        for (int m = 0; m < 2; m++)
#pragma unroll
            for (int n = 0; n < 8; n++)
#pragma unroll
                for (int r = 0; r < 4; r++) S[m][n][r] = 0.f;

#pragma unroll
        for (int k = 0; k < 8; k++) {
            uint32_t Ah[2][4], Al[2][4];
#pragma unroll
            for (int m = 0; m < 2; m++) {
                const int qr = q0 + 16 * m;
                Ah[m][0] = Qh[(qr + g) * PAD + 8 * k + tig];
                Ah[m][1] = Qh[(qr + 8 + g) * PAD + 8 * k + tig];
                Ah[m][2] = Qh[(qr + g) * PAD + 8 * k + tig + 4];
                Ah[m][3] = Qh[(qr + 8 + g) * PAD + 8 * k + tig + 4];
                Al[m][0] = Ql[(qr + g) * PAD + 8 * k + tig];
                Al[m][1] = Ql[(qr + 8 + g) * PAD + 8 * k + tig];
                Al[m][2] = Ql[(qr + g) * PAD + 8 * k + tig + 4];
                Al[m][3] = Ql[(qr + 8 + g) * PAD + 8 * k + tig + 4];
            }
#pragma unroll
            for (int n = 0; n < 8; n++) {
                const int krow = 8 * n + g;
                uint32_t bh0 = Kh[krow * PAD + 8 * k + tig];
                uint32_t bh1 = Kh[krow * PAD + 8 * k + tig + 4];
                uint32_t bl0 = Kl[krow * PAD + 8 * k + tig];
                uint32_t bl1 = Kl[krow * PAD + 8 * k + tig + 4];
                mma168(S[0][n], Ah[0], bh0, bh1);
                mma168(S[1][n], Ah[1], bh0, bh1);
                mma168(S[0][n], Ah[0], bl0, bl1);
                mma168(S[1][n], Ah[1], bl0, bl1);
                mma168(S[0][n], Al[0], bh0, bh1);
                mma168(S[1][n], Al[1], bh0, bh1);
            }
        }

        // ---- P = exp(S), accumulate row sums ----
#pragma unroll
        for (int m = 0; m < 2; m++) {
            float s0 = 0.f, s1 = 0.f;
#pragma unroll
            for (int n = 0; n < 8; n++) {
                float p0 = __expf(S[m][n][0]);
                float p1 = __expf(S[m][n][1]);
                float p2 = __expf(S[m][n][2]);
                float p3 = __expf(S[m][n][3]);
                S[m][n][0] = p0; S[m][n][1] = p1;
                S[m][n][2] = p2; S[m][n][3] = p3;
                s0 += p0 + p1; s1 += p2 + p3;
            }
            lsum[m][0] += s0; lsum[m][1] += s1;
        }

        CP_WAIT(1);                            // V(i) complete (K(i+1) may fly)
        __syncthreads();                       // V visible to all warps

        // ---- O += P V : D-frag -> A-frag via shuffles ----
        const int base = lane & ~3;
        const int srcA = base | (tig >> 1);
        const int srcB = srcA + 2;
        const bool odd = (tig & 1);
#pragma unroll
        for (int n = 0; n < 8; n++) {
            uint32_t Ap[2][4];
#pragma unroll
            for (int m = 0; m < 2; m++) {
                float e0  = __shfl_sync(0xffffffffu, S[m][n][0], srcA);
                float e1  = __shfl_sync(0xffffffffu, S[m][n][1], srcA);
                float e2  = __shfl_sync(0xffffffffu, S[m][n][2], srcA);
                float e3  = __shfl_sync(0xffffffffu, S[m][n][3], srcA);
                float f0  = __shfl_sync(0xffffffffu, S[m][n][0], srcB);
                float f1  = __shfl_sync(0xffffffffu, S[m][n][1], srcB);
                float f2  = __shfl_sync(0xffffffffu, S[m][n][2], srcB);
                float f3  = __shfl_sync(0xffffffffu, S[m][n][3], srcB);
                Ap[m][0] = __float_as_uint(odd ? e1 : e0);
                Ap[m][1] = __float_as_uint(odd ? e3 : e2);
                Ap[m][2] = __float_as_uint(odd ? f1 : f0);
                Ap[m][3] = __float_as_uint(odd ? f3 : f2);
            }
#pragma unroll
            for (int c = 0; c < 8; c++) {
                uint32_t b0 = Vt[(8 * c + g) * PAD + 8 * n + tig];
                uint32_t b1 = Vt[(8 * c + g) * PAD + 8 * n + tig + 4];
                mma168(Oa[0][c], Ap[0], b0, b1);
                mma168(Oa[1][c], Ap[1], b0, b1);
            }
        }
    }

    // ---- epilogue ----
#pragma unroll
    for (int m = 0; m < 2; m++)
#pragma unroll
        for (int h = 0; h < 2; h++) {
            lsum[m][h] += __shfl_xor_sync(0xffffffffu, lsum[m][h], 1);
            lsum[m][h] += __shfl_xor_sync(0xffffffffu, lsum[m][h], 2);
            lsum[m][h] = 1.f / lsum[m][h];
        }

#pragma unroll
    for (int m = 0; m < 2; m++) {
        const int r0 = n0 + q0 + 16 * m + g;
#pragma unroll
        for (int c = 0; c < 8; c++) {
            float2 v0 = make_float2(Oa[m][c][0] * lsum[m][0], Oa[m][c][1] * lsum[m][0]);
            float2 v1 = make_float2(Oa[m][c][2] * lsum[m][1], Oa[m][c][3] * lsum[m][1]);
            *(float2*)&Og[((size_t)(b * NHW) + r0)     * 64 + 8 * c + 2 * tig] = v0;
            *(float2*)&Og[((size_t)(b * NHW) + r0 + 8) * 64 + 8 * c + 2 * tig] = v1;
        }
    }
}

// ============================================================
// proj via mma.sync, 3x tf32 split (unchanged from R6)
// ============================================================
constexpr int WCH = 64 * 68;
constexpr int XCH = 64 * 132;
#define PROJ_SMEM ((2 * WCH + 2 * XCH) * 4)

__device__ __forceinline__ void proj_load_chunk(
    uint32_t sb, int s, const float* X, const float* W, int b, int n0, int c0, int tid)
{
    const uint32_t wdst = sb + (uint32_t)(s * WCH) * 4;
#pragma unroll
    for (int j = 0; j < 4; j++) {
        int idx = tid + j * 256;
        int o = idx >> 4, c4 = (idx & 15) << 2;
        cp16(wdst + (uint32_t)(o * 68 + c4) * 4, W + o * CC + c0 + c4);
    }
    const uint32_t xdst = sb + (uint32_t)(2 * WCH + s * XCH) * 4;
#pragma unroll
    for (int j = 0; j < 8; j++) {
        int idx = tid + j * 256;
        int cl = idx >> 5, n4 = (idx & 31) << 2;
        cp16(xdst + (uint32_t)(cl * 132 + n4) * 4,
             X + ((size_t)(b * CC + c0 + cl)) * NHW + n0 + n4);
    }
}

__global__ __launch_bounds__(256) void proj_mma0_kernel(
    const float* __restrict__ X, const float* __restrict__ W,
    float* __restrict__ out, float gain)
{
    float* smem = (float*)dyn_smem;
    const uint32_t sb = smem_u32(dyn_smem);
    const int tid  = threadIdx.x;
    const int warp = tid >> 5;
    const int lane = tid & 31;
    const int g    = lane >> 2;
    const int tig  = lane & 3;
    const int b  = blockIdx.y;
    const int n0 = blockIdx.x * 128;

    proj_load_chunk(sb, 0, X, W, b, n0, 0, tid);
    CP_COMMIT();

    float acc[4][2][4];
#pragma unroll
    for (int m = 0; m < 4; m++)
#pragma unroll
        for (int t = 0; t < 2; t++)
#pragma unroll
            for (int r = 0; r < 4; r++) acc[m][t][r] = 0.f;

    for (int kc = 0; kc < 8; kc++) {
        __syncthreads();
        if (kc + 1 < 8) proj_load_chunk(sb, (kc + 1) & 1, X, W, b, n0, (kc + 1) * 64, tid);
        CP_COMMIT();
        if (kc + 1 < 8) { CP_WAIT(1); } else { CP_WAIT(0); }
        __syncthreads();

        const float* Wc = smem + (kc & 1) * WCH;
        const float* Xc = smem + 2 * WCH + (kc & 1) * XCH;

#pragma unroll
        for (int kk = 0; kk < 8; kk++) {
            uint32_t Ah[4][4], Al[4][4];
#pragma unroll
            for (int m = 0; m < 4; m++) {
                float w0 = Wc[(16 * m + g) * 68 + 8 * kk + tig];
                float w1 = Wc[(16 * m + 8 + g) * 68 + 8 * kk + tig];
                float w2 = Wc[(16 * m + g) * 68 + 8 * kk + tig + 4];
                float w3 = Wc[(16 * m + 8 + g) * 68 + 8 * kk + tig + 4];
                float h0 = tf32hi(w0), h1 = tf32hi(w1), h2 = tf32hi(w2), h3 = tf32hi(w3);
                Ah[m][0] = __float_as_uint(h0); Ah[m][1] = __float_as_uint(h1);
                Ah[m][2] = __float_as_uint(h2); Ah[m][3] = __float_as_uint(h3);
                Al[m][0] = __float_as_uint(w0 - h0); Al[m][1] = __float_as_uint(w1 - h1);
                Al[m][2] = __float_as_uint(w2 - h2); Al[m][3] = __float_as_uint(w3 - h3);
            }
            uint32_t Bh[2][2], Bl[2][2];
#pragma unroll
            for (int t = 0; t < 2; t++) {
                float x0 = Xc[(8 * kk + tig) * 132 + 16 * warp + 8 * t + g];
                float x1 = Xc[(8 * kk + tig + 4) * 132 + 16 * warp + 8 * t + g];
                float h0 = tf32hi(x0), h1 = tf32hi(x1);
                Bh[t][0] = __float_as_uint(h0); Bh[t][1] = __float_as_uint(h1);
                Bl[t][0] = __float_as_uint(x0 - h0); Bl[t][1] = __float_as_uint(x1 - h1);
            }
#pragma unroll
            for (int m = 0; m < 4; m++)
#pragma unroll
                for (int t = 0; t < 2; t++) {
                    mma168(acc[m][t], Ah[m], Bh[t][0], Bh[t][1]);
                    mma168(acc[m][t], Ah[m], Bl[t][0], Bl[t][1]);
                    mma168(acc[m][t], Al[m], Bh[t][0], Bh[t][1]);
                }
        }
    }

#pragma unroll
    for (int m = 0; m < 4; m++)
#pragma unroll
        for (int t = 0; t < 2; t++) {
            const int o = 16 * m + g;
            const int n = n0 + 16 * warp + 8 * t + 2 * tig;
            *(float2*)&out[((size_t)(b * LL + o)) * NHW + n] =
                make_float2(acc[m][t][0] * gain, acc[m][t][1] * gain);
            *(float2*)&out[((size_t)(b * LL + o + 8)) * NHW + n] =
                make_float2(acc[m][t][2] * gain, acc[m][t][3] * gain);
        }
}

__global__ __launch_bounds__(256) void proj_mma1_kernel(
    const float* __restrict__ X, const float* __restrict__ W,
    float* __restrict__ ohi, float* __restrict__ olo, float gain)
{
    float* smem = (float*)dyn_smem;
    const uint32_t sb = smem_u32(dyn_smem);
    const int tid  = threadIdx.x;
    const int warp = tid >> 5;
    const int lane = tid & 31;
    const int g    = lane >> 2;
    const int tig  = lane & 3;
    const int b  = blockIdx.y;
    const int n0 = blockIdx.x * 128;
    const int m0 = 16 * warp;

    proj_load_chunk(sb, 0, X, W, b, n0, 0, tid);
    CP_COMMIT();

    float acc[8][4];
#pragma unroll
    for (int nc = 0; nc < 8; nc++)
#pragma unroll
        for (int r = 0; r < 4; r++) acc[nc][r] = 0.f;

    for (int kc = 0; kc < 8; kc++) {
        __syncthreads();
        if (kc + 1 < 8) proj_load_chunk(sb, (kc + 1) & 1, X, W, b, n0, (kc + 1) * 64, tid);
        CP_COMMIT();
        if (kc + 1 < 8) { CP_WAIT(1); } else { CP_WAIT(0); }
        __syncthreads();

        const float* Wc = smem + (kc & 1) * WCH;
        const float* Xc = smem + 2 * WCH + (kc & 1) * XCH;

#pragma unroll
        for (int kk = 0; kk < 8; kk++) {
            float x0 = Xc[(8 * kk + tig) * 132 + m0 + g];
            float x1 = Xc[(8 * kk + tig) * 132 + m0 + 8 + g];
            float x2 = Xc[(8 * kk + tig + 4) * 132 + m0 + g];
            float x3 = Xc[(8 * kk + tig + 4) * 132 + m0 + 8 + g];
            float h0 = tf32hi(x0), h1 = tf32hi(x1), h2 = tf32hi(x2), h3 = tf32hi(x3);
            uint32_t Ah[4] = {__float_as_uint(h0), __float_as_uint(h1),
                              __float_as_uint(h2), __float_as_uint(h3)};
            uint32_t Al[4] = {__float_as_uint(x0 - h0), __float_as_uint(x1 - h1),
                              __float_as_uint(x2 - h2), __float_as_uint(x3 - h3)};
#pragma unroll
            for (int nc = 0; nc < 8; nc++) {
                float w0 = Wc[(8 * nc + g) * 68 + 8 * kk + tig];
                float w1 = Wc[(8 * nc + g) * 68 + 8 * kk + tig + 4];
                float wh0 = tf32hi(w0), wh1 = tf32hi(w1);
                uint32_t bh0 = __float_as_uint(wh0), bh1 = __float_as_uint(wh1);
                uint32_t bl0 = __float_as_uint(w0 - wh0), bl1 = __float_as_uint(w1 - wh1);
                mma168(acc[nc], Ah, bh0, bh1);
                mma168(acc[nc], Ah, bl0, bl1);
                mma168(acc[nc], Al, bh0, bh1);
            }
        }
    }

#pragma unroll
    for (int nc = 0; nc < 8; nc++) {
        const int o = 8 * nc + 2 * tig;
        const size_t r0 = (size_t)(b * NHW + n0 + m0 + g);
        const size_t r1 = r0 + 8;
        float v0 = acc[nc][0] * gain, v1 = acc[nc][1] * gain;
        float v2 = acc[nc][2] * gain, v3 = acc[nc][3] * gain;
        float h0 = tf32hi(v0), h1 = tf32hi(v1), h2 = tf32hi(v2), h3 = tf32hi(v3);
        *(float2*)&ohi[r0 * 64 + o] = make_float2(h0, h1);
        *(float2*)&olo[r0 * 64 + o] = make_float2(v0 - h0, v1 - h1);
        *(float2*)&ohi[r1 * 64 + o] = make_float2(h2, h3);
        *(float2*)&olo[r1 * 64 + o] = make_float2(v2 - h2, v3 - h3);
    }
}

// ============================================================
// conv_o via mma.sync (1x tf32) + residual (unchanged from R6)
// ============================================================
#define CONV_SMEM ((512 * 68 + 64 * 68) * 4)
__global__ __launch_bounds__(256, 1) void conv_mma_kernel(
    const float* __restrict__ lat, const float* __restrict__ Wo,
    const float* __restrict__ addsrc, const float* __restrict__ gamma,
    float* __restrict__ out)
{
    float* smem = (float*)dyn_smem;
    const uint32_t sb = smem_u32(dyn_smem);
    float* Wos = smem;
    float* Ls  = smem + 512 * 68;

    const int tid  = threadIdx.x;
    const int warp = tid >> 5;
    const int lane = tid & 31;
    const int g    = lane >> 2;
    const int tig  = lane & 3;
    const int b  = blockIdx.y;
    const int n0 = blockIdx.x * 64;

#pragma unroll
    for (int j = 0; j < 32; j++) {
        int idx = tid + j * 256;
        int oc = idx >> 4, l4 = (idx & 15) << 2;
        cp16(sb + (uint32_t)(oc * 68 + l4) * 4, Wo + oc * LL + l4);
    }
#pragma unroll
    for (int j = 0; j < 4; j++) {
        int idx = tid + j * 256;
        int cl = idx >> 4, n4 = (idx & 15) << 2;
        cp16(sb + (uint32_t)(512 * 68 + cl * 68 + n4) * 4,
             lat + ((size_t)(b * LL + cl)) * NHW + n0 + n4);
    }
    CP_COMMIT();
    CP_WAIT(0);
    __syncthreads();

    float acc[4][8][4];
#pragma unroll
    for (int m = 0; m < 4; m++)
#pragma unroll
        for (int nc = 0; nc < 8; nc++)
#pragma unroll
            for (int r = 0; r < 4; r++) acc[m][nc][r] = 0.f;

    const uint32_t* Wu = (const uint32_t*)Wos;
    const uint32_t* Lu = (const uint32_t*)Ls;

#pragma unroll
    for (int kk = 0; kk < 8; kk++) {
        uint32_t A[4][4];
#pragma unroll
        for (int m = 0; m < 4; m++) {
            const int oc = 64 * warp + 16 * m;
            A[m][0] = Wu[(oc + g) * 68 + 8 * kk + tig];
            A[m][1] = Wu[(oc + 8 + g) * 68 + 8 * kk + tig];
            A[m][2] = Wu[(oc + g) * 68 + 8 * kk + tig + 4];
            A[m][3] = Wu[(oc + 8 + g) * 68 + 8 * kk + tig + 4];
        }
#pragma unroll
        for (int nc = 0; nc < 8; nc++) {
            uint32_t b0 = Lu[(8 * kk + tig) * 68 + 8 * nc + g];
            uint32_t b1 = Lu[(8 * kk + tig + 4) * 68 + 8 * nc + g];
#pragma unroll
            for (int m = 0; m < 4; m++) mma168(acc[m][nc], A[m], b0, b1);
        }
    }

    const float coeff = gamma[0] * GAIN_O;
#pragma unroll
    for (int m = 0; m < 4; m++)
#pragma unroll
        for (int nc = 0; nc < 8; nc++) {
            const int oc = 64 * warp + 16 * m + g;
            const int n  = n0 + 8 * nc + 2 * tig;
            const size_t base0 = ((size_t)(b * CC + oc)) * NHW + n;
            const size_t base1 = base0 + (size_t)8 * NHW;
            float2 a0 = *(const float2*)&addsrc[base0];
            float2 a1 = *(const float2*)&addsrc[base1];
            *(float2*)&out[base0] = make_float2(coeff * acc[m][nc][0] + a0.x,
                                                coeff * acc[m][nc][1] + a0.y);
            *(float2*)&out[base1] = make_float2(coeff * acc[m][nc][2] + a1.x,
                                                coeff * acc[m][nc][3] + a1.y);
        }
}

// ============================================================
// MoCA attention (unchanged FFMA)
// ============================================================
#define MOCA_SMEM 223232
__global__ __launch_bounds__(256) void moca_kernel(
    const float* __restrict__ E, const float* __restrict__ Cpt, float* __restrict__ O)
{
    float* smem = (float*)dyn_smem;
    float* Ct = smem;
    float* Cs = Ct + 64 * 260;
    float* Es = Cs + 256 * 68;
    float* Pt = Es + 64 * 68;

    const int tid = threadIdx.x;
    const int b  = blockIdx.y;
    const int n0 = blockIdx.x * 64;
    const int ty = tid >> 4;
    const int tx = tid & 15;

    {
        const int c4 = (tid & 15) << 2;
#pragma unroll
        for (int p2 = 0; p2 < 16; p2++) {
            const int p = (tid >> 4) + p2 * 16;
            float4 v = *(const float4*)&Cpt[p * 64 + c4];
            *(float4*)&Cs[p * 68 + c4] = v;
            Ct[(c4 + 0) * 260 + p] = v.x; Ct[(c4 + 1) * 260 + p] = v.y;
            Ct[(c4 + 2) * 260 + p] = v.z; Ct[(c4 + 3) * 260 + p] = v.w;
        }
    }
    {
        const int nn = (tid & 15) << 2;
#pragma unroll
        for (int p2 = 0; p2 < 4; p2++) {
            const int c = (tid >> 4) + p2 * 16;
            *(float4*)&Es[c * 68 + nn] =
                *(const float4*)&E[(size_t)b * LL * NHW + (size_t)c * NHW + n0 + nn];
        }
    }
    __syncthreads();

    float s[4][16];
#pragma unroll
    for (int i = 0; i < 4; i++)
#pragma unroll
        for (int j = 0; j < 16; j++) s[i][j] = 0.f;

#pragma unroll 4
    for (int c = 0; c < 64; c++) {
        float4 q = *(float4*)&Es[c * 68 + (ty << 2)];
        float qv[4] = {q.x, q.y, q.z, q.w};
#pragma unroll
        for (int kk = 0; kk < 4; kk++) {
            float4 k = *(float4*)&Ct[c * 260 + (tx << 4) + (kk << 2)];
            float kv[4] = {k.x, k.y, k.z, k.w};
#pragma unroll
            for (int i = 0; i < 4; i++)
#pragma unroll
                for (int w = 0; w < 4; w++) s[i][(kk << 2) + w] += qv[i] * kv[w];
        }
    }

#pragma unroll
    for (int i = 0; i < 4; i++) {
        float mx = -1e30f;
#pragma unroll
        for (int j = 0; j < 16; j++) mx = fmaxf(mx, s[i][j]);
        mx = fmaxf(mx, __shfl_xor_sync(0xffffffffu, mx, 1, 16));
        mx = fmaxf(mx, __shfl_xor_sync(0xffffffffu, mx, 2, 16));
        mx = fmaxf(mx, __shfl_xor_sync(0xffffffffu, mx, 4, 16));
        mx = fmaxf(mx, __shfl_xor_sync(0xffffffffu, mx, 8, 16));
        float rs = 0.f;
#pragma unroll
        for (int j = 0; j < 16; j++) { float p = __expf(s[i][j] - mx); s[i][j] = p; rs += p; }
        rs += __shfl_xor_sync(0xffffffffu, rs, 1, 16);
        rs += __shfl_xor_sync(0xffffffffu, rs, 2, 16);
        rs += __shfl_xor_sync(0xffffffffu, rs, 4, 16);
        rs += __shfl_xor_sync(0xffffffffu, rs, 8, 16);
        const float inv = 1.f / rs;
#pragma unroll
        for (int j = 0; j < 16; j++) s[i][j] *= inv;
    }

#pragma unroll
    for (int pp = 0; pp < 16; pp++) {
        const int p = (tx << 4) + pp;
        *(float4*)&Pt[p * 68 + (ty << 2)] = make_float4(s[0][pp], s[1][pp], s[2][pp], s[3][pp]);
    }
    __syncthreads();

    float o_acc[4][4];
#pragma unroll
    for (int i = 0; i < 4; i++)
#pragma unroll
        for (int j = 0; j < 4; j++) o_acc[i][j] = 0.f;

#pragma unroll 8
    for (int p = 0; p < 256; p++) {
        float4 pr = *(float4*)&Pt[p * 68 + (ty << 2)];
        float4 v  = *(float4*)&Cs[p * 68 + (tx << 2)];
        float pv[4] = {pr.x, pr.y, pr.z, pr.w};
        float vv[4] = {v.x, v.y, v.z, v.w};
#pragma unroll
        for (int i = 0; i < 4; i++)
#pragma unroll
            for (int j = 0; j < 4; j++) o_acc[i][j] += pv[i] * vv[j];
    }
#pragma unroll
    for (int i = 0; i < 4; i++) {
        const int n = n0 + (ty << 2) + i;
        *(float4*)&O[(size_t)b * NHW * LL + (size_t)n * LL + (tx << 2)] =
            make_float4(o_acc[i][0], o_acc[i][1], o_acc[i][2], o_acc[i][3]);
    }
}

// ============================================================
extern "C" void kernel_launch(void* const* d_in, const int* in_sizes, int n_in,
                              void* d_out, int out_size)
{
    (void)in_sizes; (void)n_in; (void)out_size;
    const float* fm         = (const float*)d_in[0];
    const float* concepts   = (const float*)d_in[1];
    const float* w_theta    = (const float*)d_in[2];
    const float* w_phi      = (const float*)d_in[3];
    const float* w_g        = (const float*)d_in[4];
    const float* w_o        = (const float*)d_in[5];
    const float* gamma_sa   = (const float*)d_in[6];
    const float* gamma_moca = (const float*)d_in[7];
    float* out = (float*)d_out;

    float *qhi, *qlo, *khi, *klo, *gv, *lat, *sa, *enc, *lat2;
    cudaGetSymbolAddress((void**)&qhi, g_qhi);
    cudaGetSymbolAddress((void**)&qlo, g_qlo);
    cudaGetSymbolAddress((void**)&khi, g_khi);
    cudaGetSymbolAddress((void**)&klo, g_klo);
    cudaGetSymbolAddress((void**)&gv,  g_gv);
    cudaGetSymbolAddress((void**)&lat, g_lat);
    cudaGetSymbolAddress((void**)&sa,  g_sa);
    cudaGetSymbolAddress((void**)&enc, g_enc);
    cudaGetSymbolAddress((void**)&lat2, g_lat2);

    cudaFuncSetAttribute(flash_mma_kernel, cudaFuncAttributeMaxDynamicSharedMemorySize, FT_SMEM);
    cudaFuncSetAttribute(proj_mma0_kernel, cudaFuncAttributeMaxDynamicSharedMemorySize, PROJ_SMEM);
    cudaFuncSetAttribute(proj_mma1_kernel, cudaFuncAttributeMaxDynamicSharedMemorySize, PROJ_SMEM);
    cudaFuncSetAttribute(conv_mma_kernel,  cudaFuncAttributeMaxDynamicSharedMemorySize, CONV_SMEM);
    cudaFuncSetAttribute(moca_kernel,      cudaFuncAttributeMaxDynamicSharedMemorySize, MOCA_SMEM);

    const dim3 pgrid(32, 8);
    proj_mma1_kernel<<<pgrid, 256, PROJ_SMEM>>>(fm, w_theta, qhi, qlo, GAIN_IN);
    proj_mma1_kernel<<<pgrid, 256, PROJ_SMEM>>>(fm, w_phi,   khi, klo, GAIN_IN);
    proj_mma0_kernel<<<pgrid, 256, PROJ_SMEM>>>(fm, w_g,     gv,  GAIN_IN);
    flash_mma_kernel<<<dim3(16, 8), 256, FT_SMEM>>>(qhi, qlo, khi, klo, gv, lat);
    conv_mma_kernel<<<dim3(64, 8), 256, CONV_SMEM>>>(lat, w_o, fm, gamma_sa, sa);
    proj_mma0_kernel<<<pgrid, 256, PROJ_SMEM>>>(sa, w_theta, enc, GAIN_IN);
    moca_kernel<<<dim3(64, 8), 256, MOCA_SMEM>>>(enc, concepts, lat2);
    conv_mma_kernel<<<dim3(64, 8), 256, CONV_SMEM>>>(lat2, w_o, sa, gamma_moca, out);
}

// round 9
// speedup vs baseline: 1.2216x; 1.1190x over previous
#include <cuda_runtime.h>
#include <cstdint>

constexpr int BB  = 8;
constexpr int CC  = 512;
constexpr int LL  = 64;
constexpr int NHW = 4096;

#define GAIN_IN 0.04419417382415922f
#define GAIN_O  0.125f

// -------- device scratch --------
__device__ float g_qhi[BB * NHW * LL];
__device__ float g_qlo[BB * NHW * LL];
__device__ float g_khi[BB * NHW * LL];
__device__ float g_klo[BB * NHW * LL];   // written by phi proj, unused by flash v3
__device__ float g_gv [BB * LL * NHW];
__device__ float g_lat[BB * NHW * LL];
__device__ float g_sa [BB * CC * NHW];
__device__ float g_enc[BB * LL * NHW];
__device__ float g_lat2[BB * NHW * LL];

extern __shared__ char dyn_smem[];

// ============================================================
// helpers
// ============================================================
__device__ __forceinline__ uint32_t smem_u32(const void* p) {
    uint32_t r;
    asm("{ .reg .u64 t; cvta.to.shared.u64 t, %1; cvt.u32.u64 %0, t; }" : "=r"(r) : "l"(p));
    return r;
}
__device__ __forceinline__ void cp16(uint32_t dst, const void* src) {
    asm volatile("cp.async.cg.shared.global [%0], [%1], 16;" :: "r"(dst), "l"(src));
}
#define CP_COMMIT() asm volatile("cp.async.commit_group;" ::: "memory")
#define CP_WAIT(n)  asm volatile("cp.async.wait_group %0;" :: "n"(n) : "memory")

__device__ __forceinline__ float tf32hi(float v) {
    float h;
    asm("cvt.rna.tf32.f32 %0, %1;" : "=f"(h) : "f"(v));
    return h;
}
__device__ __forceinline__ void mma168(float* d, const uint32_t* a, uint32_t b0, uint32_t b1) {
    asm volatile(
        "mma.sync.aligned.m16n8k8.row.col.f32.tf32.tf32.f32 "
        "{%0,%1,%2,%3}, {%4,%5,%6,%7}, {%8,%9}, {%0,%1,%2,%3};"
        : "+f"(d[0]), "+f"(d[1]), "+f"(d[2]), "+f"(d[3])
        : "r"(a[0]), "r"(a[1]), "r"(a[2]), "r"(a[3]), "r"(b0), "r"(b1));
}

// ============================================================
// flash attention v3 via mma.sync tf32
// 256 threads / 8 warps, 32 q rows/warp -> 256 q rows/CTA, grid 16x8 (1 wave).
// S = Qhi*Khi + Qlo*Khi (exact Q, K rounded to tf32 once).
// K and V both double-buffered; 2 syncs + 1 wait per iteration.
// ============================================================
constexpr int PAD = 68;
constexpr int QROWS   = 256;
constexpr int QT_F    = QROWS * PAD;          // 17408
constexpr int OFF_QH  = 0;
constexpr int OFF_QL  = QT_F;                 // 17408
constexpr int OFF_K   = 2 * QT_F;             // 34816 ; slot = 64*68 (hi only)
constexpr int KSLOT_F = 64 * PAD;             // 4352
constexpr int OFF_V   = OFF_K + 2 * KSLOT_F;  // 43520
constexpr int VSLOT_F = 64 * PAD;             // 4352
#define FT_SMEM ((OFF_V + 2 * VSLOT_F) * 4)   // 208896 bytes

__device__ __forceinline__ void loadK1(uint32_t dst, const float* Khi,
                                       int b, int m0, int tid) {
    const size_t row0 = (size_t)(b * NHW + m0);
#pragma unroll
    for (int j = 0; j < 4; j++) {
        int idx = j * 256 + tid;            // 0..1023
        int r = idx >> 4, c4 = idx & 15;
        cp16(dst + (uint32_t)(r * PAD * 4 + c4 * 16), Khi + (row0 + r) * 64 + c4 * 4);
    }
}
__device__ __forceinline__ void loadV1(uint32_t dst, const float* Vg, int b, int m0, int tid) {
#pragma unroll
    for (int j = 0; j < 4; j++) {
        int idx = j * 256 + tid;
        int r = idx >> 4, c4 = idx & 15;
        cp16(dst + (uint32_t)(r * PAD * 4 + c4 * 16),
             Vg + ((size_t)(b * LL + r)) * NHW + m0 + c4 * 4);
    }
}

__global__ __launch_bounds__(256, 1) void flash_mma_kernel(
    const float* __restrict__ Qhi, const float* __restrict__ Qlo,
    const float* __restrict__ Khi,
    const float* __restrict__ Vg,  float* __restrict__ Og)
{
    float* smem = (float*)dyn_smem;
    const uint32_t sb = smem_u32(dyn_smem);
    const int tid  = threadIdx.x;
    const int warp = tid >> 5;        // 0..7
    const int lane = tid & 31;
    const int g    = lane >> 2;
    const int tig  = lane & 3;
    const int b  = blockIdx.y;
    const int n0 = blockIdx.x * QROWS;
    const int NT = 64;

    // ---- prologue: Q (hi/lo, 256 rows) + K0 + V0 ----
    {
        const size_t qr0 = (size_t)(b * NHW + n0);
#pragma unroll
        for (int j = 0; j < 16; j++) {
            int idx = j * 256 + tid;          // 0..4095
            int r = idx >> 4, c4 = idx & 15;
            uint32_t doff = (uint32_t)(r * PAD * 4 + c4 * 16);
            size_t src = (qr0 + r) * 64 + c4 * 4;
            cp16(sb + OFF_QH * 4 + doff, Qhi + src);
            cp16(sb + OFF_QL * 4 + doff, Qlo + src);
        }
        loadK1(sb + OFF_K * 4, Khi, b, 0, tid);
        loadV1(sb + OFF_V * 4, Vg,  b, 0, tid);
        CP_COMMIT();                          // group 0: Q + K0 + V0
    }

    const uint32_t* Qh = (const uint32_t*)(smem + OFF_QH);
    const uint32_t* Ql = (const uint32_t*)(smem + OFF_QL);

    float Oa[2][8][4];
    float lsum[2][2];
#pragma unroll
    for (int m = 0; m < 2; m++) {
        lsum[m][0] = 0.f; lsum[m][1] = 0.f;
#pragma unroll
        for (int c = 0; c < 8; c++)
#pragma unroll
            for (int r = 0; r < 4; r++) Oa[m][c][r] = 0.f;
    }

    const int q0 = warp * 32;

    for (int i = 0; i < NT; i++) {
        __syncthreads();                       // slot (i+1)&1 free (readers of i-1 done)
        if (i + 1 < NT) {
            loadK1(sb + (uint32_t)(OFF_K + ((i + 1) & 1) * KSLOT_F) * 4, Khi, b, (i + 1) * 64, tid);
            loadV1(sb + (uint32_t)(OFF_V + ((i + 1) & 1) * VSLOT_F) * 4, Vg,  b, (i + 1) * 64, tid);
        }
        CP_COMMIT();                           // group i+1
        CP_WAIT(1);                            // group i (K(i), V(i)) complete
        __syncthreads();

        const uint32_t* Kh = (const uint32_t*)(smem + OFF_K + (i & 1) * KSLOT_F);
        const uint32_t* Vt = (const uint32_t*)(smem + OFF_V + (i & 1) * VSLOT_F);

        // ---- S = Qhi*Khi + Qlo*Khi (exact Q, 2-mma split) ----
        float S[2][8][4];
#pragma unroll
        for (int m = 0; m < 2; m++)
#pragma unroll
            for (int n = 0; n < 8; n++)
#pragma unroll
                for (int r = 0; r < 4; r++) S[m][n][r] = 0.f;

#pragma unroll
        for (int k = 0; k < 8; k++) {
            uint32_t Ah[2][4], Al[2][4];
#pragma unroll
            for (int m = 0; m < 2; m++) {
                const int qr = q0 + 16 * m;
                Ah[m][0] = Qh[(qr + g) * PAD + 8 * k + tig];
                Ah[m][1] = Qh[(qr + 8 + g) * PAD + 8 * k + tig];
                Ah[m][2] = Qh[(qr + g) * PAD + 8 * k + tig + 4];
                Ah[m][3] = Qh[(qr + 8 + g) * PAD + 8 * k + tig + 4];
                Al[m][0] = Ql[(qr + g) * PAD + 8 * k + tig];
                Al[m][1] = Ql[(qr + 8 + g) * PAD + 8 * k + tig];
                Al[m][2] = Ql[(qr + g) * PAD + 8 * k + tig + 4];
                Al[m][3] = Ql[(qr + 8 + g) * PAD + 8 * k + tig + 4];
            }
#pragma unroll
            for (int n = 0; n < 8; n++) {
                const int krow = 8 * n + g;
                uint32_t bh0 = Kh[krow * PAD + 8 * k + tig];
                uint32_t bh1 = Kh[krow * PAD + 8 * k + tig + 4];
                mma168(S[0][n], Ah[0], bh0, bh1);
                mma168(S[1][n], Ah[1], bh0, bh1);
                mma168(S[0][n], Al[0], bh0, bh1);
                mma168(S[1][n], Al[1], bh0, bh1);
            }
        }

        // ---- P = exp(S), accumulate row sums ----
#pragma unroll
        for (int m = 0; m < 2; m++) {
            float s0 = 0.f, s1 = 0.f;
#pragma unroll
            for (int n = 0; n < 8; n++) {
                float p0 = __expf(S[m][n][0]);
                float p1 = __expf(S[m][n][1]);
                float p2 = __expf(S[m][n][2]);
                float p3 = __expf(S[m][n][3]);
                S[m][n][0] = p0; S[m][n][1] = p1;
                S[m][n][2] = p2; S[m][n][3] = p3;
                s0 += p0 + p1; s1 += p2 + p3;
            }
            lsum[m][0] += s0; lsum[m][1] += s1;
        }

        // ---- O += P V : D-frag -> A-frag via shuffles (V already resident) ----
        const int base = lane & ~3;
        const int srcA = base | (tig >> 1);
        const int srcB = srcA + 2;
        const bool odd = (tig & 1);
#pragma unroll
        for (int n = 0; n < 8; n++) {
            uint32_t Ap[2][4];
#pragma unroll
            for (int m = 0; m < 2; m++) {
                float e0  = __shfl_sync(0xffffffffu, S[m][n][0], srcA);
                float e1  = __shfl_sync(0xffffffffu, S[m][n][1], srcA);
                float e2  = __shfl_sync(0xffffffffu, S[m][n][2], srcA);
                float e3  = __shfl_sync(0xffffffffu, S[m][n][3], srcA);
                float f0  = __shfl_sync(0xffffffffu, S[m][n][0], srcB);
                float f1  = __shfl_sync(0xffffffffu, S[m][n][1], srcB);
                float f2  = __shfl_sync(0xffffffffu, S[m][n][2], srcB);
                float f3  = __shfl_sync(0xffffffffu, S[m][n][3], srcB);
                Ap[m][0] = __float_as_uint(odd ? e1 : e0);
                Ap[m][1] = __float_as_uint(odd ? e3 : e2);
                Ap[m][2] = __float_as_uint(odd ? f1 : f0);
                Ap[m][3] = __float_as_uint(odd ? f3 : f2);
            }
#pragma unroll
            for (int c = 0; c < 8; c++) {
                uint32_t b0 = Vt[(8 * c + g) * PAD + 8 * n + tig];
                uint32_t b1 = Vt[(8 * c + g) * PAD + 8 * n + tig + 4];
                mma168(Oa[0][c], Ap[0], b0, b1);
                mma168(Oa[1][c], Ap[1], b0, b1);
            }
        }
    }

    // ---- epilogue ----
#pragma unroll
    for (int m = 0; m < 2; m++)
#pragma unroll
        for (int h = 0; h < 2; h++) {
            lsum[m][h] += __shfl_xor_sync(0xffffffffu, lsum[m][h], 1);
            lsum[m][h] += __shfl_xor_sync(0xffffffffu, lsum[m][h], 2);
            lsum[m][h] = 1.f / lsum[m][h];
        }

#pragma unroll
    for (int m = 0; m < 2; m++) {
        const int r0 = n0 + q0 + 16 * m + g;
#pragma unroll
        for (int c = 0; c < 8; c++) {
            float2 v0 = make_float2(Oa[m][c][0] * lsum[m][0], Oa[m][c][1] * lsum[m][0]);
            float2 v1 = make_float2(Oa[m][c][2] * lsum[m][1], Oa[m][c][3] * lsum[m][1]);
            *(float2*)&Og[((size_t)(b * NHW) + r0)     * 64 + 8 * c + 2 * tig] = v0;
            *(float2*)&Og[((size_t)(b * NHW) + r0 + 8) * 64 + 8 * c + 2 * tig] = v1;
        }
    }
}

// ============================================================
// proj via mma.sync, 3x tf32 split (unchanged from R8)
// ============================================================
constexpr int WCH = 64 * 68;
constexpr int XCH = 64 * 132;
#define PROJ_SMEM ((2 * WCH + 2 * XCH) * 4)

__device__ __forceinline__ void proj_load_chunk(
    uint32_t sb, int s, const float* X, const float* W, int b, int n0, int c0, int tid)
{
    const uint32_t wdst = sb + (uint32_t)(s * WCH) * 4;
#pragma unroll
    for (int j = 0; j < 4; j++) {
        int idx = tid + j * 256;
        int o = idx >> 4, c4 = (idx & 15) << 2;
        cp16(wdst + (uint32_t)(o * 68 + c4) * 4, W + o * CC + c0 + c4);
    }
    const uint32_t xdst = sb + (uint32_t)(2 * WCH + s * XCH) * 4;
#pragma unroll
    for (int j = 0; j < 8; j++) {
        int idx = tid + j * 256;
        int cl = idx >> 5, n4 = (idx & 31) << 2;
        cp16(xdst + (uint32_t)(cl * 132 + n4) * 4,
             X + ((size_t)(b * CC + c0 + cl)) * NHW + n0 + n4);
    }
}

__global__ __launch_bounds__(256) void proj_mma0_kernel(
    const float* __restrict__ X, const float* __restrict__ W,
    float* __restrict__ out, float gain)
{
    float* smem = (float*)dyn_smem;
    const uint32_t sb = smem_u32(dyn_smem);
    const int tid  = threadIdx.x;
    const int warp = tid >> 5;
    const int lane = tid & 31;
    const int g    = lane >> 2;
    const int tig  = lane & 3;
    const int b  = blockIdx.y;
    const int n0 = blockIdx.x * 128;

    proj_load_chunk(sb, 0, X, W, b, n0, 0, tid);
    CP_COMMIT();

    float acc[4][2][4];
#pragma unroll
    for (int m = 0; m < 4; m++)
#pragma unroll
        for (int t = 0; t < 2; t++)
#pragma unroll
            for (int r = 0; r < 4; r++) acc[m][t][r] = 0.f;

    for (int kc = 0; kc < 8; kc++) {
        __syncthreads();
        if (kc + 1 < 8) proj_load_chunk(sb, (kc + 1) & 1, X, W, b, n0, (kc + 1) * 64, tid);
        CP_COMMIT();
        if (kc + 1 < 8) { CP_WAIT(1); } else { CP_WAIT(0); }
        __syncthreads();

        const float* Wc = smem + (kc & 1) * WCH;
        const float* Xc = smem + 2 * WCH + (kc & 1) * XCH;

#pragma unroll
        for (int kk = 0; kk < 8; kk++) {
            uint32_t Ah[4][4], Al[4][4];
#pragma unroll
            for (int m = 0; m < 4; m++) {
                float w0 = Wc[(16 * m + g) * 68 + 8 * kk + tig];
                float w1 = Wc[(16 * m + 8 + g) * 68 + 8 * kk + tig];
                float w2 = Wc[(16 * m + g) * 68 + 8 * kk + tig + 4];
                float w3 = Wc[(16 * m + 8 + g) * 68 + 8 * kk + tig + 4];
                float h0 = tf32hi(w0), h1 = tf32hi(w1), h2 = tf32hi(w2), h3 = tf32hi(w3);
                Ah[m][0] = __float_as_uint(h0); Ah[m][1] = __float_as_uint(h1);
                Ah[m][2] = __float_as_uint(h2); Ah[m][3] = __float_as_uint(h3);
                Al[m][0] = __float_as_uint(w0 - h0); Al[m][1] = __float_as_uint(w1 - h1);
                Al[m][2] = __float_as_uint(w2 - h2); Al[m][3] = __float_as_uint(w3 - h3);
            }
            uint32_t Bh[2][2], Bl[2][2];
#pragma unroll
            for (int t = 0; t < 2; t++) {
                float x0 = Xc[(8 * kk + tig) * 132 + 16 * warp + 8 * t + g];
                float x1 = Xc[(8 * kk + tig + 4) * 132 + 16 * warp + 8 * t + g];
                float h0 = tf32hi(x0), h1 = tf32hi(x1);
                Bh[t][0] = __float_as_uint(h0); Bh[t][1] = __float_as_uint(h1);
                Bl[t][0] = __float_as_uint(x0 - h0); Bl[t][1] = __float_as_uint(x1 - h1);
            }
#pragma unroll
            for (int m = 0; m < 4; m++)
#pragma unroll
                for (int t = 0; t < 2; t++) {
                    mma168(acc[m][t], Ah[m], Bh[t][0], Bh[t][1]);
                    mma168(acc[m][t], Ah[m], Bl[t][0], Bl[t][1]);
                    mma168(acc[m][t], Al[m], Bh[t][0], Bh[t][1]);
                }
        }
    }

#pragma unroll
    for (int m = 0; m < 4; m++)
#pragma unroll
        for (int t = 0; t < 2; t++) {
            const int o = 16 * m + g;
            const int n = n0 + 16 * warp + 8 * t + 2 * tig;
            *(float2*)&out[((size_t)(b * LL + o)) * NHW + n] =
                make_float2(acc[m][t][0] * gain, acc[m][t][1] * gain);
            *(float2*)&out[((size_t)(b * LL + o + 8)) * NHW + n] =
                make_float2(acc[m][t][2] * gain, acc[m][t][3] * gain);
        }
}

__global__ __launch_bounds__(256) void proj_mma1_kernel(
    const float* __restrict__ X, const float* __restrict__ W,
    float* __restrict__ ohi, float* __restrict__ olo, float gain)
{
    float* smem = (float*)dyn_smem;
    const uint32_t sb = smem_u32(dyn_smem);
    const int tid  = threadIdx.x;
    const int warp = tid >> 5;
    const int lane = tid & 31;
    const int g    = lane >> 2;
    const int tig  = lane & 3;
    const int b  = blockIdx.y;
    const int n0 = blockIdx.x * 128;
    const int m0 = 16 * warp;

    proj_load_chunk(sb, 0, X, W, b, n0, 0, tid);
    CP_COMMIT();

    float acc[8][4];
#pragma unroll
    for (int nc = 0; nc < 8; nc++)
#pragma unroll
        for (int r = 0; r < 4; r++) acc[nc][r] = 0.f;

    for (int kc = 0; kc < 8; kc++) {
        __syncthreads();
        if (kc + 1 < 8) proj_load_chunk(sb, (kc + 1) & 1, X, W, b, n0, (kc + 1) * 64, tid);
        CP_COMMIT();
        if (kc + 1 < 8) { CP_WAIT(1); } else { CP_WAIT(0); }
        __syncthreads();

        const float* Wc = smem + (kc & 1) * WCH;
        const float* Xc = smem + 2 * WCH + (kc & 1) * XCH;

#pragma unroll
        for (int kk = 0; kk < 8; kk++) {
            float x0 = Xc[(8 * kk + tig) * 132 + m0 + g];
            float x1 = Xc[(8 * kk + tig) * 132 + m0 + 8 + g];
            float x2 = Xc[(8 * kk + tig + 4) * 132 + m0 + g];
            float x3 = Xc[(8 * kk + tig + 4) * 132 + m0 + 8 + g];
            float h0 = tf32hi(x0), h1 = tf32hi(x1), h2 = tf32hi(x2), h3 = tf32hi(x3);
            uint32_t Ah[4] = {__float_as_uint(h0), __float_as_uint(h1),
                              __float_as_uint(h2), __float_as_uint(h3)};
            uint32_t Al[4] = {__float_as_uint(x0 - h0), __float_as_uint(x1 - h1),
                              __float_as_uint(x2 - h2), __float_as_uint(x3 - h3)};
#pragma unroll
            for (int nc = 0; nc < 8; nc++) {
                float w0 = Wc[(8 * nc + g) * 68 + 8 * kk + tig];
                float w1 = Wc[(8 * nc + g) * 68 + 8 * kk + tig + 4];
                float wh0 = tf32hi(w0), wh1 = tf32hi(w1);
                uint32_t bh0 = __float_as_uint(wh0), bh1 = __float_as_uint(wh1);
                uint32_t bl0 = __float_as_uint(w0 - wh0), bl1 = __float_as_uint(w1 - wh1);
                mma168(acc[nc], Ah, bh0, bh1);
                mma168(acc[nc], Ah, bl0, bl1);
                mma168(acc[nc], Al, bh0, bh1);
            }
        }
    }

#pragma unroll
    for (int nc = 0; nc < 8; nc++) {
        const int o = 8 * nc + 2 * tig;
        const size_t r0 = (size_t)(b * NHW + n0 + m0 + g);
        const size_t r1 = r0 + 8;
        float v0 = acc[nc][0] * gain, v1 = acc[nc][1] * gain;
        float v2 = acc[nc][2] * gain, v3 = acc[nc][3] * gain;
        float h0 = tf32hi(v0), h1 = tf32hi(v1), h2 = tf32hi(v2), h3 = tf32hi(v3);
        *(float2*)&ohi[r0 * 64 + o] = make_float2(h0, h1);
        *(float2*)&olo[r0 * 64 + o] = make_float2(v0 - h0, v1 - h1);
        *(float2*)&ohi[r1 * 64 + o] = make_float2(h2, h3);
        *(float2*)&olo[r1 * 64 + o] = make_float2(v2 - h2, v3 - h3);
    }
}

// ============================================================
// conv_o via mma.sync (1x tf32) + residual (unchanged from R8)
// ============================================================
#define CONV_SMEM ((512 * 68 + 64 * 68) * 4)
__global__ __launch_bounds__(256, 1) void conv_mma_kernel(
    const float* __restrict__ lat, const float* __restrict__ Wo,
    const float* __restrict__ addsrc, const float* __restrict__ gamma,
    float* __restrict__ out)
{
    float* smem = (float*)dyn_smem;
    const uint32_t sb = smem_u32(dyn_smem);
    float* Wos = smem;
    float* Ls  = smem + 512 * 68;

    const int tid  = threadIdx.x;
    const int warp = tid >> 5;
    const int lane = tid & 31;
    const int g    = lane >> 2;
    const int tig  = lane & 3;
    const int b  = blockIdx.y;
    const int n0 = blockIdx.x * 64;

#pragma unroll
    for (int j = 0; j < 32; j++) {
        int idx = tid + j * 256;
        int oc = idx >> 4, l4 = (idx & 15) << 2;
        cp16(sb + (uint32_t)(oc * 68 + l4) * 4, Wo + oc * LL + l4);
    }
#pragma unroll
    for (int j = 0; j < 4; j++) {
        int idx = tid + j * 256;
        int cl = idx >> 4, n4 = (idx & 15) << 2;
        cp16(sb + (uint32_t)(512 * 68 + cl * 68 + n4) * 4,
             lat + ((size_t)(b * LL + cl)) * NHW + n0 + n4);
    }
    CP_COMMIT();
    CP_WAIT(0);
    __syncthreads();

    float acc[4][8][4];
#pragma unroll
    for (int m = 0; m < 4; m++)
#pragma unroll
        for (int nc = 0; nc < 8; nc++)
#pragma unroll
            for (int r = 0; r < 4; r++) acc[m][nc][r] = 0.f;

    const uint32_t* Wu = (const uint32_t*)Wos;
    const uint32_t* Lu = (const uint32_t*)Ls;

#pragma unroll
    for (int kk = 0; kk < 8; kk++) {
        uint32_t A[4][4];
#pragma unroll
        for (int m = 0; m < 4; m++) {
            const int oc = 64 * warp + 16 * m;
            A[m][0] = Wu[(oc + g) * 68 + 8 * kk + tig];
            A[m][1] = Wu[(oc + 8 + g) * 68 + 8 * kk + tig];
            A[m][2] = Wu[(oc + g) * 68 + 8 * kk + tig + 4];
            A[m][3] = Wu[(oc + 8 + g) * 68 + 8 * kk + tig + 4];
        }
#pragma unroll
        for (int nc = 0; nc < 8; nc++) {
            uint32_t b0 = Lu[(8 * kk + tig) * 68 + 8 * nc + g];
            uint32_t b1 = Lu[(8 * kk + tig + 4) * 68 + 8 * nc + g];
#pragma unroll
            for (int m = 0; m < 4; m++) mma168(acc[m][nc], A[m], b0, b1);
        }
    }

    const float coeff = gamma[0] * GAIN_O;
#pragma unroll
    for (int m = 0; m < 4; m++)
#pragma unroll
        for (int nc = 0; nc < 8; nc++) {
            const int oc = 64 * warp + 16 * m + g;
            const int n  = n0 + 8 * nc + 2 * tig;
            const size_t base0 = ((size_t)(b * CC + oc)) * NHW + n;
            const size_t base1 = base0 + (size_t)8 * NHW;
            float2 a0 = *(const float2*)&addsrc[base0];
            float2 a1 = *(const float2*)&addsrc[base1];
            *(float2*)&out[base0] = make_float2(coeff * acc[m][nc][0] + a0.x,
                                                coeff * acc[m][nc][1] + a0.y);
            *(float2*)&out[base1] = make_float2(coeff * acc[m][nc][2] + a1.x,
                                                coeff * acc[m][nc][3] + a1.y);
        }
}

// ============================================================
// MoCA attention (unchanged FFMA)
// ============================================================
#define MOCA_SMEM 223232
__global__ __launch_bounds__(256) void moca_kernel(
    const float* __restrict__ E, const float* __restrict__ Cpt, float* __restrict__ O)
{
    float* smem = (float*)dyn_smem;
    float* Ct = smem;
    float* Cs = Ct + 64 * 260;
    float* Es = Cs + 256 * 68;
    float* Pt = Es + 64 * 68;

    const int tid = threadIdx.x;
    const int b  = blockIdx.y;
    const int n0 = blockIdx.x * 64;
    const int ty = tid >> 4;
    const int tx = tid & 15;

    {
        const int c4 = (tid & 15) << 2;
#pragma unroll
        for (int p2 = 0; p2 < 16; p2++) {
            const int p = (tid >> 4) + p2 * 16;
            float4 v = *(const float4*)&Cpt[p * 64 + c4];
            *(float4*)&Cs[p * 68 + c4] = v;
            Ct[(c4 + 0) * 260 + p] = v.x; Ct[(c4 + 1) * 260 + p] = v.y;
            Ct[(c4 + 2) * 260 + p] = v.z; Ct[(c4 + 3) * 260 + p] = v.w;
        }
    }
    {
        const int nn = (tid & 15) << 2;
#pragma unroll
        for (int p2 = 0; p2 < 4; p2++) {
            const int c = (tid >> 4) + p2 * 16;
            *(float4*)&Es[c * 68 + nn] =
                *(const float4*)&E[(size_t)b * LL * NHW + (size_t)c * NHW + n0 + nn];
        }
    }
    __syncthreads();

    float s[4][16];
#pragma unroll
    for (int i = 0; i < 4; i++)
#pragma unroll
        for (int j = 0; j < 16; j++) s[i][j] = 0.f;

#pragma unroll 4
    for (int c = 0; c < 64; c++) {
        float4 q = *(float4*)&Es[c * 68 + (ty << 2)];
        float qv[4] = {q.x, q.y, q.z, q.w};
#pragma unroll
        for (int kk = 0; kk < 4; kk++) {
            float4 k = *(float4*)&Ct[c * 260 + (tx << 4) + (kk << 2)];
            float kv[4] = {k.x, k.y, k.z, k.w};
#pragma unroll
            for (int i = 0; i < 4; i++)
#pragma unroll
                for (int w = 0; w < 4; w++) s[i][(kk << 2) + w] += qv[i] * kv[w];
        }
    }

#pragma unroll
    for (int i = 0; i < 4; i++) {
        float mx = -1e30f;
#pragma unroll
        for (int j = 0; j < 16; j++) mx = fmaxf(mx, s[i][j]);
        mx = fmaxf(mx, __shfl_xor_sync(0xffffffffu, mx, 1, 16));
        mx = fmaxf(mx, __shfl_xor_sync(0xffffffffu, mx, 2, 16));
        mx = fmaxf(mx, __shfl_xor_sync(0xffffffffu, mx, 4, 16));
        mx = fmaxf(mx, __shfl_xor_sync(0xffffffffu, mx, 8, 16));
        float rs = 0.f;
#pragma unroll
        for (int j = 0; j < 16; j++) { float p = __expf(s[i][j] - mx); s[i][j] = p; rs += p; }
        rs += __shfl_xor_sync(0xffffffffu, rs, 1, 16);
        rs += __shfl_xor_sync(0xffffffffu, rs, 2, 16);
        rs += __shfl_xor_sync(0xffffffffu, rs, 4, 16);
        rs += __shfl_xor_sync(0xffffffffu, rs, 8, 16);
        const float inv = 1.f / rs;
#pragma unroll
        for (int j = 0; j < 16; j++) s[i][j] *= inv;
    }

#pragma unroll
    for (int pp = 0; pp < 16; pp++) {
        const int p = (tx << 4) + pp;
        *(float4*)&Pt[p * 68 + (ty << 2)] = make_float4(s[0][pp], s[1][pp], s[2][pp], s[3][pp]);
    }
    __syncthreads();

    float o_acc[4][4];
#pragma unroll
    for (int i = 0; i < 4; i++)
#pragma unroll
        for (int j = 0; j < 4; j++) o_acc[i][j] = 0.f;

#pragma unroll 8
    for (int p = 0; p < 256; p++) {
        float4 pr = *(float4*)&Pt[p * 68 + (ty << 2)];
        float4 v  = *(float4*)&Cs[p * 68 + (tx << 2)];
        float pv[4] = {pr.x, pr.y, pr.z, pr.w};
        float vv[4] = {v.x, v.y, v.z, v.w};
#pragma unroll
        for (int i = 0; i < 4; i++)
#pragma unroll
            for (int j = 0; j < 4; j++) o_acc[i][j] += pv[i] * vv[j];
    }
#pragma unroll
    for (int i = 0; i < 4; i++) {
        const int n = n0 + (ty << 2) + i;
        *(float4*)&O[(size_t)b * NHW * LL + (size_t)n * LL + (tx << 2)] =
            make_float4(o_acc[i][0], o_acc[i][1], o_acc[i][2], o_acc[i][3]);
    }
}

// ============================================================
extern "C" void kernel_launch(void* const* d_in, const int* in_sizes, int n_in,
                              void* d_out, int out_size)
{
    (void)in_sizes; (void)n_in; (void)out_size;
    const float* fm         = (const float*)d_in[0];
    const float* concepts   = (const float*)d_in[1];
    const float* w_theta    = (const float*)d_in[2];
    const float* w_phi      = (const float*)d_in[3];
    const float* w_g        = (const float*)d_in[4];
    const float* w_o        = (const float*)d_in[5];
    const float* gamma_sa   = (const float*)d_in[6];
    const float* gamma_moca = (const float*)d_in[7];
    float* out = (float*)d_out;

    float *qhi, *qlo, *khi, *klo, *gv, *lat, *sa, *enc, *lat2;
    cudaGetSymbolAddress((void**)&qhi, g_qhi);
    cudaGetSymbolAddress((void**)&qlo, g_qlo);
    cudaGetSymbolAddress((void**)&khi, g_khi);
    cudaGetSymbolAddress((void**)&klo, g_klo);
    cudaGetSymbolAddress((void**)&gv,  g_gv);
    cudaGetSymbolAddress((void**)&lat, g_lat);
    cudaGetSymbolAddress((void**)&sa,  g_sa);
    cudaGetSymbolAddress((void**)&enc, g_enc);
    cudaGetSymbolAddress((void**)&lat2, g_lat2);

    cudaFuncSetAttribute(flash_mma_kernel, cudaFuncAttributeMaxDynamicSharedMemorySize, FT_SMEM);
    cudaFuncSetAttribute(proj_mma0_kernel, cudaFuncAttributeMaxDynamicSharedMemorySize, PROJ_SMEM);
    cudaFuncSetAttribute(proj_mma1_kernel, cudaFuncAttributeMaxDynamicSharedMemorySize, PROJ_SMEM);
    cudaFuncSetAttribute(conv_mma_kernel,  cudaFuncAttributeMaxDynamicSharedMemorySize, CONV_SMEM);
    cudaFuncSetAttribute(moca_kernel,      cudaFuncAttributeMaxDynamicSharedMemorySize, MOCA_SMEM);

    const dim3 pgrid(32, 8);
    proj_mma1_kernel<<<pgrid, 256, PROJ_SMEM>>>(fm, w_theta, qhi, qlo, GAIN_IN);
    proj_mma1_kernel<<<pgrid, 256, PROJ_SMEM>>>(fm, w_phi,   khi, klo, GAIN_IN);
    proj_mma0_kernel<<<pgrid, 256, PROJ_SMEM>>>(fm, w_g,     gv,  GAIN_IN);
    flash_mma_kernel<<<dim3(16, 8), 256, FT_SMEM>>>(qhi, qlo, khi, gv, lat);
    conv_mma_kernel<<<dim3(64, 8), 256, CONV_SMEM>>>(lat, w_o, fm, gamma_sa, sa);
    proj_mma0_kernel<<<pgrid, 256, PROJ_SMEM>>>(sa, w_theta, enc, GAIN_IN);
    moca_kernel<<<dim3(64, 8), 256, MOCA_SMEM>>>(enc, concepts, lat2);
    conv_mma_kernel<<<dim3(64, 8), 256, CONV_SMEM>>>(lat2, w_o, sa, gamma_moca, out);
}

// round 10
// speedup vs baseline: 1.5001x; 1.2280x over previous
#include <cuda_runtime.h>
#include <cstdint>

constexpr int BB  = 8;
constexpr int CC  = 512;
constexpr int LL  = 64;
constexpr int NHW = 4096;

#define GAIN_IN 0.04419417382415922f
#define GAIN_O  0.125f

// -------- device scratch --------
__device__ float g_qh [BB * NHW * LL];   // theta proj, [b][n][c], tf32-rounded
__device__ float g_kh [BB * NHW * LL];   // phi proj,   [b][n][c], tf32-rounded
__device__ float g_gv [BB * LL * NHW];   // g proj, [b][c][n]
__device__ float g_lat[BB * NHW * LL];
__device__ float g_sa [BB * CC * NHW];
__device__ float g_enc[BB * LL * NHW];
__device__ float g_lat2[BB * NHW * LL];

extern __shared__ char dyn_smem[];

// ============================================================
// helpers
// ============================================================
__device__ __forceinline__ uint32_t smem_u32(const void* p) {
    uint32_t r;
    asm("{ .reg .u64 t; cvta.to.shared.u64 t, %1; cvt.u32.u64 %0, t; }" : "=r"(r) : "l"(p));
    return r;
}
__device__ __forceinline__ void cp16(uint32_t dst, const void* src) {
    asm volatile("cp.async.cg.shared.global [%0], [%1], 16;" :: "r"(dst), "l"(src));
}
#define CP_COMMIT() asm volatile("cp.async.commit_group;" ::: "memory")
#define CP_WAIT(n)  asm volatile("cp.async.wait_group %0;" :: "n"(n) : "memory")

__device__ __forceinline__ float tf32hi(float v) {
    float h;
    asm("cvt.rna.tf32.f32 %0, %1;" : "=f"(h) : "f"(v));
    return h;
}
__device__ __forceinline__ void mma168(float* d, const uint32_t* a, uint32_t b0, uint32_t b1) {
    asm volatile(
        "mma.sync.aligned.m16n8k8.row.col.f32.tf32.tf32.f32 "
        "{%0,%1,%2,%3}, {%4,%5,%6,%7}, {%8,%9}, {%0,%1,%2,%3};"
        : "+f"(d[0]), "+f"(d[1]), "+f"(d[2]), "+f"(d[3])
        : "r"(a[0]), "r"(a[1]), "r"(a[2]), "r"(a[3]), "r"(b0), "r"(b1));
}

// ============================================================
// flash attention v4: 1x tf32 S (Q,K pre-rounded), 1x tf32 PV.
// 256 threads / 8 warps, 32 q rows/warp -> 256 q rows/CTA, grid 16x8 (1 wave).
// K and V double-buffered.
// ============================================================
constexpr int PAD = 68;
constexpr int QROWS   = 256;
constexpr int QT_F    = QROWS * PAD;          // 17408
constexpr int OFF_Q   = 0;
constexpr int OFF_K   = QT_F;                 // 17408
constexpr int KSLOT_F = 64 * PAD;             // 4352
constexpr int OFF_V   = OFF_K + 2 * KSLOT_F;  // 26112
constexpr int VSLOT_F = 64 * PAD;             // 4352
#define FT_SMEM ((OFF_V + 2 * VSLOT_F) * 4)   // 139264 bytes

__device__ __forceinline__ void loadK1(uint32_t dst, const float* Kh,
                                       int b, int m0, int tid) {
    const size_t row0 = (size_t)(b * NHW + m0);
#pragma unroll
    for (int j = 0; j < 4; j++) {
        int idx = j * 256 + tid;
        int r = idx >> 4, c4 = idx & 15;
        cp16(dst + (uint32_t)(r * PAD * 4 + c4 * 16), Kh + (row0 + r) * 64 + c4 * 4);
    }
}
__device__ __forceinline__ void loadV1(uint32_t dst, const float* Vg, int b, int m0, int tid) {
#pragma unroll
    for (int j = 0; j < 4; j++) {
        int idx = j * 256 + tid;
        int r = idx >> 4, c4 = idx & 15;
        cp16(dst + (uint32_t)(r * PAD * 4 + c4 * 16),
             Vg + ((size_t)(b * LL + r)) * NHW + m0 + c4 * 4);
    }
}

__global__ __launch_bounds__(256, 1) void flash_mma_kernel(
    const float* __restrict__ Qg, const float* __restrict__ Kg,
    const float* __restrict__ Vg, float* __restrict__ Og)
{
    float* smem = (float*)dyn_smem;
    const uint32_t sb = smem_u32(dyn_smem);
    const int tid  = threadIdx.x;
    const int warp = tid >> 5;
    const int lane = tid & 31;
    const int g    = lane >> 2;
    const int tig  = lane & 3;
    const int b  = blockIdx.y;
    const int n0 = blockIdx.x * QROWS;
    const int NT = 64;

    // ---- prologue: Q (256 rows) + K0 + V0 ----
    {
        const size_t qr0 = (size_t)(b * NHW + n0);
#pragma unroll
        for (int j = 0; j < 16; j++) {
            int idx = j * 256 + tid;          // 0..4095
            int r = idx >> 4, c4 = idx & 15;
            cp16(sb + OFF_Q * 4 + (uint32_t)(r * PAD * 4 + c4 * 16),
                 Qg + (qr0 + r) * 64 + c4 * 4);
        }
        loadK1(sb + OFF_K * 4, Kg, b, 0, tid);
        loadV1(sb + OFF_V * 4, Vg, b, 0, tid);
        CP_COMMIT();                          // group 0
    }

    const uint32_t* Qh = (const uint32_t*)(smem + OFF_Q);

    float Oa[2][8][4];
    float lsum[2][2];
#pragma unroll
    for (int m = 0; m < 2; m++) {
        lsum[m][0] = 0.f; lsum[m][1] = 0.f;
#pragma unroll
        for (int c = 0; c < 8; c++)
#pragma unroll
            for (int r = 0; r < 4; r++) Oa[m][c][r] = 0.f;
    }

    const int q0 = warp * 32;

    for (int i = 0; i < NT; i++) {
        __syncthreads();
        if (i + 1 < NT) {
            loadK1(sb + (uint32_t)(OFF_K + ((i + 1) & 1) * KSLOT_F) * 4, Kg, b, (i + 1) * 64, tid);
            loadV1(sb + (uint32_t)(OFF_V + ((i + 1) & 1) * VSLOT_F) * 4, Vg, b, (i + 1) * 64, tid);
        }
        CP_COMMIT();
        CP_WAIT(1);
        __syncthreads();

        const uint32_t* Kh = (const uint32_t*)(smem + OFF_K + (i & 1) * KSLOT_F);
        const uint32_t* Vt = (const uint32_t*)(smem + OFF_V + (i & 1) * VSLOT_F);

        // ---- S = Q K^T, 1x tf32 ----
        float S[2][8][4];
#pragma unroll
        for (int m = 0; m < 2; m++)
#pragma unroll
            for (int n = 0; n < 8; n++)
#pragma unroll
                for (int r = 0; r < 4; r++) S[m][n][r] = 0.f;

#pragma unroll
        for (int k = 0; k < 8; k++) {
            uint32_t Ah[2][4];
#pragma unroll
            for (int m = 0; m < 2; m++) {
                const int qr = q0 + 16 * m;
                Ah[m][0] = Qh[(qr + g) * PAD + 8 * k + tig];
                Ah[m][1] = Qh[(qr + 8 + g) * PAD + 8 * k + tig];
                Ah[m][2] = Qh[(qr + g) * PAD + 8 * k + tig + 4];
                Ah[m][3] = Qh[(qr + 8 + g) * PAD + 8 * k + tig + 4];
            }
#pragma unroll
            for (int n = 0; n < 8; n++) {
                const int krow = 8 * n + g;
                uint32_t bh0 = Kh[krow * PAD + 8 * k + tig];
                uint32_t bh1 = Kh[krow * PAD + 8 * k + tig + 4];
                mma168(S[0][n], Ah[0], bh0, bh1);
                mma168(S[1][n], Ah[1], bh0, bh1);
            }
        }

        // ---- P = exp(S), accumulate row sums ----
#pragma unroll
        for (int m = 0; m < 2; m++) {
            float s0 = 0.f, s1 = 0.f;
#pragma unroll
            for (int n = 0; n < 8; n++) {
                float p0 = __expf(S[m][n][0]);
                float p1 = __expf(S[m][n][1]);
                float p2 = __expf(S[m][n][2]);
                float p3 = __expf(S[m][n][3]);
                S[m][n][0] = p0; S[m][n][1] = p1;
                S[m][n][2] = p2; S[m][n][3] = p3;
                s0 += p0 + p1; s1 += p2 + p3;
            }
            lsum[m][0] += s0; lsum[m][1] += s1;
        }

        // ---- O += P V : D-frag -> A-frag via shuffles ----
        const int base = lane & ~3;
        const int srcA = base | (tig >> 1);
        const int srcB = srcA + 2;
        const bool odd = (tig & 1);
#pragma unroll
        for (int n = 0; n < 8; n++) {
            uint32_t Ap[2][4];
#pragma unroll
            for (int m = 0; m < 2; m++) {
                float e0  = __shfl_sync(0xffffffffu, S[m][n][0], srcA);
                float e1  = __shfl_sync(0xffffffffu, S[m][n][1], srcA);
                float e2  = __shfl_sync(0xffffffffu, S[m][n][2], srcA);
                float e3  = __shfl_sync(0xffffffffu, S[m][n][3], srcA);
                float f0  = __shfl_sync(0xffffffffu, S[m][n][0], srcB);
                float f1  = __shfl_sync(0xffffffffu, S[m][n][1], srcB);
                float f2  = __shfl_sync(0xffffffffu, S[m][n][2], srcB);
                float f3  = __shfl_sync(0xffffffffu, S[m][n][3], srcB);
                Ap[m][0] = __float_as_uint(odd ? e1 : e0);
                Ap[m][1] = __float_as_uint(odd ? e3 : e2);
                Ap[m][2] = __float_as_uint(odd ? f1 : f0);
                Ap[m][3] = __float_as_uint(odd ? f3 : f2);
            }
#pragma unroll
            for (int c = 0; c < 8; c++) {
                uint32_t b0 = Vt[(8 * c + g) * PAD + 8 * n + tig];
                uint32_t b1 = Vt[(8 * c + g) * PAD + 8 * n + tig + 4];
                mma168(Oa[0][c], Ap[0], b0, b1);
                mma168(Oa[1][c], Ap[1], b0, b1);
            }
        }
    }

    // ---- epilogue ----
#pragma unroll
    for (int m = 0; m < 2; m++)
#pragma unroll
        for (int h = 0; h < 2; h++) {
            lsum[m][h] += __shfl_xor_sync(0xffffffffu, lsum[m][h], 1);
            lsum[m][h] += __shfl_xor_sync(0xffffffffu, lsum[m][h], 2);
            lsum[m][h] = 1.f / lsum[m][h];
        }

#pragma unroll
    for (int m = 0; m < 2; m++) {
        const int r0 = n0 + q0 + 16 * m + g;
#pragma unroll
        for (int c = 0; c < 8; c++) {
            float2 v0 = make_float2(Oa[m][c][0] * lsum[m][0], Oa[m][c][1] * lsum[m][0]);
            float2 v1 = make_float2(Oa[m][c][2] * lsum[m][1], Oa[m][c][3] * lsum[m][1]);
            *(float2*)&Og[((size_t)(b * NHW) + r0)     * 64 + 8 * c + 2 * tig] = v0;
            *(float2*)&Og[((size_t)(b * NHW) + r0 + 8) * 64 + 8 * c + 2 * tig] = v1;
        }
    }
}

// ============================================================
// fused theta+phi projection: q/k = gain * X^T W^T, written [b][n][o],
// tf32-rounded. 2x split: X exact (hi+lo), W rounded once.
// X fragments built ONCE, applied to both weight sets.
// ============================================================
constexpr int QK_WCH = 64 * 68;    // 4352
constexpr int QK_XCH = 64 * 132;   // 8448
#define QK_SMEM ((4 * QK_WCH + 2 * QK_XCH) * 4)   // 137216

__device__ __forceinline__ void qk_load_chunk(
    uint32_t sb, int s, const float* X, const float* Wt, const float* Wp,
    int b, int n0, int c0, int tid)
{
    const uint32_t wtd = sb + (uint32_t)(s * QK_WCH) * 4;
    const uint32_t wpd = sb + (uint32_t)((2 + s) * QK_WCH) * 4;
#pragma unroll
    for (int j = 0; j < 4; j++) {
        int idx = tid + j * 256;
        int o = idx >> 4, c4 = (idx & 15) << 2;
        cp16(wtd + (uint32_t)(o * 68 + c4) * 4, Wt + o * CC + c0 + c4);
        cp16(wpd + (uint32_t)(o * 68 + c4) * 4, Wp + o * CC + c0 + c4);
    }
    const uint32_t xd = sb + (uint32_t)(4 * QK_WCH + s * QK_XCH) * 4;
#pragma unroll
    for (int j = 0; j < 8; j++) {
        int idx = tid + j * 256;
        int cl = idx >> 5, n4 = (idx & 31) << 2;
        cp16(xd + (uint32_t)(cl * 132 + n4) * 4,
             X + ((size_t)(b * CC + c0 + cl)) * NHW + n0 + n4);
    }
}

__global__ __launch_bounds__(256) void proj_qk_kernel(
    const float* __restrict__ X, const float* __restrict__ Wt, const float* __restrict__ Wp,
    float* __restrict__ oq, float* __restrict__ ok, float gain)
{
    float* smem = (float*)dyn_smem;
    const uint32_t sb = smem_u32(dyn_smem);
    const int tid  = threadIdx.x;
    const int warp = tid >> 5;
    const int lane = tid & 31;
    const int g    = lane >> 2;
    const int tig  = lane & 3;
    const int b  = blockIdx.y;
    const int n0 = blockIdx.x * 128;
    const int m0 = 16 * warp;

    qk_load_chunk(sb, 0, X, Wt, Wp, b, n0, 0, tid);
    CP_COMMIT();

    float aq[8][4], ak[8][4];
#pragma unroll
    for (int nc = 0; nc < 8; nc++)
#pragma unroll
        for (int r = 0; r < 4; r++) { aq[nc][r] = 0.f; ak[nc][r] = 0.f; }

    for (int kc = 0; kc < 8; kc++) {
        __syncthreads();
        if (kc + 1 < 8) qk_load_chunk(sb, (kc + 1) & 1, X, Wt, Wp, b, n0, (kc + 1) * 64, tid);
        CP_COMMIT();
        if (kc + 1 < 8) { CP_WAIT(1); } else { CP_WAIT(0); }
        __syncthreads();

        const float* Wtc = smem + (kc & 1) * QK_WCH;
        const float* Wpc = smem + (2 + (kc & 1)) * QK_WCH;
        const float* Xc  = smem + 4 * QK_WCH + (kc & 1) * QK_XCH;

#pragma unroll
        for (int kk = 0; kk < 8; kk++) {
            // A = X^T fragments (built once, shared by theta and phi)
            float x0 = Xc[(8 * kk + tig) * 132 + m0 + g];
            float x1 = Xc[(8 * kk + tig) * 132 + m0 + 8 + g];
            float x2 = Xc[(8 * kk + tig + 4) * 132 + m0 + g];
            float x3 = Xc[(8 * kk + tig + 4) * 132 + m0 + 8 + g];
            float h0 = tf32hi(x0), h1 = tf32hi(x1), h2 = tf32hi(x2), h3 = tf32hi(x3);
            uint32_t Ah[4] = {__float_as_uint(h0), __float_as_uint(h1),
                              __float_as_uint(h2), __float_as_uint(h3)};
            uint32_t Al[4] = {__float_as_uint(x0 - h0), __float_as_uint(x1 - h1),
                              __float_as_uint(x2 - h2), __float_as_uint(x3 - h3)};
#pragma unroll
            for (int nc = 0; nc < 8; nc++) {
                const int wrow = (8 * nc + g) * 68 + 8 * kk + tig;
                uint32_t tb0 = __float_as_uint(tf32hi(Wtc[wrow]));
                uint32_t tb1 = __float_as_uint(tf32hi(Wtc[wrow + 4]));
                mma168(aq[nc], Ah, tb0, tb1);
                mma168(aq[nc], Al, tb0, tb1);
                uint32_t pb0 = __float_as_uint(tf32hi(Wpc[wrow]));
                uint32_t pb1 = __float_as_uint(tf32hi(Wpc[wrow + 4]));
                mma168(ak[nc], Ah, pb0, pb1);
                mma168(ak[nc], Al, pb0, pb1);
            }
        }
    }

#pragma unroll
    for (int nc = 0; nc < 8; nc++) {
        const int o = 8 * nc + 2 * tig;
        const size_t r0 = (size_t)(b * NHW + n0 + m0 + g);
        const size_t r1 = r0 + 8;
        *(float2*)&oq[r0 * 64 + o] = make_float2(tf32hi(aq[nc][0] * gain), tf32hi(aq[nc][1] * gain));
        *(float2*)&oq[r1 * 64 + o] = make_float2(tf32hi(aq[nc][2] * gain), tf32hi(aq[nc][3] * gain));
        *(float2*)&ok[r0 * 64 + o] = make_float2(tf32hi(ak[nc][0] * gain), tf32hi(ak[nc][1] * gain));
        *(float2*)&ok[r1 * 64 + o] = make_float2(tf32hi(ak[nc][2] * gain), tf32hi(ak[nc][3] * gain));
    }
}

// ============================================================
// proj mode0 (g / enc): out[b][o][n], 2x split (W exact hi+lo, X rounded)
// ============================================================
constexpr int WCH = 64 * 68;
constexpr int XCH = 64 * 132;
#define PROJ_SMEM ((2 * WCH + 2 * XCH) * 4)

__device__ __forceinline__ void proj_load_chunk(
    uint32_t sb, int s, const float* X, const float* W, int b, int n0, int c0, int tid)
{
    const uint32_t wdst = sb + (uint32_t)(s * WCH) * 4;
#pragma unroll
    for (int j = 0; j < 4; j++) {
        int idx = tid + j * 256;
        int o = idx >> 4, c4 = (idx & 15) << 2;
        cp16(wdst + (uint32_t)(o * 68 + c4) * 4, W + o * CC + c0 + c4);
    }
    const uint32_t xdst = sb + (uint32_t)(2 * WCH + s * XCH) * 4;
#pragma unroll
    for (int j = 0; j < 8; j++) {
        int idx = tid + j * 256;
        int cl = idx >> 5, n4 = (idx & 31) << 2;
        cp16(xdst + (uint32_t)(cl * 132 + n4) * 4,
             X + ((size_t)(b * CC + c0 + cl)) * NHW + n0 + n4);
    }
}

__global__ __launch_bounds__(256) void proj_mma0_kernel(
    const float* __restrict__ X, const float* __restrict__ W,
    float* __restrict__ out, float gain)
{
    float* smem = (float*)dyn_smem;
    const uint32_t sb = smem_u32(dyn_smem);
    const int tid  = threadIdx.x;
    const int warp = tid >> 5;
    const int lane = tid & 31;
    const int g    = lane >> 2;
    const int tig  = lane & 3;
    const int b  = blockIdx.y;
    const int n0 = blockIdx.x * 128;

    proj_load_chunk(sb, 0, X, W, b, n0, 0, tid);
    CP_COMMIT();

    float acc[4][2][4];
#pragma unroll
    for (int m = 0; m < 4; m++)
#pragma unroll
        for (int t = 0; t < 2; t++)
#pragma unroll
            for (int r = 0; r < 4; r++) acc[m][t][r] = 0.f;

    for (int kc = 0; kc < 8; kc++) {
        __syncthreads();
        if (kc + 1 < 8) proj_load_chunk(sb, (kc + 1) & 1, X, W, b, n0, (kc + 1) * 64, tid);
        CP_COMMIT();
        if (kc + 1 < 8) { CP_WAIT(1); } else { CP_WAIT(0); }
        __syncthreads();

        const float* Wc = smem + (kc & 1) * WCH;
        const float* Xc = smem + 2 * WCH + (kc & 1) * XCH;

#pragma unroll
        for (int kk = 0; kk < 8; kk++) {
            uint32_t Ah[4][4], Al[4][4];
#pragma unroll
            for (int m = 0; m < 4; m++) {
                float w0 = Wc[(16 * m + g) * 68 + 8 * kk + tig];
                float w1 = Wc[(16 * m + 8 + g) * 68 + 8 * kk + tig];
                float w2 = Wc[(16 * m + g) * 68 + 8 * kk + tig + 4];
                float w3 = Wc[(16 * m + 8 + g) * 68 + 8 * kk + tig + 4];
                float h0 = tf32hi(w0), h1 = tf32hi(w1), h2 = tf32hi(w2), h3 = tf32hi(w3);
                Ah[m][0] = __float_as_uint(h0); Ah[m][1] = __float_as_uint(h1);
                Ah[m][2] = __float_as_uint(h2); Ah[m][3] = __float_as_uint(h3);
                Al[m][0] = __float_as_uint(w0 - h0); Al[m][1] = __float_as_uint(w1 - h1);
                Al[m][2] = __float_as_uint(w2 - h2); Al[m][3] = __float_as_uint(w3 - h3);
            }
            uint32_t Bh[2][2];
#pragma unroll
            for (int t = 0; t < 2; t++) {
                Bh[t][0] = __float_as_uint(tf32hi(Xc[(8 * kk + tig) * 132 + 16 * warp + 8 * t + g]));
                Bh[t][1] = __float_as_uint(tf32hi(Xc[(8 * kk + tig + 4) * 132 + 16 * warp + 8 * t + g]));
            }
#pragma unroll
            for (int m = 0; m < 4; m++)
#pragma unroll
                for (int t = 0; t < 2; t++) {
                    mma168(acc[m][t], Ah[m], Bh[t][0], Bh[t][1]);
                    mma168(acc[m][t], Al[m], Bh[t][0], Bh[t][1]);
                }
        }
    }

#pragma unroll
    for (int m = 0; m < 4; m++)
#pragma unroll
        for (int t = 0; t < 2; t++) {
            const int o = 16 * m + g;
            const int n = n0 + 16 * warp + 8 * t + 2 * tig;
            *(float2*)&out[((size_t)(b * LL + o)) * NHW + n] =
                make_float2(acc[m][t][0] * gain, acc[m][t][1] * gain);
            *(float2*)&out[((size_t)(b * LL + o + 8)) * NHW + n] =
                make_float2(acc[m][t][2] * gain, acc[m][t][3] * gain);
        }
}

// ============================================================
// conv_o via mma.sync (1x tf32) + residual (unchanged)
// ============================================================
#define CONV_SMEM ((512 * 68 + 64 * 68) * 4)
__global__ __launch_bounds__(256, 1) void conv_mma_kernel(
    const float* __restrict__ lat, const float* __restrict__ Wo,
    const float* __restrict__ addsrc, const float* __restrict__ gamma,
    float* __restrict__ out)
{
    float* smem = (float*)dyn_smem;
    const uint32_t sb = smem_u32(dyn_smem);

    const int tid  = threadIdx.x;
    const int warp = tid >> 5;
    const int lane = tid & 31;
    const int g    = lane >> 2;
    const int tig  = lane & 3;
    const int b  = blockIdx.y;
    const int n0 = blockIdx.x * 64;

#pragma unroll
    for (int j = 0; j < 32; j++) {
        int idx = tid + j * 256;
        int oc = idx >> 4, l4 = (idx & 15) << 2;
        cp16(sb + (uint32_t)(oc * 68 + l4) * 4, Wo + oc * LL + l4);
    }
#pragma unroll
    for (int j = 0; j < 4; j++) {
        int idx = tid + j * 256;
        int cl = idx >> 4, n4 = (idx & 15) << 2;
        cp16(sb + (uint32_t)(512 * 68 + cl * 68 + n4) * 4,
             lat + ((size_t)(b * LL + cl)) * NHW + n0 + n4);
    }
    CP_COMMIT();
    CP_WAIT(0);
    __syncthreads();

    float acc[4][8][4];
#pragma unroll
    for (int m = 0; m < 4; m++)
#pragma unroll
        for (int nc = 0; nc < 8; nc++)
#pragma unroll
            for (int r = 0; r < 4; r++) acc[m][nc][r] = 0.f;

    const uint32_t* Wu = (const uint32_t*)smem;
    const uint32_t* Lu = (const uint32_t*)(smem + 512 * 68);

#pragma unroll
    for (int kk = 0; kk < 8; kk++) {
        uint32_t A[4][4];
#pragma unroll
        for (int m = 0; m < 4; m++) {
            const int oc = 64 * warp + 16 * m;
            A[m][0] = Wu[(oc + g) * 68 + 8 * kk + tig];
            A[m][1] = Wu[(oc + 8 + g) * 68 + 8 * kk + tig];
            A[m][2] = Wu[(oc + g) * 68 + 8 * kk + tig + 4];
            A[m][3] = Wu[(oc + 8 + g) * 68 + 8 * kk + tig + 4];
        }
#pragma unroll
        for (int nc = 0; nc < 8; nc++) {
            uint32_t b0 = Lu[(8 * kk + tig) * 68 + 8 * nc + g];
            uint32_t b1 = Lu[(8 * kk + tig + 4) * 68 + 8 * nc + g];
#pragma unroll
            for (int m = 0; m < 4; m++) mma168(acc[m][nc], A[m], b0, b1);
        }
    }

    const float coeff = gamma[0] * GAIN_O;
#pragma unroll
    for (int m = 0; m < 4; m++)
#pragma unroll
        for (int nc = 0; nc < 8; nc++) {
            const int oc = 64 * warp + 16 * m + g;
            const int n  = n0 + 8 * nc + 2 * tig;
            const size_t base0 = ((size_t)(b * CC + oc)) * NHW + n;
            const size_t base1 = base0 + (size_t)8 * NHW;
            float2 a0 = *(const float2*)&addsrc[base0];
            float2 a1 = *(const float2*)&addsrc[base1];
            *(float2*)&out[base0] = make_float2(coeff * acc[m][nc][0] + a0.x,
                                                coeff * acc[m][nc][1] + a0.y);
            *(float2*)&out[base1] = make_float2(coeff * acc[m][nc][2] + a1.x,
                                                coeff * acc[m][nc][3] + a1.y);
        }
}

// ============================================================
// MoCA attention (unchanged FFMA)
// ============================================================
#define MOCA_SMEM 223232
__global__ __launch_bounds__(256) void moca_kernel(
    const float* __restrict__ E, const float* __restrict__ Cpt, float* __restrict__ O)
{
    float* smem = (float*)dyn_smem;
    float* Ct = smem;
    float* Cs = Ct + 64 * 260;
    float* Es = Cs + 256 * 68;
    float* Pt = Es + 64 * 68;

    const int tid = threadIdx.x;
    const int b  = blockIdx.y;
    const int n0 = blockIdx.x * 64;
    const int ty = tid >> 4;
    const int tx = tid & 15;

    {
        const int c4 = (tid & 15) << 2;
#pragma unroll
        for (int p2 = 0; p2 < 16; p2++) {
            const int p = (tid >> 4) + p2 * 16;
            float4 v = *(const float4*)&Cpt[p * 64 + c4];
            *(float4*)&Cs[p * 68 + c4] = v;
            Ct[(c4 + 0) * 260 + p] = v.x; Ct[(c4 + 1) * 260 + p] = v.y;
            Ct[(c4 + 2) * 260 + p] = v.z; Ct[(c4 + 3) * 260 + p] = v.w;
        }
    }
    {
        const int nn = (tid & 15) << 2;
#pragma unroll
        for (int p2 = 0; p2 < 4; p2++) {
            const int c = (tid >> 4) + p2 * 16;
            *(float4*)&Es[c * 68 + nn] =
                *(const float4*)&E[(size_t)b * LL * NHW + (size_t)c * NHW + n0 + nn];
        }
    }
    __syncthreads();

    float s[4][16];
#pragma unroll
    for (int i = 0; i < 4; i++)
#pragma unroll
        for (int j = 0; j < 16; j++) s[i][j] = 0.f;

#pragma unroll 4
    for (int c = 0; c < 64; c++) {
        float4 q = *(float4*)&Es[c * 68 + (ty << 2)];
        float qv[4] = {q.x, q.y, q.z, q.w};
#pragma unroll
        for (int kk = 0; kk < 4; kk++) {
            float4 k = *(float4*)&Ct[c * 260 + (tx << 4) + (kk << 2)];
            float kv[4] = {k.x, k.y, k.z, k.w};
#pragma unroll
            for (int i = 0; i < 4; i++)
#pragma unroll
                for (int w = 0; w < 4; w++) s[i][(kk << 2) + w] += qv[i] * kv[w];
        }
    }

#pragma unroll
    for (int i = 0; i < 4; i++) {
        float mx = -1e30f;
#pragma unroll
        for (int j = 0; j < 16; j++) mx = fmaxf(mx, s[i][j]);
        mx = fmaxf(mx, __shfl_xor_sync(0xffffffffu, mx, 1, 16));
        mx = fmaxf(mx, __shfl_xor_sync(0xffffffffu, mx, 2, 16));
        mx = fmaxf(mx, __shfl_xor_sync(0xffffffffu, mx, 4, 16));
        mx = fmaxf(mx, __shfl_xor_sync(0xffffffffu, mx, 8, 16));
        float rs = 0.f;
#pragma unroll
        for (int j = 0; j < 16; j++) { float p = __expf(s[i][j] - mx); s[i][j] = p; rs += p; }
        rs += __shfl_xor_sync(0xffffffffu, rs, 1, 16);
        rs += __shfl_xor_sync(0xffffffffu, rs, 2, 16);
        rs += __shfl_xor_sync(0xffffffffu, rs, 4, 16);
        rs += __shfl_xor_sync(0xffffffffu, rs, 8, 16);
        const float inv = 1.f / rs;
#pragma unroll
        for (int j = 0; j < 16; j++) s[i][j] *= inv;
    }

#pragma unroll
    for (int pp = 0; pp < 16; pp++) {
        const int p = (tx << 4) + pp;
        *(float4*)&Pt[p * 68 + (ty << 2)] = make_float4(s[0][pp], s[1][pp], s[2][pp], s[3][pp]);
    }
    __syncthreads();

    float o_acc[4][4];
#pragma unroll
    for (int i = 0; i < 4; i++)
#pragma unroll
        for (int j = 0; j < 4; j++) o_acc[i][j] = 0.f;

#pragma unroll 8
    for (int p = 0; p < 256; p++) {
        float4 pr = *(float4*)&Pt[p * 68 + (ty << 2)];
        float4 v  = *(float4*)&Cs[p * 68 + (tx << 2)];
        float pv[4] = {pr.x, pr.y, pr.z, pr.w};
        float vv[4] = {v.x, v.y, v.z, v.w};
#pragma unroll
        for (int i = 0; i < 4; i++)
#pragma unroll
            for (int j = 0; j < 4; j++) o_acc[i][j] += pv[i] * vv[j];
    }
#pragma unroll
    for (int i = 0; i < 4; i++) {
        const int n = n0 + (ty << 2) + i;
        *(float4*)&O[(size_t)b * NHW * LL + (size_t)n * LL + (tx << 2)] =
            make_float4(o_acc[i][0], o_acc[i][1], o_acc[i][2], o_acc[i][3]);
    }
}

// ============================================================
extern "C" void kernel_launch(void* const* d_in, const int* in_sizes, int n_in,
                              void* d_out, int out_size)
{
    (void)in_sizes; (void)n_in; (void)out_size;
    const float* fm         = (const float*)d_in[0];
    const float* concepts   = (const float*)d_in[1];
    const float* w_theta    = (const float*)d_in[2];
    const float* w_phi      = (const float*)d_in[3];
    const float* w_g        = (const float*)d_in[4];
    const float* w_o        = (const float*)d_in[5];
    const float* gamma_sa   = (const float*)d_in[6];
    const float* gamma_moca = (const float*)d_in[7];
    float* out = (float*)d_out;

    float *qh, *kh, *gv, *lat, *sa, *enc, *lat2;
    cudaGetSymbolAddress((void**)&qh,  g_qh);
    cudaGetSymbolAddress((void**)&kh,  g_kh);
    cudaGetSymbolAddress((void**)&gv,  g_gv);
    cudaGetSymbolAddress((void**)&lat, g_lat);
    cudaGetSymbolAddress((void**)&sa,  g_sa);
    cudaGetSymbolAddress((void**)&enc, g_enc);
    cudaGetSymbolAddress((void**)&lat2, g_lat2);

    cudaFuncSetAttribute(flash_mma_kernel, cudaFuncAttributeMaxDynamicSharedMemorySize, FT_SMEM);
    cudaFuncSetAttribute(proj_qk_kernel,   cudaFuncAttributeMaxDynamicSharedMemorySize, QK_SMEM);
    cudaFuncSetAttribute(proj_mma0_kernel, cudaFuncAttributeMaxDynamicSharedMemorySize, PROJ_SMEM);
    cudaFuncSetAttribute(conv_mma_kernel,  cudaFuncAttributeMaxDynamicSharedMemorySize, CONV_SMEM);
    cudaFuncSetAttribute(moca_kernel,      cudaFuncAttributeMaxDynamicSharedMemorySize, MOCA_SMEM);

    const dim3 pgrid(32, 8);
    proj_qk_kernel<<<pgrid, 256, QK_SMEM>>>(fm, w_theta, w_phi, qh, kh, GAIN_IN);
    proj_mma0_kernel<<<pgrid, 256, PROJ_SMEM>>>(fm, w_g, gv, GAIN_IN);
    flash_mma_kernel<<<dim3(16, 8), 256, FT_SMEM>>>(qh, kh, gv, lat);
    conv_mma_kernel<<<dim3(64, 8), 256, CONV_SMEM>>>(lat, w_o, fm, gamma_sa, sa);
    proj_mma0_kernel<<<pgrid, 256, PROJ_SMEM>>>(sa, w_theta, enc, GAIN_IN);
    moca_kernel<<<dim3(64, 8), 256, MOCA_SMEM>>>(enc, concepts, lat2);
    conv_mma_kernel<<<dim3(64, 8), 256, CONV_SMEM>>>(lat2, w_o, sa, gamma_moca, out);
}

// round 11
// speedup vs baseline: 1.8988x; 1.2658x over previous
#include <cuda_runtime.h>
#include <cstdint>

constexpr int BB  = 8;
constexpr int CC  = 512;
constexpr int LL  = 64;
constexpr int NHW = 4096;

#define GAIN_IN 0.04419417382415922f
#define GAIN_O  0.125f

// -------- device scratch --------
__device__ float g_qh [BB * NHW * LL];   // theta proj, [b][n][c], tf32-rounded
__device__ float g_kh [BB * NHW * LL];   // phi proj,   [b][n][c], tf32-rounded
__device__ float g_vv [BB * NHW * LL];   // g proj,     [b][n][c], raw fp32
__device__ float g_lat[BB * NHW * LL];
__device__ float g_sa [BB * CC * NHW];
__device__ float g_enc[BB * NHW * LL];   // [b][n][c] raw fp32
__device__ float g_lat2[BB * NHW * LL];

extern __shared__ char dyn_smem[];

// ============================================================
// helpers
// ============================================================
__device__ __forceinline__ uint32_t smem_u32(const void* p) {
    uint32_t r;
    asm("{ .reg .u64 t; cvta.to.shared.u64 t, %1; cvt.u32.u64 %0, t; }" : "=r"(r) : "l"(p));
    return r;
}
__device__ __forceinline__ void cp16(uint32_t dst, const void* src) {
    asm volatile("cp.async.cg.shared.global [%0], [%1], 16;" :: "r"(dst), "l"(src));
}
#define CP_COMMIT() asm volatile("cp.async.commit_group;" ::: "memory")
#define CP_WAIT(n)  asm volatile("cp.async.wait_group %0;" :: "n"(n) : "memory")

__device__ __forceinline__ float tf32hi(float v) {
    float h;
    asm("cvt.rna.tf32.f32 %0, %1;" : "=f"(h) : "f"(v));
    return h;
}
__device__ __forceinline__ void mma168(float* d, const uint32_t* a, uint32_t b0, uint32_t b1) {
    asm volatile(
        "mma.sync.aligned.m16n8k8.row.col.f32.tf32.tf32.f32 "
        "{%0,%1,%2,%3}, {%4,%5,%6,%7}, {%8,%9}, {%0,%1,%2,%3};"
        : "+f"(d[0]), "+f"(d[1]), "+f"(d[2]), "+f"(d[3])
        : "r"(a[0]), "r"(a[1]), "r"(a[2]), "r"(a[3]), "r"(b0), "r"(b1));
}

// ============================================================
// flash attention v5: 1x tf32 S and PV. V in [n][c] layout, PAD 72.
// 256 threads / 8 warps, 32 q rows/warp, grid 16x8 (1 wave).
// ============================================================
constexpr int PAD  = 68;
constexpr int VPAD = 72;
constexpr int QROWS   = 256;
constexpr int QT_F    = QROWS * PAD;          // 17408
constexpr int OFF_Q   = 0;
constexpr int OFF_K   = QT_F;                 // 17408
constexpr int KSLOT_F = 64 * PAD;             // 4352
constexpr int OFF_V   = OFF_K + 2 * KSLOT_F;  // 26112
constexpr int VSLOT_F = 64 * VPAD;            // 4608
#define FT_SMEM ((OFF_V + 2 * VSLOT_F) * 4)   // 141312 bytes

__device__ __forceinline__ void loadK1(uint32_t dst, const float* Kh,
                                       int b, int m0, int tid) {
    const size_t row0 = (size_t)(b * NHW + m0);
#pragma unroll
    for (int j = 0; j < 4; j++) {
        int idx = j * 256 + tid;
        int r = idx >> 4, c4 = idx & 15;
        cp16(dst + (uint32_t)(r * PAD * 4 + c4 * 16), Kh + (row0 + r) * 64 + c4 * 4);
    }
}
__device__ __forceinline__ void loadV1(uint32_t dst, const float* Vg, int b, int m0, int tid) {
    const size_t row0 = (size_t)(b * NHW + m0);
#pragma unroll
    for (int j = 0; j < 4; j++) {
        int idx = j * 256 + tid;
        int r = idx >> 4, c4 = idx & 15;
        cp16(dst + (uint32_t)(r * VPAD * 4 + c4 * 16), Vg + (row0 + r) * 64 + c4 * 4);
    }
}

__global__ __launch_bounds__(256, 1) void flash_mma_kernel(
    const float* __restrict__ Qg, const float* __restrict__ Kg,
    const float* __restrict__ Vg, float* __restrict__ Og)
{
    float* smem = (float*)dyn_smem;
    const uint32_t sb = smem_u32(dyn_smem);
    const int tid  = threadIdx.x;
    const int warp = tid >> 5;
    const int lane = tid & 31;
    const int g    = lane >> 2;
    const int tig  = lane & 3;
    const int b  = blockIdx.y;
    const int n0 = blockIdx.x * QROWS;
    const int NT = 64;

    {
        const size_t qr0 = (size_t)(b * NHW + n0);
#pragma unroll
        for (int j = 0; j < 16; j++) {
            int idx = j * 256 + tid;
            int r = idx >> 4, c4 = idx & 15;
            cp16(sb + OFF_Q * 4 + (uint32_t)(r * PAD * 4 + c4 * 16),
                 Qg + (qr0 + r) * 64 + c4 * 4);
        }
        loadK1(sb + OFF_K * 4, Kg, b, 0, tid);
        loadV1(sb + OFF_V * 4, Vg, b, 0, tid);
        CP_COMMIT();
    }

    const uint32_t* Qh = (const uint32_t*)(smem + OFF_Q);

    float Oa[2][8][4];
    float lsum[2][2];
#pragma unroll
    for (int m = 0; m < 2; m++) {
        lsum[m][0] = 0.f; lsum[m][1] = 0.f;
#pragma unroll
        for (int c = 0; c < 8; c++)
#pragma unroll
            for (int r = 0; r < 4; r++) Oa[m][c][r] = 0.f;
    }

    const int q0 = warp * 32;

    for (int i = 0; i < NT; i++) {
        __syncthreads();
        if (i + 1 < NT) {
            loadK1(sb + (uint32_t)(OFF_K + ((i + 1) & 1) * KSLOT_F) * 4, Kg, b, (i + 1) * 64, tid);
            loadV1(sb + (uint32_t)(OFF_V + ((i + 1) & 1) * VSLOT_F) * 4, Vg, b, (i + 1) * 64, tid);
        }
        CP_COMMIT();
        CP_WAIT(1);
        __syncthreads();

        const uint32_t* Kh = (const uint32_t*)(smem + OFF_K + (i & 1) * KSLOT_F);
        const uint32_t* Vt = (const uint32_t*)(smem + OFF_V + (i & 1) * VSLOT_F);

        // ---- S = Q K^T, 1x tf32 ----
        float S[2][8][4];
#pragma unroll
        for (int m = 0; m < 2; m++)
#pragma unroll
            for (int n = 0; n < 8; n++)
#pragma unroll
                for (int r = 0; r < 4; r++) S[m][n][r] = 0.f;

#pragma unroll
        for (int k = 0; k < 8; k++) {
            uint32_t Ah[2][4];
#pragma unroll
            for (int m = 0; m < 2; m++) {
                const int qr = q0 + 16 * m;
                Ah[m][0] = Qh[(qr + g) * PAD + 8 * k + tig];
                Ah[m][1] = Qh[(qr + 8 + g) * PAD + 8 * k + tig];
                Ah[m][2] = Qh[(qr + g) * PAD + 8 * k + tig + 4];
                Ah[m][3] = Qh[(qr + 8 + g) * PAD + 8 * k + tig + 4];
            }
#pragma unroll
            for (int n = 0; n < 8; n++) {
                const int krow = 8 * n + g;
                uint32_t bh0 = Kh[krow * PAD + 8 * k + tig];
                uint32_t bh1 = Kh[krow * PAD + 8 * k + tig + 4];
                mma168(S[0][n], Ah[0], bh0, bh1);
                mma168(S[1][n], Ah[1], bh0, bh1);
            }
        }

        // ---- P = exp(S) ----
#pragma unroll
        for (int m = 0; m < 2; m++) {
            float s0 = 0.f, s1 = 0.f;
#pragma unroll
            for (int n = 0; n < 8; n++) {
                float p0 = __expf(S[m][n][0]);
                float p1 = __expf(S[m][n][1]);
                float p2 = __expf(S[m][n][2]);
                float p3 = __expf(S[m][n][3]);
                S[m][n][0] = p0; S[m][n][1] = p1;
                S[m][n][2] = p2; S[m][n][3] = p3;
                s0 += p0 + p1; s1 += p2 + p3;
            }
            lsum[m][0] += s0; lsum[m][1] += s1;
        }

        // ---- O += P V ----
        const int base = lane & ~3;
        const int srcA = base | (tig >> 1);
        const int srcB = srcA + 2;
        const bool odd = (tig & 1);
#pragma unroll
        for (int n = 0; n < 8; n++) {
            uint32_t Ap[2][4];
#pragma unroll
            for (int m = 0; m < 2; m++) {
                float e0  = __shfl_sync(0xffffffffu, S[m][n][0], srcA);
                float e1  = __shfl_sync(0xffffffffu, S[m][n][1], srcA);
                float e2  = __shfl_sync(0xffffffffu, S[m][n][2], srcA);
                float e3  = __shfl_sync(0xffffffffu, S[m][n][3], srcA);
                float f0  = __shfl_sync(0xffffffffu, S[m][n][0], srcB);
                float f1  = __shfl_sync(0xffffffffu, S[m][n][1], srcB);
                float f2  = __shfl_sync(0xffffffffu, S[m][n][2], srcB);
                float f3  = __shfl_sync(0xffffffffu, S[m][n][3], srcB);
                Ap[m][0] = __float_as_uint(odd ? e1 : e0);
                Ap[m][1] = __float_as_uint(odd ? e3 : e2);
                Ap[m][2] = __float_as_uint(odd ? f1 : f0);
                Ap[m][3] = __float_as_uint(odd ? f3 : f2);
            }
#pragma unroll
            for (int c = 0; c < 8; c++) {
                // B[k=m][n=c] from V rows [m][c], PAD 72 (conflict-free)
                uint32_t b0 = Vt[(8 * n + tig) * VPAD + 8 * c + g];
                uint32_t b1 = Vt[(8 * n + tig + 4) * VPAD + 8 * c + g];
                mma168(Oa[0][c], Ap[0], b0, b1);
                mma168(Oa[1][c], Ap[1], b0, b1);
            }
        }
    }

    // ---- epilogue ----
#pragma unroll
    for (int m = 0; m < 2; m++)
#pragma unroll
        for (int h = 0; h < 2; h++) {
            lsum[m][h] += __shfl_xor_sync(0xffffffffu, lsum[m][h], 1);
            lsum[m][h] += __shfl_xor_sync(0xffffffffu, lsum[m][h], 2);
            lsum[m][h] = 1.f / lsum[m][h];
        }

#pragma unroll
    for (int m = 0; m < 2; m++) {
        const int r0 = n0 + q0 + 16 * m + g;
#pragma unroll
        for (int c = 0; c < 8; c++) {
            float2 v0 = make_float2(Oa[m][c][0] * lsum[m][0], Oa[m][c][1] * lsum[m][0]);
            float2 v1 = make_float2(Oa[m][c][2] * lsum[m][1], Oa[m][c][3] * lsum[m][1]);
            *(float2*)&Og[((size_t)(b * NHW) + r0)     * 64 + 8 * c + 2 * tig] = v0;
            *(float2*)&Og[((size_t)(b * NHW) + r0 + 8) * 64 + 8 * c + 2 * tig] = v1;
        }
    }
}

// ============================================================
// fused theta+phi+g projection: q/k/v = gain * X^T W^T, [b][n][64].
// 2x split (X exact hi+lo, W rounded). X fragments built once, used 3x.
// q,k stored tf32-rounded; v raw fp32.
// ============================================================
constexpr int QK_WCH = 64 * 68;    // 4352
constexpr int QK_XCH = 64 * 132;   // 8448
constexpr int QKV_XOFF = 6 * QK_WCH;   // 26112
#define QKV_SMEM ((6 * QK_WCH + 2 * QK_XCH) * 4)   // 172032

__device__ __forceinline__ void qkv_load_chunk(
    uint32_t sb, int s, const float* X, const float* Wt, const float* Wp, const float* Wg,
    int b, int n0, int c0, int tid)
{
#pragma unroll
    for (int j = 0; j < 4; j++) {
        int idx = tid + j * 256;
        int o = idx >> 4, c4 = (idx & 15) << 2;
        uint32_t doff = (uint32_t)(o * 68 + c4) * 4;
        const int soff = o * CC + c0 + c4;
        cp16(sb + (uint32_t)((0 + s) * QK_WCH) * 4 + doff, Wt + soff);
        cp16(sb + (uint32_t)((2 + s) * QK_WCH) * 4 + doff, Wp + soff);
        cp16(sb + (uint32_t)((4 + s) * QK_WCH) * 4 + doff, Wg + soff);
    }
    const uint32_t xd = sb + (uint32_t)(QKV_XOFF + s * QK_XCH) * 4;
#pragma unroll
    for (int j = 0; j < 8; j++) {
        int idx = tid + j * 256;
        int cl = idx >> 5, n4 = (idx & 31) << 2;
        cp16(xd + (uint32_t)(cl * 132 + n4) * 4,
             X + ((size_t)(b * CC + c0 + cl)) * NHW + n0 + n4);
    }
}

__global__ __launch_bounds__(256) void proj_qkv_kernel(
    const float* __restrict__ X, const float* __restrict__ Wt,
    const float* __restrict__ Wp, const float* __restrict__ Wg,
    float* __restrict__ oq, float* __restrict__ ok, float* __restrict__ ov, float gain)
{
    float* smem = (float*)dyn_smem;
    const uint32_t sb = smem_u32(dyn_smem);
    const int tid  = threadIdx.x;
    const int warp = tid >> 5;
    const int lane = tid & 31;
    const int g    = lane >> 2;
    const int tig  = lane & 3;
    const int b  = blockIdx.y;
    const int n0 = blockIdx.x * 128;
    const int m0 = 16 * warp;

    qkv_load_chunk(sb, 0, X, Wt, Wp, Wg, b, n0, 0, tid);
    CP_COMMIT();

    float aq[8][4], ak[8][4], av[8][4];
#pragma unroll
    for (int nc = 0; nc < 8; nc++)
#pragma unroll
        for (int r = 0; r < 4; r++) { aq[nc][r] = 0.f; ak[nc][r] = 0.f; av[nc][r] = 0.f; }

    for (int kc = 0; kc < 8; kc++) {
        __syncthreads();
        if (kc + 1 < 8) qkv_load_chunk(sb, (kc + 1) & 1, X, Wt, Wp, Wg, b, n0, (kc + 1) * 64, tid);
        CP_COMMIT();
        if (kc + 1 < 8) { CP_WAIT(1); } else { CP_WAIT(0); }
        __syncthreads();

        const float* Wtc = smem + (0 + (kc & 1)) * QK_WCH;
        const float* Wpc = smem + (2 + (kc & 1)) * QK_WCH;
        const float* Wgc = smem + (4 + (kc & 1)) * QK_WCH;
        const float* Xc  = smem + QKV_XOFF + (kc & 1) * QK_XCH;

#pragma unroll
        for (int kk = 0; kk < 8; kk++) {
            float x0 = Xc[(8 * kk + tig) * 132 + m0 + g];
            float x1 = Xc[(8 * kk + tig) * 132 + m0 + 8 + g];
            float x2 = Xc[(8 * kk + tig + 4) * 132 + m0 + g];
            float x3 = Xc[(8 * kk + tig + 4) * 132 + m0 + 8 + g];
            float h0 = tf32hi(x0), h1 = tf32hi(x1), h2 = tf32hi(x2), h3 = tf32hi(x3);
            uint32_t Ah[4] = {__float_as_uint(h0), __float_as_uint(h1),
                              __float_as_uint(h2), __float_as_uint(h3)};
            uint32_t Al[4] = {__float_as_uint(x0 - h0), __float_as_uint(x1 - h1),
                              __float_as_uint(x2 - h2), __float_as_uint(x3 - h3)};
#pragma unroll
            for (int nc = 0; nc < 8; nc++) {
                const int wrow = (8 * nc + g) * 68 + 8 * kk + tig;
                uint32_t tb0 = __float_as_uint(tf32hi(Wtc[wrow]));
                uint32_t tb1 = __float_as_uint(tf32hi(Wtc[wrow + 4]));
                mma168(aq[nc], Ah, tb0, tb1);
                mma168(aq[nc], Al, tb0, tb1);
                uint32_t pb0 = __float_as_uint(tf32hi(Wpc[wrow]));
                uint32_t pb1 = __float_as_uint(tf32hi(Wpc[wrow + 4]));
                mma168(ak[nc], Ah, pb0, pb1);
                mma168(ak[nc], Al, pb0, pb1);
                uint32_t gb0 = __float_as_uint(tf32hi(Wgc[wrow]));
                uint32_t gb1 = __float_as_uint(tf32hi(Wgc[wrow + 4]));
                mma168(av[nc], Ah, gb0, gb1);
                mma168(av[nc], Al, gb0, gb1);
            }
        }
    }

#pragma unroll
    for (int nc = 0; nc < 8; nc++) {
        const int o = 8 * nc + 2 * tig;
        const size_t r0 = (size_t)(b * NHW + n0 + m0 + g);
        const size_t r1 = r0 + 8;
        *(float2*)&oq[r0 * 64 + o] = make_float2(tf32hi(aq[nc][0] * gain), tf32hi(aq[nc][1] * gain));
        *(float2*)&oq[r1 * 64 + o] = make_float2(tf32hi(aq[nc][2] * gain), tf32hi(aq[nc][3] * gain));
        *(float2*)&ok[r0 * 64 + o] = make_float2(tf32hi(ak[nc][0] * gain), tf32hi(ak[nc][1] * gain));
        *(float2*)&ok[r1 * 64 + o] = make_float2(tf32hi(ak[nc][2] * gain), tf32hi(ak[nc][3] * gain));
        *(float2*)&ov[r0 * 64 + o] = make_float2(av[nc][0] * gain, av[nc][1] * gain);
        *(float2*)&ov[r1 * 64 + o] = make_float2(av[nc][2] * gain, av[nc][3] * gain);
    }
}

// ============================================================
// proj_nc: single-weight projection -> [b][n][64] raw fp32 (enc)
// ============================================================
#define NC_SMEM ((2 * QK_WCH + 2 * QK_XCH) * 4)   // 102400

__device__ __forceinline__ void nc_load_chunk(
    uint32_t sb, int s, const float* X, const float* W, int b, int n0, int c0, int tid)
{
#pragma unroll
    for (int j = 0; j < 4; j++) {
        int idx = tid + j * 256;
        int o = idx >> 4, c4 = (idx & 15) << 2;
        cp16(sb + (uint32_t)(s * QK_WCH + o * 68 + c4) * 4, W + o * CC + c0 + c4);
    }
    const uint32_t xd = sb + (uint32_t)(2 * QK_WCH + s * QK_XCH) * 4;
#pragma unroll
    for (int j = 0; j < 8; j++) {
        int idx = tid + j * 256;
        int cl = idx >> 5, n4 = (idx & 31) << 2;
        cp16(xd + (uint32_t)(cl * 132 + n4) * 4,
             X + ((size_t)(b * CC + c0 + cl)) * NHW + n0 + n4);
    }
}

__global__ __launch_bounds__(256) void proj_nc_kernel(
    const float* __restrict__ X, const float* __restrict__ W,
    float* __restrict__ oe, float gain)
{
    float* smem = (float*)dyn_smem;
    const uint32_t sb = smem_u32(dyn_smem);
    const int tid  = threadIdx.x;
    const int warp = tid >> 5;
    const int lane = tid & 31;
    const int g    = lane >> 2;
    const int tig  = lane & 3;
    const int b  = blockIdx.y;
    const int n0 = blockIdx.x * 128;
    const int m0 = 16 * warp;

    nc_load_chunk(sb, 0, X, W, b, n0, 0, tid);
    CP_COMMIT();

    float acc[8][4];
#pragma unroll
    for (int nc = 0; nc < 8; nc++)
#pragma unroll
        for (int r = 0; r < 4; r++) acc[nc][r] = 0.f;

    for (int kc = 0; kc < 8; kc++) {
        __syncthreads();
        if (kc + 1 < 8) nc_load_chunk(sb, (kc + 1) & 1, X, W, b, n0, (kc + 1) * 64, tid);
        CP_COMMIT();
        if (kc + 1 < 8) { CP_WAIT(1); } else { CP_WAIT(0); }
        __syncthreads();

        const float* Wc = smem + (kc & 1) * QK_WCH;
        const float* Xc = smem + 2 * QK_WCH + (kc & 1) * QK_XCH;

#pragma unroll
        for (int kk = 0; kk < 8; kk++) {
            float x0 = Xc[(8 * kk + tig) * 132 + m0 + g];
            float x1 = Xc[(8 * kk + tig) * 132 + m0 + 8 + g];
            float x2 = Xc[(8 * kk + tig + 4) * 132 + m0 + g];
            float x3 = Xc[(8 * kk + tig + 4) * 132 + m0 + 8 + g];
            float h0 = tf32hi(x0), h1 = tf32hi(x1), h2 = tf32hi(x2), h3 = tf32hi(x3);
            uint32_t Ah[4] = {__float_as_uint(h0), __float_as_uint(h1),
                              __float_as_uint(h2), __float_as_uint(h3)};
            uint32_t Al[4] = {__float_as_uint(x0 - h0), __float_as_uint(x1 - h1),
                              __float_as_uint(x2 - h2), __float_as_uint(x3 - h3)};
#pragma unroll
            for (int nc = 0; nc < 8; nc++) {
                const int wrow = (8 * nc + g) * 68 + 8 * kk + tig;
                uint32_t b0 = __float_as_uint(tf32hi(Wc[wrow]));
                uint32_t b1 = __float_as_uint(tf32hi(Wc[wrow + 4]));
                mma168(acc[nc], Ah, b0, b1);
                mma168(acc[nc], Al, b0, b1);
            }
        }
    }

#pragma unroll
    for (int nc = 0; nc < 8; nc++) {
        const int o = 8 * nc + 2 * tig;
        const size_t r0 = (size_t)(b * NHW + n0 + m0 + g);
        const size_t r1 = r0 + 8;
        *(float2*)&oe[r0 * 64 + o] = make_float2(acc[nc][0] * gain, acc[nc][1] * gain);
        *(float2*)&oe[r1 * 64 + o] = make_float2(acc[nc][2] * gain, acc[nc][3] * gain);
    }
}

// ============================================================
// MoCA via mma.sync: mini-flash, concepts resident (two layouts).
// enc [b][n][64]; 256 n rows/CTA, 4 p-tiles of 64; grid 16x8.
// ============================================================
constexpr int MC68_OFF = 0;                  // [256 p][68]
constexpr int MC72_OFF = 256 * 68;           // 17408, [256 p][72]
constexpr int MES_OFF  = MC72_OFF + 256 * 72; // 35840, [256 n][68]
#define MOCA_SMEM ((MES_OFF + 256 * 68) * 4)  // 212992

__global__ __launch_bounds__(256, 1) void moca_mma_kernel(
    const float* __restrict__ E, const float* __restrict__ Cpt, float* __restrict__ O)
{
    float* smem = (float*)dyn_smem;
    const uint32_t sb = smem_u32(dyn_smem);
    const int tid  = threadIdx.x;
    const int warp = tid >> 5;
    const int lane = tid & 31;
    const int g    = lane >> 2;
    const int tig  = lane & 3;
    const int b  = blockIdx.y;
    const int n0 = blockIdx.x * 256;

    // loads: concepts (both layouts) + enc tile
    {
        const size_t er0 = (size_t)(b * NHW + n0);
#pragma unroll
        for (int j = 0; j < 16; j++) {
            int idx = j * 256 + tid;          // 0..4095
            int r = idx >> 4, c4 = idx & 15;
            const float* csrc = Cpt + r * 64 + c4 * 4;
            cp16(sb + (uint32_t)(MC68_OFF + r * 68 + c4 * 4) * 4, csrc);
            cp16(sb + (uint32_t)(MC72_OFF + r * 72 + c4 * 4) * 4, csrc);
            cp16(sb + (uint32_t)(MES_OFF + r * 68 + c4 * 4) * 4,
                 E + (er0 + r) * 64 + c4 * 4);
        }
        CP_COMMIT();
        CP_WAIT(0);
        __syncthreads();
    }

    const uint32_t* Cs68 = (const uint32_t*)(smem + MC68_OFF);
    const uint32_t* Cs72 = (const uint32_t*)(smem + MC72_OFF);
    const uint32_t* Es   = (const uint32_t*)(smem + MES_OFF);

    float Oa[2][8][4];
    float lsum[2][2];
#pragma unroll
    for (int m = 0; m < 2; m++) {
        lsum[m][0] = 0.f; lsum[m][1] = 0.f;
#pragma unroll
        for (int c = 0; c < 8; c++)
#pragma unroll
            for (int r = 0; r < 4; r++) Oa[m][c][r] = 0.f;
    }

    const int q0 = warp * 32;

#pragma unroll
    for (int pt = 0; pt < 4; pt++) {
        const int p0 = pt * 64;

        // ---- S = E C^T, 1x tf32 ----
        float S[2][8][4];
#pragma unroll
        for (int m = 0; m < 2; m++)
#pragma unroll
            for (int n = 0; n < 8; n++)
#pragma unroll
                for (int r = 0; r < 4; r++) S[m][n][r] = 0.f;

#pragma unroll
        for (int k = 0; k < 8; k++) {
            uint32_t Ah[2][4];
#pragma unroll
            for (int m = 0; m < 2; m++) {
                const int qr = q0 + 16 * m;
                Ah[m][0] = Es[(qr + g) * PAD + 8 * k + tig];
                Ah[m][1] = Es[(qr + 8 + g) * PAD + 8 * k + tig];
                Ah[m][2] = Es[(qr + g) * PAD + 8 * k + tig + 4];
                Ah[m][3] = Es[(qr + 8 + g) * PAD + 8 * k + tig + 4];
            }
#pragma unroll
            for (int n = 0; n < 8; n++) {
                const int prow = p0 + 8 * n + g;
                uint32_t bh0 = Cs68[prow * PAD + 8 * k + tig];
                uint32_t bh1 = Cs68[prow * PAD + 8 * k + tig + 4];
                mma168(S[0][n], Ah[0], bh0, bh1);
                mma168(S[1][n], Ah[1], bh0, bh1);
            }
        }

        // ---- P = exp(S) ----
#pragma unroll
        for (int m = 0; m < 2; m++) {
            float s0 = 0.f, s1 = 0.f;
#pragma unroll
            for (int n = 0; n < 8; n++) {
                float p0f = __expf(S[m][n][0]);
                float p1f = __expf(S[m][n][1]);
                float p2f = __expf(S[m][n][2]);
                float p3f = __expf(S[m][n][3]);
                S[m][n][0] = p0f; S[m][n][1] = p1f;
                S[m][n][2] = p2f; S[m][n][3] = p3f;
                s0 += p0f + p1f; s1 += p2f + p3f;
            }
            lsum[m][0] += s0; lsum[m][1] += s1;
        }

        // ---- O += P C ----
        const int base = lane & ~3;
        const int srcA = base | (tig >> 1);
        const int srcB = srcA + 2;
        const bool odd = (tig & 1);
#pragma unroll
        for (int n = 0; n < 8; n++) {
            uint32_t Ap[2][4];
#pragma unroll
            for (int m = 0; m < 2; m++) {
                float e0  = __shfl_sync(0xffffffffu, S[m][n][0], srcA);
                float e1  = __shfl_sync(0xffffffffu, S[m][n][1], srcA);
                float e2  = __shfl_sync(0xffffffffu, S[m][n][2], srcA);
                float e3  = __shfl_sync(0xffffffffu, S[m][n][3], srcA);
                float f0  = __shfl_sync(0xffffffffu, S[m][n][0], srcB);
                float f1  = __shfl_sync(0xffffffffu, S[m][n][1], srcB);
                float f2  = __shfl_sync(0xffffffffu, S[m][n][2], srcB);
                float f3  = __shfl_sync(0xffffffffu, S[m][n][3], srcB);
                Ap[m][0] = __float_as_uint(odd ? e1 : e0);
                Ap[m][1] = __float_as_uint(odd ? e3 : e2);
                Ap[m][2] = __float_as_uint(odd ? f1 : f0);
                Ap[m][3] = __float_as_uint(odd ? f3 : f2);
            }
#pragma unroll
            for (int c = 0; c < 8; c++) {
                uint32_t b0 = Cs72[(p0 + 8 * n + tig) * VPAD + 8 * c + g];
                uint32_t b1 = Cs72[(p0 + 8 * n + tig + 4) * VPAD + 8 * c + g];
                mma168(Oa[0][c], Ap[0], b0, b1);
                mma168(Oa[1][c], Ap[1], b0, b1);
            }
        }
    }

    // ---- epilogue ----
#pragma unroll
    for (int m = 0; m < 2; m++)
#pragma unroll
        for (int h = 0; h < 2; h++) {
            lsum[m][h] += __shfl_xor_sync(0xffffffffu, lsum[m][h], 1);
            lsum[m][h] += __shfl_xor_sync(0xffffffffu, lsum[m][h], 2);
            lsum[m][h] = 1.f / lsum[m][h];
        }

#pragma unroll
    for (int m = 0; m < 2; m++) {
        const int r0 = n0 + q0 + 16 * m + g;
#pragma unroll
        for (int c = 0; c < 8; c++) {
            float2 v0 = make_float2(Oa[m][c][0] * lsum[m][0], Oa[m][c][1] * lsum[m][0]);
            float2 v1 = make_float2(Oa[m][c][2] * lsum[m][1], Oa[m][c][3] * lsum[m][1]);
            *(float2*)&O[((size_t)(b * NHW) + r0)     * 64 + 8 * c + 2 * tig] = v0;
            *(float2*)&O[((size_t)(b * NHW) + r0 + 8) * 64 + 8 * c + 2 * tig] = v1;
        }
    }
}

// ============================================================
// conv_o via mma.sync (1x tf32) + residual (unchanged)
// ============================================================
#define CONV_SMEM ((512 * 68 + 64 * 68) * 4)
__global__ __launch_bounds__(256, 1) void conv_mma_kernel(
    const float* __restrict__ lat, const float* __restrict__ Wo,
    const float* __restrict__ addsrc, const float* __restrict__ gamma,
    float* __restrict__ out)
{
    float* smem = (float*)dyn_smem;
    const uint32_t sb = smem_u32(dyn_smem);

    const int tid  = threadIdx.x;
    const int warp = tid >> 5;
    const int lane = tid & 31;
    const int g    = lane >> 2;
    const int tig  = lane & 3;
    const int b  = blockIdx.y;
    const int n0 = blockIdx.x * 64;

#pragma unroll
    for (int j = 0; j < 32; j++) {
        int idx = tid + j * 256;
        int oc = idx >> 4, l4 = (idx & 15) << 2;
        cp16(sb + (uint32_t)(oc * 68 + l4) * 4, Wo + oc * LL + l4);
    }
#pragma unroll
    for (int j = 0; j < 4; j++) {
        int idx = tid + j * 256;
        int cl = idx >> 4, n4 = (idx & 15) << 2;
        cp16(sb + (uint32_t)(512 * 68 + cl * 68 + n4) * 4,
             lat + ((size_t)(b * LL + cl)) * NHW + n0 + n4);
    }
    CP_COMMIT();
    CP_WAIT(0);
    __syncthreads();

    float acc[4][8][4];
#pragma unroll
    for (int m = 0; m < 4; m++)
#pragma unroll
        for (int nc = 0; nc < 8; nc++)
#pragma unroll
            for (int r = 0; r < 4; r++) acc[m][nc][r] = 0.f;

    const uint32_t* Wu = (const uint32_t*)smem;
    const uint32_t* Lu = (const uint32_t*)(smem + 512 * 68);

#pragma unroll
    for (int kk = 0; kk < 8; kk++) {
        uint32_t A[4][4];
#pragma unroll
        for (int m = 0; m < 4; m++) {
            const int oc = 64 * warp + 16 * m;
            A[m][0] = Wu[(oc + g) * 68 + 8 * kk + tig];
            A[m][1] = Wu[(oc + 8 + g) * 68 + 8 * kk + tig];
            A[m][2] = Wu[(oc + g) * 68 + 8 * kk + tig + 4];
            A[m][3] = Wu[(oc + 8 + g) * 68 + 8 * kk + tig + 4];
        }
#pragma unroll
        for (int nc = 0; nc < 8; nc++) {
            uint32_t b0 = Lu[(8 * kk + tig) * 68 + 8 * nc + g];
            uint32_t b1 = Lu[(8 * kk + tig + 4) * 68 + 8 * nc + g];
#pragma unroll
            for (int m = 0; m < 4; m++) mma168(acc[m][nc], A[m], b0, b1);
        }
    }

    const float coeff = gamma[0] * GAIN_O;
#pragma unroll
    for (int m = 0; m < 4; m++)
#pragma unroll
        for (int nc = 0; nc < 8; nc++) {
            const int oc = 64 * warp + 16 * m + g;
            const int n  = n0 + 8 * nc + 2 * tig;
            const size_t base0 = ((size_t)(b * CC + oc)) * NHW + n;
            const size_t base1 = base0 + (size_t)8 * NHW;
            float2 a0 = *(const float2*)&addsrc[base0];
            float2 a1 = *(const float2*)&addsrc[base1];
            *(float2*)&out[base0] = make_float2(coeff * acc[m][nc][0] + a0.x,
                                                coeff * acc[m][nc][1] + a0.y);
            *(float2*)&out[base1] = make_float2(coeff * acc[m][nc][2] + a1.x,
                                                coeff * acc[m][nc][3] + a1.y);
        }
}

// ============================================================
extern "C" void kernel_launch(void* const* d_in, const int* in_sizes, int n_in,
                              void* d_out, int out_size)
{
    (void)in_sizes; (void)n_in; (void)out_size;
    const float* fm         = (const float*)d_in[0];
    const float* concepts   = (const float*)d_in[1];
    const float* w_theta    = (const float*)d_in[2];
    const float* w_phi      = (const float*)d_in[3];
    const float* w_g        = (const float*)d_in[4];
    const float* w_o        = (const float*)d_in[5];
    const float* gamma_sa   = (const float*)d_in[6];
    const float* gamma_moca = (const float*)d_in[7];
    float* out = (float*)d_out;

    float *qh, *kh, *vv, *lat, *sa, *enc, *lat2;
    cudaGetSymbolAddress((void**)&qh,  g_qh);
    cudaGetSymbolAddress((void**)&kh,  g_kh);
    cudaGetSymbolAddress((void**)&vv,  g_vv);
    cudaGetSymbolAddress((void**)&lat, g_lat);
    cudaGetSymbolAddress((void**)&sa,  g_sa);
    cudaGetSymbolAddress((void**)&enc, g_enc);
    cudaGetSymbolAddress((void**)&lat2, g_lat2);

    cudaFuncSetAttribute(flash_mma_kernel, cudaFuncAttributeMaxDynamicSharedMemorySize, FT_SMEM);
    cudaFuncSetAttribute(proj_qkv_kernel,  cudaFuncAttributeMaxDynamicSharedMemorySize, QKV_SMEM);
    cudaFuncSetAttribute(proj_nc_kernel,   cudaFuncAttributeMaxDynamicSharedMemorySize, NC_SMEM);
    cudaFuncSetAttribute(conv_mma_kernel,  cudaFuncAttributeMaxDynamicSharedMemorySize, CONV_SMEM);
    cudaFuncSetAttribute(moca_mma_kernel,  cudaFuncAttributeMaxDynamicSharedMemorySize, MOCA_SMEM);

    proj_qkv_kernel<<<dim3(32, 8), 256, QKV_SMEM>>>(fm, w_theta, w_phi, w_g, qh, kh, vv, GAIN_IN);
    flash_mma_kernel<<<dim3(16, 8), 256, FT_SMEM>>>(qh, kh, vv, lat);
    conv_mma_kernel<<<dim3(64, 8), 256, CONV_SMEM>>>(lat, w_o, fm, gamma_sa, sa);
    proj_nc_kernel<<<dim3(32, 8), 256, NC_SMEM>>>(sa, w_theta, enc, GAIN_IN);
    moca_mma_kernel<<<dim3(16, 8), 256, MOCA_SMEM>>>(enc, concepts, lat2);
    conv_mma_kernel<<<dim3(64, 8), 256, CONV_SMEM>>>(lat2, w_o, sa, gamma_moca, out);
}

// round 12
// speedup vs baseline: 2.0893x; 1.1003x over previous
#include <cuda_runtime.h>
#include <cstdint>

constexpr int BB  = 8;
constexpr int CC  = 512;
constexpr int LL  = 64;
constexpr int NHW = 4096;

#define GAIN_IN 0.04419417382415922f
#define GAIN_O  0.125f

// -------- device scratch --------
__device__ float g_qh [BB * NHW * LL];   // theta proj, [b][n][c], tf32-rounded
__device__ float g_kh [BB * NHW * LL];   // phi proj,   [b][n][c], tf32-rounded
__device__ float g_vv [BB * NHW * LL];   // g proj,     [b][n][c], raw fp32
__device__ float g_lat[BB * NHW * LL];
__device__ float g_enc[BB * NHW * LL];
__device__ float g_lat2[BB * NHW * LL];
__device__ float g_M  [LL * LL];         // GAIN_IN * Wtheta @ Wo

extern __shared__ char dyn_smem[];

// ============================================================
// helpers
// ============================================================
__device__ __forceinline__ uint32_t smem_u32(const void* p) {
    uint32_t r;
    asm("{ .reg .u64 t; cvta.to.shared.u64 t, %1; cvt.u32.u64 %0, t; }" : "=r"(r) : "l"(p));
    return r;
}
__device__ __forceinline__ void cp16(uint32_t dst, const void* src) {
    asm volatile("cp.async.cg.shared.global [%0], [%1], 16;" :: "r"(dst), "l"(src));
}
#define CP_COMMIT() asm volatile("cp.async.commit_group;" ::: "memory")
#define CP_WAIT(n)  asm volatile("cp.async.wait_group %0;" :: "n"(n) : "memory")

__device__ __forceinline__ float tf32hi(float v) {
    float h;
    asm("cvt.rna.tf32.f32 %0, %1;" : "=f"(h) : "f"(v));
    return h;
}
__device__ __forceinline__ void mma168(float* d, const uint32_t* a, uint32_t b0, uint32_t b1) {
    asm volatile(
        "mma.sync.aligned.m16n8k8.row.col.f32.tf32.tf32.f32 "
        "{%0,%1,%2,%3}, {%4,%5,%6,%7}, {%8,%9}, {%0,%1,%2,%3};"
        : "+f"(d[0]), "+f"(d[1]), "+f"(d[2]), "+f"(d[3])
        : "r"(a[0]), "r"(a[1]), "r"(a[2]), "r"(a[3]), "r"(b0), "r"(b1));
}

// ============================================================
// flash attention (unchanged from R11)
// ============================================================
constexpr int PAD  = 68;
constexpr int VPAD = 72;
constexpr int QROWS   = 256;
constexpr int QT_F    = QROWS * PAD;
constexpr int OFF_Q   = 0;
constexpr int OFF_K   = QT_F;
constexpr int KSLOT_F = 64 * PAD;
constexpr int OFF_V   = OFF_K + 2 * KSLOT_F;
constexpr int VSLOT_F = 64 * VPAD;
#define FT_SMEM ((OFF_V + 2 * VSLOT_F) * 4)

__device__ __forceinline__ void loadK1(uint32_t dst, const float* Kh,
                                       int b, int m0, int tid) {
    const size_t row0 = (size_t)(b * NHW + m0);
#pragma unroll
    for (int j = 0; j < 4; j++) {
        int idx = j * 256 + tid;
        int r = idx >> 4, c4 = idx & 15;
        cp16(dst + (uint32_t)(r * PAD * 4 + c4 * 16), Kh + (row0 + r) * 64 + c4 * 4);
    }
}
__device__ __forceinline__ void loadV1(uint32_t dst, const float* Vg, int b, int m0, int tid) {
    const size_t row0 = (size_t)(b * NHW + m0);
#pragma unroll
    for (int j = 0; j < 4; j++) {
        int idx = j * 256 + tid;
        int r = idx >> 4, c4 = idx & 15;
        cp16(dst + (uint32_t)(r * VPAD * 4 + c4 * 16), Vg + (row0 + r) * 64 + c4 * 4);
    }
}

__global__ __launch_bounds__(256, 1) void flash_mma_kernel(
    const float* __restrict__ Qg, const float* __restrict__ Kg,
    const float* __restrict__ Vg, float* __restrict__ Og)
{
    float* smem = (float*)dyn_smem;
    const uint32_t sb = smem_u32(dyn_smem);
    const int tid  = threadIdx.x;
    const int warp = tid >> 5;
    const int lane = tid & 31;
    const int g    = lane >> 2;
    const int tig  = lane & 3;
    const int b  = blockIdx.y;
    const int n0 = blockIdx.x * QROWS;
    const int NT = 64;

    {
        const size_t qr0 = (size_t)(b * NHW + n0);
#pragma unroll
        for (int j = 0; j < 16; j++) {
            int idx = j * 256 + tid;
            int r = idx >> 4, c4 = idx & 15;
            cp16(sb + OFF_Q * 4 + (uint32_t)(r * PAD * 4 + c4 * 16),
                 Qg + (qr0 + r) * 64 + c4 * 4);
        }
        loadK1(sb + OFF_K * 4, Kg, b, 0, tid);
        loadV1(sb + OFF_V * 4, Vg, b, 0, tid);
        CP_COMMIT();
    }

    const uint32_t* Qh = (const uint32_t*)(smem + OFF_Q);

    float Oa[2][8][4];
    float lsum[2][2];
#pragma unroll
    for (int m = 0; m < 2; m++) {
        lsum[m][0] = 0.f; lsum[m][1] = 0.f;
#pragma unroll
        for (int c = 0; c < 8; c++)
#pragma unroll
            for (int r = 0; r < 4; r++) Oa[m][c][r] = 0.f;
    }

    const int q0 = warp * 32;

    for (int i = 0; i < NT; i++) {
        __syncthreads();
        if (i + 1 < NT) {
            loadK1(sb + (uint32_t)(OFF_K + ((i + 1) & 1) * KSLOT_F) * 4, Kg, b, (i + 1) * 64, tid);
            loadV1(sb + (uint32_t)(OFF_V + ((i + 1) & 1) * VSLOT_F) * 4, Vg, b, (i + 1) * 64, tid);
        }
        CP_COMMIT();
        CP_WAIT(1);
        __syncthreads();

        const uint32_t* Kh = (const uint32_t*)(smem + OFF_K + (i & 1) * KSLOT_F);
        const uint32_t* Vt = (const uint32_t*)(smem + OFF_V + (i & 1) * VSLOT_F);

        float S[2][8][4];
#pragma unroll
        for (int m = 0; m < 2; m++)
#pragma unroll
            for (int n = 0; n < 8; n++)
#pragma unroll
                for (int r = 0; r < 4; r++) S[m][n][r] = 0.f;

#pragma unroll
        for (int k = 0; k < 8; k++) {
            uint32_t Ah[2][4];
#pragma unroll
            for (int m = 0; m < 2; m++) {
                const int qr = q0 + 16 * m;
                Ah[m][0] = Qh[(qr + g) * PAD + 8 * k + tig];
                Ah[m][1] = Qh[(qr + 8 + g) * PAD + 8 * k + tig];
                Ah[m][2] = Qh[(qr + g) * PAD + 8 * k + tig + 4];
                Ah[m][3] = Qh[(qr + 8 + g) * PAD + 8 * k + tig + 4];
            }
#pragma unroll
            for (int n = 0; n < 8; n++) {
                const int krow = 8 * n + g;
                uint32_t bh0 = Kh[krow * PAD + 8 * k + tig];
                uint32_t bh1 = Kh[krow * PAD + 8 * k + tig + 4];
                mma168(S[0][n], Ah[0], bh0, bh1);
                mma168(S[1][n], Ah[1], bh0, bh1);
            }
        }

#pragma unroll
        for (int m = 0; m < 2; m++) {
            float s0 = 0.f, s1 = 0.f;
#pragma unroll
            for (int n = 0; n < 8; n++) {
                float p0 = __expf(S[m][n][0]);
                float p1 = __expf(S[m][n][1]);
                float p2 = __expf(S[m][n][2]);
                float p3 = __expf(S[m][n][3]);
                S[m][n][0] = p0; S[m][n][1] = p1;
                S[m][n][2] = p2; S[m][n][3] = p3;
                s0 += p0 + p1; s1 += p2 + p3;
            }
            lsum[m][0] += s0; lsum[m][1] += s1;
        }

        const int base = lane & ~3;
        const int srcA = base | (tig >> 1);
        const int srcB = srcA + 2;
        const bool odd = (tig & 1);
#pragma unroll
        for (int n = 0; n < 8; n++) {
            uint32_t Ap[2][4];
#pragma unroll
            for (int m = 0; m < 2; m++) {
                float e0  = __shfl_sync(0xffffffffu, S[m][n][0], srcA);
                float e1  = __shfl_sync(0xffffffffu, S[m][n][1], srcA);
                float e2  = __shfl_sync(0xffffffffu, S[m][n][2], srcA);
                float e3  = __shfl_sync(0xffffffffu, S[m][n][3], srcA);
                float f0  = __shfl_sync(0xffffffffu, S[m][n][0], srcB);
                float f1  = __shfl_sync(0xffffffffu, S[m][n][1], srcB);
                float f2  = __shfl_sync(0xffffffffu, S[m][n][2], srcB);
                float f3  = __shfl_sync(0xffffffffu, S[m][n][3], srcB);
                Ap[m][0] = __float_as_uint(odd ? e1 : e0);
                Ap[m][1] = __float_as_uint(odd ? e3 : e2);
                Ap[m][2] = __float_as_uint(odd ? f1 : f0);
                Ap[m][3] = __float_as_uint(odd ? f3 : f2);
            }
#pragma unroll
            for (int c = 0; c < 8; c++) {
                uint32_t b0 = Vt[(8 * n + tig) * VPAD + 8 * c + g];
                uint32_t b1 = Vt[(8 * n + tig + 4) * VPAD + 8 * c + g];
                mma168(Oa[0][c], Ap[0], b0, b1);
                mma168(Oa[1][c], Ap[1], b0, b1);
            }
        }
    }

#pragma unroll
    for (int m = 0; m < 2; m++)
#pragma unroll
        for (int h = 0; h < 2; h++) {
            lsum[m][h] += __shfl_xor_sync(0xffffffffu, lsum[m][h], 1);
            lsum[m][h] += __shfl_xor_sync(0xffffffffu, lsum[m][h], 2);
            lsum[m][h] = 1.f / lsum[m][h];
        }

#pragma unroll
    for (int m = 0; m < 2; m++) {
        const int r0 = n0 + q0 + 16 * m + g;
#pragma unroll
        for (int c = 0; c < 8; c++) {
            float2 v0 = make_float2(Oa[m][c][0] * lsum[m][0], Oa[m][c][1] * lsum[m][0]);
            float2 v1 = make_float2(Oa[m][c][2] * lsum[m][1], Oa[m][c][3] * lsum[m][1]);
            *(float2*)&Og[((size_t)(b * NHW) + r0)     * 64 + 8 * c + 2 * tig] = v0;
            *(float2*)&Og[((size_t)(b * NHW) + r0 + 8) * 64 + 8 * c + 2 * tig] = v1;
        }
    }
}

// ============================================================
// fused theta+phi+g projection (unchanged from R11)
// ============================================================
constexpr int QK_WCH = 64 * 68;
constexpr int QK_XCH = 64 * 132;
constexpr int QKV_XOFF = 6 * QK_WCH;
#define QKV_SMEM ((6 * QK_WCH + 2 * QK_XCH) * 4)

__device__ __forceinline__ void qkv_load_chunk(
    uint32_t sb, int s, const float* X, const float* Wt, const float* Wp, const float* Wg,
    int b, int n0, int c0, int tid)
{
#pragma unroll
    for (int j = 0; j < 4; j++) {
        int idx = tid + j * 256;
        int o = idx >> 4, c4 = (idx & 15) << 2;
        uint32_t doff = (uint32_t)(o * 68 + c4) * 4;
        const int soff = o * CC + c0 + c4;
        cp16(sb + (uint32_t)((0 + s) * QK_WCH) * 4 + doff, Wt + soff);
        cp16(sb + (uint32_t)((2 + s) * QK_WCH) * 4 + doff, Wp + soff);
        cp16(sb + (uint32_t)((4 + s) * QK_WCH) * 4 + doff, Wg + soff);
    }
    const uint32_t xd = sb + (uint32_t)(QKV_XOFF + s * QK_XCH) * 4;
#pragma unroll
    for (int j = 0; j < 8; j++) {
        int idx = tid + j * 256;
        int cl = idx >> 5, n4 = (idx & 31) << 2;
        cp16(xd + (uint32_t)(cl * 132 + n4) * 4,
             X + ((size_t)(b * CC + c0 + cl)) * NHW + n0 + n4);
    }
}

__global__ __launch_bounds__(256) void proj_qkv_kernel(
    const float* __restrict__ X, const float* __restrict__ Wt,
    const float* __restrict__ Wp, const float* __restrict__ Wg,
    float* __restrict__ oq, float* __restrict__ ok, float* __restrict__ ov, float gain)
{
    float* smem = (float*)dyn_smem;
    const uint32_t sb = smem_u32(dyn_smem);
    const int tid  = threadIdx.x;
    const int warp = tid >> 5;
    const int lane = tid & 31;
    const int g    = lane >> 2;
    const int tig  = lane & 3;
    const int b  = blockIdx.y;
    const int n0 = blockIdx.x * 128;
    const int m0 = 16 * warp;

    qkv_load_chunk(sb, 0, X, Wt, Wp, Wg, b, n0, 0, tid);
    CP_COMMIT();

    float aq[8][4], ak[8][4], av[8][4];
#pragma unroll
    for (int nc = 0; nc < 8; nc++)
#pragma unroll
        for (int r = 0; r < 4; r++) { aq[nc][r] = 0.f; ak[nc][r] = 0.f; av[nc][r] = 0.f; }

    for (int kc = 0; kc < 8; kc++) {
        __syncthreads();
        if (kc + 1 < 8) qkv_load_chunk(sb, (kc + 1) & 1, X, Wt, Wp, Wg, b, n0, (kc + 1) * 64, tid);
        CP_COMMIT();
        if (kc + 1 < 8) { CP_WAIT(1); } else { CP_WAIT(0); }
        __syncthreads();

        const float* Wtc = smem + (0 + (kc & 1)) * QK_WCH;
        const float* Wpc = smem + (2 + (kc & 1)) * QK_WCH;
        const float* Wgc = smem + (4 + (kc & 1)) * QK_WCH;
        const float* Xc  = smem + QKV_XOFF + (kc & 1) * QK_XCH;

#pragma unroll
        for (int kk = 0; kk < 8; kk++) {
            float x0 = Xc[(8 * kk + tig) * 132 + m0 + g];
            float x1 = Xc[(8 * kk + tig) * 132 + m0 + 8 + g];
            float x2 = Xc[(8 * kk + tig + 4) * 132 + m0 + g];
            float x3 = Xc[(8 * kk + tig + 4) * 132 + m0 + 8 + g];
            float h0 = tf32hi(x0), h1 = tf32hi(x1), h2 = tf32hi(x2), h3 = tf32hi(x3);
            uint32_t Ah[4] = {__float_as_uint(h0), __float_as_uint(h1),
                              __float_as_uint(h2), __float_as_uint(h3)};
            uint32_t Al[4] = {__float_as_uint(x0 - h0), __float_as_uint(x1 - h1),
                              __float_as_uint(x2 - h2), __float_as_uint(x3 - h3)};
#pragma unroll
            for (int nc = 0; nc < 8; nc++) {
                const int wrow = (8 * nc + g) * 68 + 8 * kk + tig;
                uint32_t tb0 = __float_as_uint(tf32hi(Wtc[wrow]));
                uint32_t tb1 = __float_as_uint(tf32hi(Wtc[wrow + 4]));
                mma168(aq[nc], Ah, tb0, tb1);
                mma168(aq[nc], Al, tb0, tb1);
                uint32_t pb0 = __float_as_uint(tf32hi(Wpc[wrow]));
                uint32_t pb1 = __float_as_uint(tf32hi(Wpc[wrow + 4]));
                mma168(ak[nc], Ah, pb0, pb1);
                mma168(ak[nc], Al, pb0, pb1);
                uint32_t gb0 = __float_as_uint(tf32hi(Wgc[wrow]));
                uint32_t gb1 = __float_as_uint(tf32hi(Wgc[wrow + 4]));
                mma168(av[nc], Ah, gb0, gb1);
                mma168(av[nc], Al, gb0, gb1);
            }
        }
    }

#pragma unroll
    for (int nc = 0; nc < 8; nc++) {
        const int o = 8 * nc + 2 * tig;
        const size_t r0 = (size_t)(b * NHW + n0 + m0 + g);
        const size_t r1 = r0 + 8;
        *(float2*)&oq[r0 * 64 + o] = make_float2(tf32hi(aq[nc][0] * gain), tf32hi(aq[nc][1] * gain));
        *(float2*)&oq[r1 * 64 + o] = make_float2(tf32hi(aq[nc][2] * gain), tf32hi(aq[nc][3] * gain));
        *(float2*)&ok[r0 * 64 + o] = make_float2(tf32hi(ak[nc][0] * gain), tf32hi(ak[nc][1] * gain));
        *(float2*)&ok[r1 * 64 + o] = make_float2(tf32hi(ak[nc][2] * gain), tf32hi(ak[nc][3] * gain));
        *(float2*)&ov[r0 * 64 + o] = make_float2(av[nc][0] * gain, av[nc][1] * gain);
        *(float2*)&ov[r1 * 64 + o] = make_float2(av[nc][2] * gain, av[nc][3] * gain);
    }
}

// ============================================================
// mmat: M[o][l] = GAIN_IN * sum_c Wtheta[o][c] * Wo[c][l]   (64x64)
// ============================================================
__global__ __launch_bounds__(256) void mmat_kernel(
    const float* __restrict__ Wt, const float* __restrict__ Wo, float* __restrict__ M)
{
    const int gid = blockIdx.x * 256 + threadIdx.x;   // 0..4095
    const int o = gid >> 6, l = gid & 63;
    float acc = 0.f;
    for (int c = 0; c < CC; c++)
        acc += Wt[o * CC + c] * Wo[c * LL + l];
    M[o * LL + l] = GAIN_IN * acc;
}

// ============================================================
// enc_fix: enc[b][n][o] = qh[b][n][o] + gamma_sa*0.125 * sum_l M[o][l]*lat_view[l][n]
// lat_view[l][n] = lat_flat[b*262144 + l*4096 + n]   (the torch reinterpret)
// grid (32, 8), 256 threads, n-tile 128.
// ============================================================
#define ENCFIX_SMEM ((64 * 65 + 64 * 132) * 4)   // 50432

__global__ __launch_bounds__(256) void enc_fix_kernel(
    const float* __restrict__ qh, const float* __restrict__ lat,
    const float* __restrict__ M, const float* __restrict__ gamma_sa,
    float* __restrict__ enc)
{
    float* smem = (float*)dyn_smem;
    float* Ms = smem;             // [o][l] pad 65
    float* Ls = smem + 64 * 65;   // [l][n] pad 132
    const uint32_t sb = smem_u32(dyn_smem);

    const int tid = threadIdx.x;
    const int b  = blockIdx.y;
    const int n0 = blockIdx.x * 128;

    // load M (transposed pad): Ms[o*65+l]
    for (int i = tid; i < 4096; i += 256) {
        int o = i >> 6, l = i & 63;
        Ms[o * 65 + l] = M[i];
    }
    // load lat view rows: Ls[l*132 + nn] = lat[b*262144 + l*4096 + n0+nn]
#pragma unroll
    for (int j = 0; j < 8; j++) {
        int idx = tid + j * 256;             // 0..2047 -> l, n4
        int l = idx >> 5, n4 = (idx & 31) << 2;
        cp16(sb + (uint32_t)(64 * 65 + l * 132 + n4) * 4,
             lat + (size_t)b * (NHW * 64) + l * NHW + n0 + n4);
    }
    CP_COMMIT();
    CP_WAIT(0);
    __syncthreads();

    const float coeff = gamma_sa[0] * GAIN_O;
    const int o = tid & 63;
    const int pg = tid >> 6;     // 0..3

#pragma unroll
    for (int pass = 0; pass < 8; pass++) {
        const int nl = pg * 4 + pass * 16;
        float a0 = 0.f, a1 = 0.f, a2 = 0.f, a3 = 0.f;
#pragma unroll 16
        for (int l = 0; l < 64; l++) {
            float m = Ms[o * 65 + l];
            float4 lv = *(float4*)&Ls[l * 132 + nl];
            a0 += m * lv.x; a1 += m * lv.y; a2 += m * lv.z; a3 += m * lv.w;
        }
        const size_t r = (size_t)(b * NHW + n0 + nl);
        enc[(r + 0) * 64 + o] = qh[(r + 0) * 64 + o] + coeff * a0;
        enc[(r + 1) * 64 + o] = qh[(r + 1) * 64 + o] + coeff * a1;
        enc[(r + 2) * 64 + o] = qh[(r + 2) * 64 + o] + coeff * a2;
        enc[(r + 3) * 64 + o] = qh[(r + 3) * 64 + o] + coeff * a3;
    }
}

// ============================================================
// MoCA via mma.sync (unchanged from R11)
// ============================================================
constexpr int MC68_OFF = 0;
constexpr int MC72_OFF = 256 * 68;
constexpr int MES_OFF  = MC72_OFF + 256 * 72;
#define MOCA_SMEM ((MES_OFF + 256 * 68) * 4)

__global__ __launch_bounds__(256, 1) void moca_mma_kernel(
    const float* __restrict__ E, const float* __restrict__ Cpt, float* __restrict__ O)
{
    float* smem = (float*)dyn_smem;
    const uint32_t sb = smem_u32(dyn_smem);
    const int tid  = threadIdx.x;
    const int warp = tid >> 5;
    const int lane = tid & 31;
    const int g    = lane >> 2;
    const int tig  = lane & 3;
    const int b  = blockIdx.y;
    const int n0 = blockIdx.x * 256;

    {
        const size_t er0 = (size_t)(b * NHW + n0);
#pragma unroll
        for (int j = 0; j < 16; j++) {
            int idx = j * 256 + tid;
            int r = idx >> 4, c4 = idx & 15;
            const float* csrc = Cpt + r * 64 + c4 * 4;
            cp16(sb + (uint32_t)(MC68_OFF + r * 68 + c4 * 4) * 4, csrc);
            cp16(sb + (uint32_t)(MC72_OFF + r * 72 + c4 * 4) * 4, csrc);
            cp16(sb + (uint32_t)(MES_OFF + r * 68 + c4 * 4) * 4,
                 E + (er0 + r) * 64 + c4 * 4);
        }
        CP_COMMIT();
        CP_WAIT(0);
        __syncthreads();
    }

    const uint32_t* Cs68 = (const uint32_t*)(smem + MC68_OFF);
    const uint32_t* Cs72 = (const uint32_t*)(smem + MC72_OFF);
    const uint32_t* Es   = (const uint32_t*)(smem + MES_OFF);

    float Oa[2][8][4];
    float lsum[2][2];
#pragma unroll
    for (int m = 0; m < 2; m++) {
        lsum[m][0] = 0.f; lsum[m][1] = 0.f;
#pragma unroll
        for (int c = 0; c < 8; c++)
#pragma unroll
            for (int r = 0; r < 4; r++) Oa[m][c][r] = 0.f;
    }

    const int q0 = warp * 32;

#pragma unroll
    for (int pt = 0; pt < 4; pt++) {
        const int p0 = pt * 64;

        float S[2][8][4];
#pragma unroll
        for (int m = 0; m < 2; m++)
#pragma unroll
            for (int n = 0; n < 8; n++)
#pragma unroll
                for (int r = 0; r < 4; r++) S[m][n][r] = 0.f;

#pragma unroll
        for (int k = 0; k < 8; k++) {
            uint32_t Ah[2][4];
#pragma unroll
            for (int m = 0; m < 2; m++) {
                const int qr = q0 + 16 * m;
                Ah[m][0] = Es[(qr + g) * PAD + 8 * k + tig];
                Ah[m][1] = Es[(qr + 8 + g) * PAD + 8 * k + tig];
                Ah[m][2] = Es[(qr + g) * PAD + 8 * k + tig + 4];
                Ah[m][3] = Es[(qr + 8 + g) * PAD + 8 * k + tig + 4];
            }
#pragma unroll
            for (int n = 0; n < 8; n++) {
                const int prow = p0 + 8 * n + g;
                uint32_t bh0 = Cs68[prow * PAD + 8 * k + tig];
                uint32_t bh1 = Cs68[prow * PAD + 8 * k + tig + 4];
                mma168(S[0][n], Ah[0], bh0, bh1);
                mma168(S[1][n], Ah[1], bh0, bh1);
            }
        }

#pragma unroll
        for (int m = 0; m < 2; m++) {
            float s0 = 0.f, s1 = 0.f;
#pragma unroll
            for (int n = 0; n < 8; n++) {
                float p0f = __expf(S[m][n][0]);
                float p1f = __expf(S[m][n][1]);
                float p2f = __expf(S[m][n][2]);
                float p3f = __expf(S[m][n][3]);
                S[m][n][0] = p0f; S[m][n][1] = p1f;
                S[m][n][2] = p2f; S[m][n][3] = p3f;
                s0 += p0f + p1f; s1 += p2f + p3f;
            }
            lsum[m][0] += s0; lsum[m][1] += s1;
        }

        const int base = lane & ~3;
        const int srcA = base | (tig >> 1);
        const int srcB = srcA + 2;
        const bool odd = (tig & 1);
#pragma unroll
        for (int n = 0; n < 8; n++) {
            uint32_t Ap[2][4];
#pragma unroll
            for (int m = 0; m < 2; m++) {
                float e0  = __shfl_sync(0xffffffffu, S[m][n][0], srcA);
                float e1  = __shfl_sync(0xffffffffu, S[m][n][1], srcA);
                float e2  = __shfl_sync(0xffffffffu, S[m][n][2], srcA);
                float e3  = __shfl_sync(0xffffffffu, S[m][n][3], srcA);
                float f0  = __shfl_sync(0xffffffffu, S[m][n][0], srcB);
                float f1  = __shfl_sync(0xffffffffu, S[m][n][1], srcB);
                float f2  = __shfl_sync(0xffffffffu, S[m][n][2], srcB);
                float f3  = __shfl_sync(0xffffffffu, S[m][n][3], srcB);
                Ap[m][0] = __float_as_uint(odd ? e1 : e0);
                Ap[m][1] = __float_as_uint(odd ? e3 : e2);
                Ap[m][2] = __float_as_uint(odd ? f1 : f0);
                Ap[m][3] = __float_as_uint(odd ? f3 : f2);
            }
#pragma unroll
            for (int c = 0; c < 8; c++) {
                uint32_t b0 = Cs72[(p0 + 8 * n + tig) * VPAD + 8 * c + g];
                uint32_t b1 = Cs72[(p0 + 8 * n + tig + 4) * VPAD + 8 * c + g];
                mma168(Oa[0][c], Ap[0], b0, b1);
                mma168(Oa[1][c], Ap[1], b0, b1);
            }
        }
    }

#pragma unroll
    for (int m = 0; m < 2; m++)
#pragma unroll
        for (int h = 0; h < 2; h++) {
            lsum[m][h] += __shfl_xor_sync(0xffffffffu, lsum[m][h], 1);
            lsum[m][h] += __shfl_xor_sync(0xffffffffu, lsum[m][h], 2);
            lsum[m][h] = 1.f / lsum[m][h];
        }

#pragma unroll
    for (int m = 0; m < 2; m++) {
        const int r0 = n0 + q0 + 16 * m + g;
#pragma unroll
        for (int c = 0; c < 8; c++) {
            float2 v0 = make_float2(Oa[m][c][0] * lsum[m][0], Oa[m][c][1] * lsum[m][0]);
            float2 v1 = make_float2(Oa[m][c][2] * lsum[m][1], Oa[m][c][3] * lsum[m][1]);
            *(float2*)&O[((size_t)(b * NHW) + r0)     * 64 + 8 * c + 2 * tig] = v0;
            *(float2*)&O[((size_t)(b * NHW) + r0 + 8) * 64 + 8 * c + 2 * tig] = v1;
        }
    }
}

// ============================================================
// fused output conv: out = 0.125*Wo@(gsa*lat + gmoca*lat2) + fm
// ============================================================
#define CONV_SMEM ((512 * 68 + 2 * 64 * 68) * 4)   // 174080
__global__ __launch_bounds__(256, 1) void conv_fused_kernel(
    const float* __restrict__ lat, const float* __restrict__ lat2,
    const float* __restrict__ Wo, const float* __restrict__ fm,
    const float* __restrict__ gsa, const float* __restrict__ gmoca,
    float* __restrict__ out)
{
    float* smem = (float*)dyn_smem;
    const uint32_t sb = smem_u32(dyn_smem);

    const int tid  = threadIdx.x;
    const int warp = tid >> 5;
    const int lane = tid & 31;
    const int g    = lane >> 2;
    const int tig  = lane & 3;
    const int b  = blockIdx.y;
    const int n0 = blockIdx.x * 64;

#pragma unroll
    for (int j = 0; j < 32; j++) {
        int idx = tid + j * 256;
        int oc = idx >> 4, l4 = (idx & 15) << 2;
        cp16(sb + (uint32_t)(oc * 68 + l4) * 4, Wo + oc * LL + l4);
    }
#pragma unroll
    for (int j = 0; j < 4; j++) {
        int idx = tid + j * 256;
        int cl = idx >> 4, n4 = (idx & 15) << 2;
        const size_t src = (size_t)b * (NHW * 64) + cl * NHW + n0 + n4;
        cp16(sb + (uint32_t)((512 + cl) * 68 + n4) * 4, lat + src);
        cp16(sb + (uint32_t)((576 + cl) * 68 + n4) * 4, lat2 + src);
    }
    CP_COMMIT();
    CP_WAIT(0);
    __syncthreads();

    float acc[4][8][4];
#pragma unroll
    for (int m = 0; m < 4; m++)
#pragma unroll
        for (int nc = 0; nc < 8; nc++)
#pragma unroll
            for (int r = 0; r < 4; r++) acc[m][nc][r] = 0.f;

    const uint32_t* Wu = (const uint32_t*)smem;
    const float* L1 = smem + 512 * 68;
    const float* L2 = smem + 576 * 68;
    const float cs = gsa[0], cm = gmoca[0];

#pragma unroll
    for (int kk = 0; kk < 8; kk++) {
        uint32_t A[4][4];
#pragma unroll
        for (int m = 0; m < 4; m++) {
            const int oc = 64 * warp + 16 * m;
            A[m][0] = Wu[(oc + g) * 68 + 8 * kk + tig];
            A[m][1] = Wu[(oc + 8 + g) * 68 + 8 * kk + tig];
            A[m][2] = Wu[(oc + g) * 68 + 8 * kk + tig + 4];
            A[m][3] = Wu[(oc + 8 + g) * 68 + 8 * kk + tig + 4];
        }
#pragma unroll
        for (int nc = 0; nc < 8; nc++) {
            const int i0 = (8 * kk + tig) * 68 + 8 * nc + g;
            const int i1 = (8 * kk + tig + 4) * 68 + 8 * nc + g;
            uint32_t b0 = __float_as_uint(cs * L1[i0] + cm * L2[i0]);
            uint32_t b1 = __float_as_uint(cs * L1[i1] + cm * L2[i1]);
#pragma unroll
            for (int m = 0; m < 4; m++) mma168(acc[m][nc], A[m], b0, b1);
        }
    }

#pragma unroll
    for (int m = 0; m < 4; m++)
#pragma unroll
        for (int nc = 0; nc < 8; nc++) {
            const int oc = 64 * warp + 16 * m + g;
            const int n  = n0 + 8 * nc + 2 * tig;
            const size_t base0 = ((size_t)(b * CC + oc)) * NHW + n;
            const size_t base1 = base0 + (size_t)8 * NHW;
            float2 a0 = *(const float2*)&fm[base0];
            float2 a1 = *(const float2*)&fm[base1];
            *(float2*)&out[base0] = make_float2(GAIN_O * acc[m][nc][0] + a0.x,
                                                GAIN_O * acc[m][nc][1] + a0.y);
            *(float2*)&out[base1] = make_float2(GAIN_O * acc[m][nc][2] + a1.x,
                                                GAIN_O * acc[m][nc][3] + a1.y);
        }
}

// ============================================================
extern "C" void kernel_launch(void* const* d_in, const int* in_sizes, int n_in,
                              void* d_out, int out_size)
{
    (void)in_sizes; (void)n_in; (void)out_size;
    const float* fm         = (const float*)d_in[0];
    const float* concepts   = (const float*)d_in[1];
    const float* w_theta    = (const float*)d_in[2];
    const float* w_phi      = (const float*)d_in[3];
    const float* w_g        = (const float*)d_in[4];
    const float* w_o        = (const float*)d_in[5];
    const float* gamma_sa   = (const float*)d_in[6];
    const float* gamma_moca = (const float*)d_in[7];
    float* out = (float*)d_out;

    float *qh, *kh, *vv, *lat, *enc, *lat2, *Mb;
    cudaGetSymbolAddress((void**)&qh,  g_qh);
    cudaGetSymbolAddress((void**)&kh,  g_kh);
    cudaGetSymbolAddress((void**)&vv,  g_vv);
    cudaGetSymbolAddress((void**)&lat, g_lat);
    cudaGetSymbolAddress((void**)&enc, g_enc);
    cudaGetSymbolAddress((void**)&lat2, g_lat2);
    cudaGetSymbolAddress((void**)&Mb,  g_M);

    cudaFuncSetAttribute(flash_mma_kernel, cudaFuncAttributeMaxDynamicSharedMemorySize, FT_SMEM);
    cudaFuncSetAttribute(proj_qkv_kernel,  cudaFuncAttributeMaxDynamicSharedMemorySize, QKV_SMEM);
    cudaFuncSetAttribute(enc_fix_kernel,   cudaFuncAttributeMaxDynamicSharedMemorySize, ENCFIX_SMEM);
    cudaFuncSetAttribute(conv_fused_kernel, cudaFuncAttributeMaxDynamicSharedMemorySize, CONV_SMEM);
    cudaFuncSetAttribute(moca_mma_kernel,  cudaFuncAttributeMaxDynamicSharedMemorySize, MOCA_SMEM);

    mmat_kernel<<<16, 256>>>(w_theta, w_o, Mb);
    proj_qkv_kernel<<<dim3(32, 8), 256, QKV_SMEM>>>(fm, w_theta, w_phi, w_g, qh, kh, vv, GAIN_IN);
    flash_mma_kernel<<<dim3(16, 8), 256, FT_SMEM>>>(qh, kh, vv, lat);
    enc_fix_kernel<<<dim3(32, 8), 256, ENCFIX_SMEM>>>(qh, lat, Mb, gamma_sa, enc);
    moca_mma_kernel<<<dim3(16, 8), 256, MOCA_SMEM>>>(enc, concepts, lat2);
    conv_fused_kernel<<<dim3(64, 8), 256, CONV_SMEM>>>(lat, lat2, w_o, fm, gamma_sa, gamma_moca, out);
}

// round 13
// speedup vs baseline: 2.0984x; 1.0044x over previous
#include <cuda_runtime.h>
#include <cstdint>

constexpr int BB  = 8;
constexpr int CC  = 512;
constexpr int LL  = 64;
constexpr int NHW = 4096;

#define GAIN_IN 0.04419417382415922f
#define GAIN_O  0.125f

// -------- device scratch --------
__device__ float g_qh [BB * NHW * LL];
__device__ float g_kh [BB * NHW * LL];
__device__ float g_vv [BB * NHW * LL];
__device__ float g_lat[BB * NHW * LL];
__device__ float g_enc[BB * NHW * LL];
__device__ float g_lat2[BB * NHW * LL];
__device__ float g_M  [LL * LL];

extern __shared__ char dyn_smem[];

// ============================================================
// helpers
// ============================================================
__device__ __forceinline__ uint32_t smem_u32(const void* p) {
    uint32_t r;
    asm("{ .reg .u64 t; cvta.to.shared.u64 t, %1; cvt.u32.u64 %0, t; }" : "=r"(r) : "l"(p));
    return r;
}
__device__ __forceinline__ void cp16(uint32_t dst, const void* src) {
    asm volatile("cp.async.cg.shared.global [%0], [%1], 16;" :: "r"(dst), "l"(src));
}
#define CP_COMMIT() asm volatile("cp.async.commit_group;" ::: "memory")
#define CP_WAIT(n)  asm volatile("cp.async.wait_group %0;" :: "n"(n) : "memory")

__device__ __forceinline__ float tf32hi(float v) {
    float h;
    asm("cvt.rna.tf32.f32 %0, %1;" : "=f"(h) : "f"(v));
    return h;
}
__device__ __forceinline__ void mma168(float* d, const uint32_t* a, uint32_t b0, uint32_t b1) {
    asm volatile(
        "mma.sync.aligned.m16n8k8.row.col.f32.tf32.tf32.f32 "
        "{%0,%1,%2,%3}, {%4,%5,%6,%7}, {%8,%9}, {%0,%1,%2,%3};"
        : "+f"(d[0]), "+f"(d[1]), "+f"(d[2]), "+f"(d[3])
        : "r"(a[0]), "r"(a[1]), "r"(a[2]), "r"(a[3]), "r"(b0), "r"(b1));
}

// ============================================================
// flash attention v6: triple-buffered K/V, ONE sync per tile.
// ============================================================
constexpr int PAD  = 68;
constexpr int VPAD = 72;
constexpr int QROWS   = 256;
constexpr int QT_F    = QROWS * PAD;
constexpr int OFF_Q   = 0;
constexpr int OFF_K   = QT_F;                  // 17408
constexpr int KSLOT_F = 64 * PAD;              // 4352
constexpr int OFF_V   = OFF_K + 3 * KSLOT_F;   // 30464
constexpr int VSLOT_F = 64 * VPAD;             // 4608
#define FT_SMEM ((OFF_V + 3 * VSLOT_F) * 4)    // 177152 bytes

__device__ __forceinline__ void loadK1(uint32_t dst, const float* Kh,
                                       int b, int m0, int tid) {
    const size_t row0 = (size_t)(b * NHW + m0);
#pragma unroll
    for (int j = 0; j < 4; j++) {
        int idx = j * 256 + tid;
        int r = idx >> 4, c4 = idx & 15;
        cp16(dst + (uint32_t)(r * PAD * 4 + c4 * 16), Kh + (row0 + r) * 64 + c4 * 4);
    }
}
__device__ __forceinline__ void loadV1(uint32_t dst, const float* Vg, int b, int m0, int tid) {
    const size_t row0 = (size_t)(b * NHW + m0);
#pragma unroll
    for (int j = 0; j < 4; j++) {
        int idx = j * 256 + tid;
        int r = idx >> 4, c4 = idx & 15;
        cp16(dst + (uint32_t)(r * VPAD * 4 + c4 * 16), Vg + (row0 + r) * 64 + c4 * 4);
    }
}

__global__ __launch_bounds__(256, 1) void flash_mma_kernel(
    const float* __restrict__ Qg, const float* __restrict__ Kg,
    const float* __restrict__ Vg, float* __restrict__ Og)
{
    float* smem = (float*)dyn_smem;
    const uint32_t sb = smem_u32(dyn_smem);
    const int tid  = threadIdx.x;
    const int warp = tid >> 5;
    const int lane = tid & 31;
    const int g    = lane >> 2;
    const int tig  = lane & 3;
    const int b  = blockIdx.y;
    const int n0 = blockIdx.x * QROWS;
    const int NT = 64;

    {
        const size_t qr0 = (size_t)(b * NHW + n0);
#pragma unroll
        for (int j = 0; j < 16; j++) {
            int idx = j * 256 + tid;
            int r = idx >> 4, c4 = idx & 15;
            cp16(sb + OFF_Q * 4 + (uint32_t)(r * PAD * 4 + c4 * 16),
                 Qg + (qr0 + r) * 64 + c4 * 4);
        }
        loadK1(sb + OFF_K * 4, Kg, b, 0, tid);
        loadV1(sb + OFF_V * 4, Vg, b, 0, tid);
        CP_COMMIT();                          // group 0
    }

    const uint32_t* Qh = (const uint32_t*)(smem + OFF_Q);

    float Oa[2][8][4];
    float lsum[2][2];
#pragma unroll
    for (int m = 0; m < 2; m++) {
        lsum[m][0] = 0.f; lsum[m][1] = 0.f;
#pragma unroll
        for (int c = 0; c < 8; c++)
#pragma unroll
            for (int r = 0; r < 4; r++) Oa[m][c][r] = 0.f;
    }

    const int q0 = warp * 32;

    for (int i = 0; i < NT; i++) {
        if (i + 1 < NT) {
            const int s = (i + 1) % 3;
            loadK1(sb + (uint32_t)(OFF_K + s * KSLOT_F) * 4, Kg, b, (i + 1) * 64, tid);
            loadV1(sb + (uint32_t)(OFF_V + s * VSLOT_F) * 4, Vg, b, (i + 1) * 64, tid);
        }
        CP_COMMIT();
        CP_WAIT(1);                            // group i complete
        __syncthreads();

        const int sc = i % 3;
        const uint32_t* Kh = (const uint32_t*)(smem + OFF_K + sc * KSLOT_F);
        const uint32_t* Vt = (const uint32_t*)(smem + OFF_V + sc * VSLOT_F);

        // ---- S = Q K^T, 1x tf32 ----
        float S[2][8][4];
#pragma unroll
        for (int m = 0; m < 2; m++)
#pragma unroll
            for (int n = 0; n < 8; n++)
#pragma unroll
                for (int r = 0; r < 4; r++) S[m][n][r] = 0.f;

#pragma unroll
        for (int k = 0; k < 8; k++) {
            uint32_t Ah[2][4];
#pragma unroll
            for (int m = 0; m < 2; m++) {
                const int qr = q0 + 16 * m;
                Ah[m][0] = Qh[(qr + g) * PAD + 8 * k + tig];
                Ah[m][1] = Qh[(qr + 8 + g) * PAD + 8 * k + tig];
                Ah[m][2] = Qh[(qr + g) * PAD + 8 * k + tig + 4];
                Ah[m][3] = Qh[(qr + 8 + g) * PAD + 8 * k + tig + 4];
            }
#pragma unroll
            for (int n = 0; n < 8; n++) {
                const int krow = 8 * n + g;
                uint32_t bh0 = Kh[krow * PAD + 8 * k + tig];
                uint32_t bh1 = Kh[krow * PAD + 8 * k + tig + 4];
                mma168(S[0][n], Ah[0], bh0, bh1);
                mma168(S[1][n], Ah[1], bh0, bh1);
            }
        }

        // ---- P = exp(S) ----
#pragma unroll
        for (int m = 0; m < 2; m++) {
            float s0 = 0.f, s1 = 0.f;
#pragma unroll
            for (int n = 0; n < 8; n++) {
                float p0 = __expf(S[m][n][0]);
                float p1 = __expf(S[m][n][1]);
                float p2 = __expf(S[m][n][2]);
                float p3 = __expf(S[m][n][3]);
                S[m][n][0] = p0; S[m][n][1] = p1;
                S[m][n][2] = p2; S[m][n][3] = p3;
                s0 += p0 + p1; s1 += p2 + p3;
            }
            lsum[m][0] += s0; lsum[m][1] += s1;
        }

        // ---- O += P V ----
        const int base = lane & ~3;
        const int srcA = base | (tig >> 1);
        const int srcB = srcA + 2;
        const bool odd = (tig & 1);
#pragma unroll
        for (int n = 0; n < 8; n++) {
            uint32_t Ap[2][4];
#pragma unroll
            for (int m = 0; m < 2; m++) {
                float e0  = __shfl_sync(0xffffffffu, S[m][n][0], srcA);
                float e1  = __shfl_sync(0xffffffffu, S[m][n][1], srcA);
                float e2  = __shfl_sync(0xffffffffu, S[m][n][2], srcA);
                float e3  = __shfl_sync(0xffffffffu, S[m][n][3], srcA);
                float f0  = __shfl_sync(0xffffffffu, S[m][n][0], srcB);
                float f1  = __shfl_sync(0xffffffffu, S[m][n][1], srcB);
                float f2  = __shfl_sync(0xffffffffu, S[m][n][2], srcB);
                float f3  = __shfl_sync(0xffffffffu, S[m][n][3], srcB);
                Ap[m][0] = __float_as_uint(odd ? e1 : e0);
                Ap[m][1] = __float_as_uint(odd ? e3 : e2);
                Ap[m][2] = __float_as_uint(odd ? f1 : f0);
                Ap[m][3] = __float_as_uint(odd ? f3 : f2);
            }
#pragma unroll
            for (int c = 0; c < 8; c++) {
                uint32_t b0 = Vt[(8 * n + tig) * VPAD + 8 * c + g];
                uint32_t b1 = Vt[(8 * n + tig + 4) * VPAD + 8 * c + g];
                mma168(Oa[0][c], Ap[0], b0, b1);
                mma168(Oa[1][c], Ap[1], b0, b1);
            }
        }
    }

    // ---- epilogue ----
#pragma unroll
    for (int m = 0; m < 2; m++)
#pragma unroll
        for (int h = 0; h < 2; h++) {
            lsum[m][h] += __shfl_xor_sync(0xffffffffu, lsum[m][h], 1);
            lsum[m][h] += __shfl_xor_sync(0xffffffffu, lsum[m][h], 2);
            lsum[m][h] = 1.f / lsum[m][h];
        }

#pragma unroll
    for (int m = 0; m < 2; m++) {
        const int r0 = n0 + q0 + 16 * m + g;
#pragma unroll
        for (int c = 0; c < 8; c++) {
            float2 v0 = make_float2(Oa[m][c][0] * lsum[m][0], Oa[m][c][1] * lsum[m][0]);
            float2 v1 = make_float2(Oa[m][c][2] * lsum[m][1], Oa[m][c][3] * lsum[m][1]);
            *(float2*)&Og[((size_t)(b * NHW) + r0)     * 64 + 8 * c + 2 * tig] = v0;
            *(float2*)&Og[((size_t)(b * NHW) + r0 + 8) * 64 + 8 * c + 2 * tig] = v1;
        }
    }
}

// ============================================================
// fused theta+phi+g projection, W chunks PRE-ROUNDED in smem.
// ============================================================
constexpr int QK_WCH = 64 * 68;
constexpr int QK_XCH = 64 * 132;
constexpr int QKV_XOFF = 6 * QK_WCH;
#define QKV_SMEM ((6 * QK_WCH + 2 * QK_XCH) * 4)

__device__ __forceinline__ void qkv_load_chunk(
    uint32_t sb, int s, const float* X, const float* Wt, const float* Wp, const float* Wg,
    int b, int n0, int c0, int tid)
{
#pragma unroll
    for (int j = 0; j < 4; j++) {
        int idx = tid + j * 256;
        int o = idx >> 4, c4 = (idx & 15) << 2;
        uint32_t doff = (uint32_t)(o * 68 + c4) * 4;
        const int soff = o * CC + c0 + c4;
        cp16(sb + (uint32_t)((0 + s) * QK_WCH) * 4 + doff, Wt + soff);
        cp16(sb + (uint32_t)((2 + s) * QK_WCH) * 4 + doff, Wp + soff);
        cp16(sb + (uint32_t)((4 + s) * QK_WCH) * 4 + doff, Wg + soff);
    }
    const uint32_t xd = sb + (uint32_t)(QKV_XOFF + s * QK_XCH) * 4;
#pragma unroll
    for (int j = 0; j < 8; j++) {
        int idx = tid + j * 256;
        int cl = idx >> 5, n4 = (idx & 31) << 2;
        cp16(xd + (uint32_t)(cl * 132 + n4) * 4,
             X + ((size_t)(b * CC + c0 + cl)) * NHW + n0 + n4);
    }
}

__global__ __launch_bounds__(256) void proj_qkv_kernel(
    const float* __restrict__ X, const float* __restrict__ Wt,
    const float* __restrict__ Wp, const float* __restrict__ Wg,
    float* __restrict__ oq, float* __restrict__ ok, float* __restrict__ ov, float gain)
{
    float* smem = (float*)dyn_smem;
    const uint32_t sb = smem_u32(dyn_smem);
    const int tid  = threadIdx.x;
    const int warp = tid >> 5;
    const int lane = tid & 31;
    const int g    = lane >> 2;
    const int tig  = lane & 3;
    const int b  = blockIdx.y;
    const int n0 = blockIdx.x * 128;
    const int m0 = 16 * warp;

    qkv_load_chunk(sb, 0, X, Wt, Wp, Wg, b, n0, 0, tid);
    CP_COMMIT();

    float aq[8][4], ak[8][4], av[8][4];
#pragma unroll
    for (int nc = 0; nc < 8; nc++)
#pragma unroll
        for (int r = 0; r < 4; r++) { aq[nc][r] = 0.f; ak[nc][r] = 0.f; av[nc][r] = 0.f; }

    for (int kc = 0; kc < 8; kc++) {
        __syncthreads();
        if (kc + 1 < 8) qkv_load_chunk(sb, (kc + 1) & 1, X, Wt, Wp, Wg, b, n0, (kc + 1) * 64, tid);
        CP_COMMIT();
        if (kc + 1 < 8) { CP_WAIT(1); } else { CP_WAIT(0); }
        __syncthreads();

        float* Wtc = smem + (0 + (kc & 1)) * QK_WCH;
        float* Wpc = smem + (2 + (kc & 1)) * QK_WCH;
        float* Wgc = smem + (4 + (kc & 1)) * QK_WCH;
        const float* Xc = smem + QKV_XOFF + (kc & 1) * QK_XCH;

        // pre-round W slot in place (once per chunk, not per fragment)
        for (int j = tid; j < QK_WCH; j += 256) {
            Wtc[j] = tf32hi(Wtc[j]);
            Wpc[j] = tf32hi(Wpc[j]);
            Wgc[j] = tf32hi(Wgc[j]);
        }
        __syncthreads();

        const uint32_t* Wtu = (const uint32_t*)Wtc;
        const uint32_t* Wpu = (const uint32_t*)Wpc;
        const uint32_t* Wgu = (const uint32_t*)Wgc;

#pragma unroll
        for (int kk = 0; kk < 8; kk++) {
            float x0 = Xc[(8 * kk + tig) * 132 + m0 + g];
            float x1 = Xc[(8 * kk + tig) * 132 + m0 + 8 + g];
            float x2 = Xc[(8 * kk + tig + 4) * 132 + m0 + g];
            float x3 = Xc[(8 * kk + tig + 4) * 132 + m0 + 8 + g];
            float h0 = tf32hi(x0), h1 = tf32hi(x1), h2 = tf32hi(x2), h3 = tf32hi(x3);
            uint32_t Ah[4] = {__float_as_uint(h0), __float_as_uint(h1),
                              __float_as_uint(h2), __float_as_uint(h3)};
            uint32_t Al[4] = {__float_as_uint(x0 - h0), __float_as_uint(x1 - h1),
                              __float_as_uint(x2 - h2), __float_as_uint(x3 - h3)};
#pragma unroll
            for (int nc = 0; nc < 8; nc++) {
                const int wrow = (8 * nc + g) * 68 + 8 * kk + tig;
                uint32_t tb0 = Wtu[wrow], tb1 = Wtu[wrow + 4];
                mma168(aq[nc], Ah, tb0, tb1);
                mma168(aq[nc], Al, tb0, tb1);
                uint32_t pb0 = Wpu[wrow], pb1 = Wpu[wrow + 4];
                mma168(ak[nc], Ah, pb0, pb1);
                mma168(ak[nc], Al, pb0, pb1);
                uint32_t gb0 = Wgu[wrow], gb1 = Wgu[wrow + 4];
                mma168(av[nc], Ah, gb0, gb1);
                mma168(av[nc], Al, gb0, gb1);
            }
        }
    }

#pragma unroll
    for (int nc = 0; nc < 8; nc++) {
        const int o = 8 * nc + 2 * tig;
        const size_t r0 = (size_t)(b * NHW + n0 + m0 + g);
        const size_t r1 = r0 + 8;
        *(float2*)&oq[r0 * 64 + o] = make_float2(tf32hi(aq[nc][0] * gain), tf32hi(aq[nc][1] * gain));
        *(float2*)&oq[r1 * 64 + o] = make_float2(tf32hi(aq[nc][2] * gain), tf32hi(aq[nc][3] * gain));
        *(float2*)&ok[r0 * 64 + o] = make_float2(tf32hi(ak[nc][0] * gain), tf32hi(ak[nc][1] * gain));
        *(float2*)&ok[r1 * 64 + o] = make_float2(tf32hi(ak[nc][2] * gain), tf32hi(ak[nc][3] * gain));
        *(float2*)&ov[r0 * 64 + o] = make_float2(av[nc][0] * gain, av[nc][1] * gain);
        *(float2*)&ov[r1 * 64 + o] = make_float2(av[nc][2] * gain, av[nc][3] * gain);
    }
}

// ============================================================
// mmat: M[o][l] = GAIN_IN * Wtheta @ Wo   (64x64)
// ============================================================
__global__ __launch_bounds__(256) void mmat_kernel(
    const float* __restrict__ Wt, const float* __restrict__ Wo, float* __restrict__ M)
{
    const int gid = blockIdx.x * 256 + threadIdx.x;
    const int o = gid >> 6, l = gid & 63;
    float acc = 0.f;
    for (int c = 0; c < CC; c++)
        acc += Wt[o * CC + c] * Wo[c * LL + l];
    M[o * LL + l] = GAIN_IN * acc;
}

// ============================================================
// enc via mma: enc[b][n][o] = qh[b][n][o] + coeff * sum_l M[o][l]*latview[l][n]
// A = M (64x64), B = lat view tile [64 l][256 n]. grid (16,8), 256 thr.
// ============================================================
constexpr int ELPAD = 260;
#define ENC_SMEM ((64 * 68 + 64 * ELPAD) * 4)   // 83968

__global__ __launch_bounds__(256, 1) void enc_mma_kernel(
    const float* __restrict__ qh, const float* __restrict__ lat,
    const float* __restrict__ M, const float* __restrict__ gamma_sa,
    float* __restrict__ enc)
{
    float* smem = (float*)dyn_smem;
    const uint32_t sb = smem_u32(dyn_smem);
    float* Ls = smem + 64 * 68;

    const int tid  = threadIdx.x;
    const int warp = tid >> 5;
    const int lane = tid & 31;
    const int g    = lane >> 2;
    const int tig  = lane & 3;
    const int b  = blockIdx.y;
    const int n0 = blockIdx.x * 256;
    const int nb = warp * 32;      // warp's n sub-tile

    // load M [64][64] -> pad 68
#pragma unroll
    for (int j = 0; j < 4; j++) {
        int idx = tid + j * 256;
        int o = idx >> 4, c4 = (idx & 15) << 2;
        cp16(sb + (uint32_t)(o * 68 + c4) * 4, M + o * 64 + c4);
    }
    // load lat view tile [64 l][256 n] -> pad 260
#pragma unroll
    for (int j = 0; j < 16; j++) {
        int idx = tid + j * 256;
        int l = idx >> 6, n4 = (idx & 63) << 2;
        cp16(sb + (uint32_t)(64 * 68 + l * ELPAD + n4) * 4,
             lat + (size_t)b * (NHW * 64) + l * NHW + n0 + n4);
    }
    CP_COMMIT();
    CP_WAIT(0);
    __syncthreads();

    float acc[4][4][4];
#pragma unroll
    for (int m = 0; m < 4; m++)
#pragma unroll
        for (int nc = 0; nc < 4; nc++)
#pragma unroll
            for (int r = 0; r < 4; r++) acc[m][nc][r] = 0.f;

    const uint32_t* Mu = (const uint32_t*)smem;
    const uint32_t* Lu = (const uint32_t*)Ls;

#pragma unroll
    for (int kk = 0; kk < 8; kk++) {
        uint32_t A[4][4];
#pragma unroll
        for (int m = 0; m < 4; m++) {
            const int oc = 16 * m;
            A[m][0] = Mu[(oc + g) * 68 + 8 * kk + tig];
            A[m][1] = Mu[(oc + 8 + g) * 68 + 8 * kk + tig];
            A[m][2] = Mu[(oc + g) * 68 + 8 * kk + tig + 4];
            A[m][3] = Mu[(oc + 8 + g) * 68 + 8 * kk + tig + 4];
        }
#pragma unroll
        for (int nc = 0; nc < 4; nc++) {
            const int col = nb + 8 * nc + g;
            uint32_t b0 = Lu[(8 * kk + tig) * ELPAD + col];
            uint32_t b1 = Lu[(8 * kk + tig + 4) * ELPAD + col];
#pragma unroll
            for (int m = 0; m < 4; m++) mma168(acc[m][nc], A[m], b0, b1);
        }
    }

    const float coeff = gamma_sa[0] * GAIN_O;
#pragma unroll
    for (int m = 0; m < 4; m++)
#pragma unroll
        for (int nc = 0; nc < 4; nc++) {
            const int oc = 16 * m + g;
            const int n  = n0 + nb + 8 * nc + 2 * tig;
            const size_t r = ((size_t)(b * NHW) + n) * 64;
            enc[r + oc]           = qh[r + oc]           + coeff * acc[m][nc][0];
            enc[r + 64 + oc]      = qh[r + 64 + oc]      + coeff * acc[m][nc][1];
            enc[r + oc + 8]       = qh[r + oc + 8]       + coeff * acc[m][nc][2];
            enc[r + 64 + oc + 8]  = qh[r + 64 + oc + 8]  + coeff * acc[m][nc][3];
        }
}

// ============================================================
// MoCA via mma.sync (unchanged from R12)
// ============================================================
constexpr int MC68_OFF = 0;
constexpr int MC72_OFF = 256 * 68;
constexpr int MES_OFF  = MC72_OFF + 256 * 72;
#define MOCA_SMEM ((MES_OFF + 256 * 68) * 4)

__global__ __launch_bounds__(256, 1) void moca_mma_kernel(
    const float* __restrict__ E, const float* __restrict__ Cpt, float* __restrict__ O)
{
    float* smem = (float*)dyn_smem;
    const uint32_t sb = smem_u32(dyn_smem);
    const int tid  = threadIdx.x;
    const int warp = tid >> 5;
    const int lane = tid & 31;
    const int g    = lane >> 2;
    const int tig  = lane & 3;
    const int b  = blockIdx.y;
    const int n0 = blockIdx.x * 256;

    {
        const size_t er0 = (size_t)(b * NHW + n0);
#pragma unroll
        for (int j = 0; j < 16; j++) {
            int idx = j * 256 + tid;
            int r = idx >> 4, c4 = idx & 15;
            const float* csrc = Cpt + r * 64 + c4 * 4;
            cp16(sb + (uint32_t)(MC68_OFF + r * 68 + c4 * 4) * 4, csrc);
            cp16(sb + (uint32_t)(MC72_OFF + r * 72 + c4 * 4) * 4, csrc);
            cp16(sb + (uint32_t)(MES_OFF + r * 68 + c4 * 4) * 4,
                 E + (er0 + r) * 64 + c4 * 4);
        }
        CP_COMMIT();
        CP_WAIT(0);
        __syncthreads();
    }

    const uint32_t* Cs68 = (const uint32_t*)(smem + MC68_OFF);
    const uint32_t* Cs72 = (const uint32_t*)(smem + MC72_OFF);
    const uint32_t* Es   = (const uint32_t*)(smem + MES_OFF);

    float Oa[2][8][4];
    float lsum[2][2];
#pragma unroll
    for (int m = 0; m < 2; m++) {
        lsum[m][0] = 0.f; lsum[m][1] = 0.f;
#pragma unroll
        for (int c = 0; c < 8; c++)
#pragma unroll
            for (int r = 0; r < 4; r++) Oa[m][c][r] = 0.f;
    }

    const int q0 = warp * 32;

#pragma unroll
    for (int pt = 0; pt < 4; pt++) {
        const int p0 = pt * 64;

        float S[2][8][4];
#pragma unroll
        for (int m = 0; m < 2; m++)
#pragma unroll
            for (int n = 0; n < 8; n++)
#pragma unroll
                for (int r = 0; r < 4; r++) S[m][n][r] = 0.f;

#pragma unroll
        for (int k = 0; k < 8; k++) {
            uint32_t Ah[2][4];
#pragma unroll
            for (int m = 0; m < 2; m++) {
                const int qr = q0 + 16 * m;
                Ah[m][0] = Es[(qr + g) * PAD + 8 * k + tig];
                Ah[m][1] = Es[(qr + 8 + g) * PAD + 8 * k + tig];
                Ah[m][2] = Es[(qr + g) * PAD + 8 * k + tig + 4];
                Ah[m][3] = Es[(qr + 8 + g) * PAD + 8 * k + tig + 4];
            }
#pragma unroll
            for (int n = 0; n < 8; n++) {
                const int prow = p0 + 8 * n + g;
                uint32_t bh0 = Cs68[prow * PAD + 8 * k + tig];
                uint32_t bh1 = Cs68[prow * PAD + 8 * k + tig + 4];
                mma168(S[0][n], Ah[0], bh0, bh1);
                mma168(S[1][n], Ah[1], bh0, bh1);
            }
        }

#pragma unroll
        for (int m = 0; m < 2; m++) {
            float s0 = 0.f, s1 = 0.f;
#pragma unroll
            for (int n = 0; n < 8; n++) {
                float p0f = __expf(S[m][n][0]);
                float p1f = __expf(S[m][n][1]);
                float p2f = __expf(S[m][n][2]);
                float p3f = __expf(S[m][n][3]);
                S[m][n][0] = p0f; S[m][n][1] = p1f;
                S[m][n][2] = p2f; S[m][n][3] = p3f;
                s0 += p0f + p1f; s1 += p2f + p3f;
            }
            lsum[m][0] += s0; lsum[m][1] += s1;
        }

        const int base = lane & ~3;
        const int srcA = base | (tig >> 1);
        const int srcB = srcA + 2;
        const bool odd = (tig & 1);
#pragma unroll
        for (int n = 0; n < 8; n++) {
            uint32_t Ap[2][4];
#pragma unroll
            for (int m = 0; m < 2; m++) {
                float e0  = __shfl_sync(0xffffffffu, S[m][n][0], srcA);
                float e1  = __shfl_sync(0xffffffffu, S[m][n][1], srcA);
                float e2  = __shfl_sync(0xffffffffu, S[m][n][2], srcA);
                float e3  = __shfl_sync(0xffffffffu, S[m][n][3], srcA);
                float f0  = __shfl_sync(0xffffffffu, S[m][n][0], srcB);
                float f1  = __shfl_sync(0xffffffffu, S[m][n][1], srcB);
                float f2  = __shfl_sync(0xffffffffu, S[m][n][2], srcB);
                float f3  = __shfl_sync(0xffffffffu, S[m][n][3], srcB);
                Ap[m][0] = __float_as_uint(odd ? e1 : e0);
                Ap[m][1] = __float_as_uint(odd ? e3 : e2);
                Ap[m][2] = __float_as_uint(odd ? f1 : f0);
                Ap[m][3] = __float_as_uint(odd ? f3 : f2);
            }
#pragma unroll
            for (int c = 0; c < 8; c++) {
                uint32_t b0 = Cs72[(p0 + 8 * n + tig) * VPAD + 8 * c + g];
                uint32_t b1 = Cs72[(p0 + 8 * n + tig + 4) * VPAD + 8 * c + g];
                mma168(Oa[0][c], Ap[0], b0, b1);
                mma168(Oa[1][c], Ap[1], b0, b1);
            }
        }
    }

#pragma unroll
    for (int m = 0; m < 2; m++)
#pragma unroll
        for (int h = 0; h < 2; h++) {
            lsum[m][h] += __shfl_xor_sync(0xffffffffu, lsum[m][h], 1);
            lsum[m][h] += __shfl_xor_sync(0xffffffffu, lsum[m][h], 2);
            lsum[m][h] = 1.f / lsum[m][h];
        }

#pragma unroll
    for (int m = 0; m < 2; m++) {
        const int r0 = n0 + q0 + 16 * m + g;
#pragma unroll
        for (int c = 0; c < 8; c++) {
            float2 v0 = make_float2(Oa[m][c][0] * lsum[m][0], Oa[m][c][1] * lsum[m][0]);
            float2 v1 = make_float2(Oa[m][c][2] * lsum[m][1], Oa[m][c][3] * lsum[m][1]);
            *(float2*)&O[((size_t)(b * NHW) + r0)     * 64 + 8 * c + 2 * tig] = v0;
            *(float2*)&O[((size_t)(b * NHW) + r0 + 8) * 64 + 8 * c + 2 * tig] = v1;
        }
    }
}

// ============================================================
// fused output conv (unchanged from R12)
// ============================================================
#define CONV_SMEM ((512 * 68 + 2 * 64 * 68) * 4)
__global__ __launch_bounds__(256, 1) void conv_fused_kernel(
    const float* __restrict__ lat, const float* __restrict__ lat2,
    const float* __restrict__ Wo, const float* __restrict__ fm,
    const float* __restrict__ gsa, const float* __restrict__ gmoca,
    float* __restrict__ out)
{
    float* smem = (float*)dyn_smem;
    const uint32_t sb = smem_u32(dyn_smem);

    const int tid  = threadIdx.x;
    const int warp = tid >> 5;
    const int lane = tid & 31;
    const int g    = lane >> 2;
    const int tig  = lane & 3;
    const int b  = blockIdx.y;
    const int n0 = blockIdx.x * 64;

#pragma unroll
    for (int j = 0; j < 32; j++) {
        int idx = tid + j * 256;
        int oc = idx >> 4, l4 = (idx & 15) << 2;
        cp16(sb + (uint32_t)(oc * 68 + l4) * 4, Wo + oc * LL + l4);
    }
#pragma unroll
    for (int j = 0; j < 4; j++) {
        int idx = tid + j * 256;
        int cl = idx >> 4, n4 = (idx & 15) << 2;
        const size_t src = (size_t)b * (NHW * 64) + cl * NHW + n0 + n4;
        cp16(sb + (uint32_t)((512 + cl) * 68 + n4) * 4, lat + src);
        cp16(sb + (uint32_t)((576 + cl) * 68 + n4) * 4, lat2 + src);
    }
    CP_COMMIT();
    CP_WAIT(0);
    __syncthreads();

    float acc[4][8][4];
#pragma unroll
    for (int m = 0; m < 4; m++)
#pragma unroll
        for (int nc = 0; nc < 8; nc++)
#pragma unroll
            for (int r = 0; r < 4; r++) acc[m][nc][r] = 0.f;

    const uint32_t* Wu = (const uint32_t*)smem;
    const float* L1 = smem + 512 * 68;
    const float* L2 = smem + 576 * 68;
    const float cs = gsa[0], cm = gmoca[0];

#pragma unroll
    for (int kk = 0; kk < 8; kk++) {
        uint32_t A[4][4];
#pragma unroll
        for (int m = 0; m < 4; m++) {
            const int oc = 64 * warp + 16 * m;
            A[m][0] = Wu[(oc + g) * 68 + 8 * kk + tig];
            A[m][1] = Wu[(oc + 8 + g) * 68 + 8 * kk + tig];
            A[m][2] = Wu[(oc + g) * 68 + 8 * kk + tig + 4];
            A[m][3] = Wu[(oc + 8 + g) * 68 + 8 * kk + tig + 4];
        }
#pragma unroll
        for (int nc = 0; nc < 8; nc++) {
            const int i0 = (8 * kk + tig) * 68 + 8 * nc + g;
            const int i1 = (8 * kk + tig + 4) * 68 + 8 * nc + g;
            uint32_t b0 = __float_as_uint(cs * L1[i0] + cm * L2[i0]);
            uint32_t b1 = __float_as_uint(cs * L1[i1] + cm * L2[i1]);
#pragma unroll
            for (int m = 0; m < 4; m++) mma168(acc[m][nc], A[m], b0, b1);
        }
    }

#pragma unroll
    for (int m = 0; m < 4; m++)
#pragma unroll
        for (int nc = 0; nc < 8; nc++) {
            const int oc = 64 * warp + 16 * m + g;
            const int n  = n0 + 8 * nc + 2 * tig;
            const size_t base0 = ((size_t)(b * CC + oc)) * NHW + n;
            const size_t base1 = base0 + (size_t)8 * NHW;
            float2 a0 = *(const float2*)&fm[base0];
            float2 a1 = *(const float2*)&fm[base1];
            *(float2*)&out[base0] = make_float2(GAIN_O * acc[m][nc][0] + a0.x,
                                                GAIN_O * acc[m][nc][1] + a0.y);
            *(float2*)&out[base1] = make_float2(GAIN_O * acc[m][nc][2] + a1.x,
                                                GAIN_O * acc[m][nc][3] + a1.y);
        }
}

// ============================================================
extern "C" void kernel_launch(void* const* d_in, const int* in_sizes, int n_in,
                              void* d_out, int out_size)
{
    (void)in_sizes; (void)n_in; (void)out_size;
    const float* fm         = (const float*)d_in[0];
    const float* concepts   = (const float*)d_in[1];
    const float* w_theta    = (const float*)d_in[2];
    const float* w_phi      = (const float*)d_in[3];
    const float* w_g        = (const float*)d_in[4];
    const float* w_o        = (const float*)d_in[5];
    const float* gamma_sa   = (const float*)d_in[6];
    const float* gamma_moca = (const float*)d_in[7];
    float* out = (float*)d_out;

    float *qh, *kh, *vv, *lat, *enc, *lat2, *Mb;
    cudaGetSymbolAddress((void**)&qh,  g_qh);
    cudaGetSymbolAddress((void**)&kh,  g_kh);
    cudaGetSymbolAddress((void**)&vv,  g_vv);
    cudaGetSymbolAddress((void**)&lat, g_lat);
    cudaGetSymbolAddress((void**)&enc, g_enc);
    cudaGetSymbolAddress((void**)&lat2, g_lat2);
    cudaGetSymbolAddress((void**)&Mb,  g_M);

    cudaFuncSetAttribute(flash_mma_kernel, cudaFuncAttributeMaxDynamicSharedMemorySize, FT_SMEM);
    cudaFuncSetAttribute(proj_qkv_kernel,  cudaFuncAttributeMaxDynamicSharedMemorySize, QKV_SMEM);
    cudaFuncSetAttribute(enc_mma_kernel,   cudaFuncAttributeMaxDynamicSharedMemorySize, ENC_SMEM);
    cudaFuncSetAttribute(conv_fused_kernel, cudaFuncAttributeMaxDynamicSharedMemorySize, CONV_SMEM);
    cudaFuncSetAttribute(moca_mma_kernel,  cudaFuncAttributeMaxDynamicSharedMemorySize, MOCA_SMEM);

    mmat_kernel<<<16, 256>>>(w_theta, w_o, Mb);
    proj_qkv_kernel<<<dim3(32, 8), 256, QKV_SMEM>>>(fm, w_theta, w_phi, w_g, qh, kh, vv, GAIN_IN);
    flash_mma_kernel<<<dim3(16, 8), 256, FT_SMEM>>>(qh, kh, vv, lat);
    enc_mma_kernel<<<dim3(16, 8), 256, ENC_SMEM>>>(qh, lat, Mb, gamma_sa, enc);
    moca_mma_kernel<<<dim3(16, 8), 256, MOCA_SMEM>>>(enc, concepts, lat2);
    conv_fused_kernel<<<dim3(64, 8), 256, CONV_SMEM>>>(lat, lat2, w_o, fm, gamma_sa, gamma_moca, out);
}

// round 14
// speedup vs baseline: 2.2596x; 1.0768x over previous
#include <cuda_runtime.h>
#include <cstdint>

constexpr int BB  = 8;
constexpr int CC  = 512;
constexpr int LL  = 64;
constexpr int NHW = 4096;

#define GAIN_IN 0.04419417382415922f
#define GAIN_O  0.125f

// -------- device scratch --------
__device__ float g_qh [BB * NHW * LL];
__device__ float g_kh [BB * NHW * LL];
__device__ float g_vv [BB * NHW * LL];
__device__ float g_lat[BB * NHW * LL];
__device__ float g_enc[BB * NHW * LL];
__device__ float g_lat2[BB * NHW * LL];
__device__ float g_M  [LL * LL];
__device__ float g_wr [3 * LL * CC];     // tf32-rounded Wtheta|Wphi|Wg

extern __shared__ char dyn_smem[];

// ============================================================
// helpers
// ============================================================
__device__ __forceinline__ uint32_t smem_u32(const void* p) {
    uint32_t r;
    asm("{ .reg .u64 t; cvta.to.shared.u64 t, %1; cvt.u32.u64 %0, t; }" : "=r"(r) : "l"(p));
    return r;
}
__device__ __forceinline__ void cp16(uint32_t dst, const void* src) {
    asm volatile("cp.async.cg.shared.global [%0], [%1], 16;" :: "r"(dst), "l"(src));
}
#define CP_COMMIT() asm volatile("cp.async.commit_group;" ::: "memory")
#define CP_WAIT(n)  asm volatile("cp.async.wait_group %0;" :: "n"(n) : "memory")

__device__ __forceinline__ float tf32hi(float v) {
    float h;
    asm("cvt.rna.tf32.f32 %0, %1;" : "=f"(h) : "f"(v));
    return h;
}
__device__ __forceinline__ void mma168(float* d, const uint32_t* a, uint32_t b0, uint32_t b1) {
    asm volatile(
        "mma.sync.aligned.m16n8k8.row.col.f32.tf32.tf32.f32 "
        "{%0,%1,%2,%3}, {%4,%5,%6,%7}, {%8,%9}, {%0,%1,%2,%3};"
        : "+f"(d[0]), "+f"(d[1]), "+f"(d[2]), "+f"(d[3])
        : "r"(a[0]), "r"(a[1]), "r"(a[2]), "r"(a[3]), "r"(b0), "r"(b1));
}

// ============================================================
// w_round: tf32-round theta/phi/g weights into g_wr (once)
// ============================================================
__global__ __launch_bounds__(256) void wround_kernel(
    const float* __restrict__ Wt, const float* __restrict__ Wp,
    const float* __restrict__ Wg, float* __restrict__ wr)
{
    const int i = blockIdx.x * 256 + threadIdx.x;   // 0..32767
    wr[i]                = tf32hi(Wt[i]);
    wr[LL * CC + i]      = tf32hi(Wp[i]);
    wr[2 * LL * CC + i]  = tf32hi(Wg[i]);
}

// ============================================================
// flash attention v7: 128 threads / 4 warps / 128 q rows,
// 2 CTAs per SM (cross-CTA warp overlap), K/V double-buffered.
// grid (32, 8) = 256 CTAs, single wave at occ 2.
// ============================================================
constexpr int PAD  = 68;
constexpr int VPAD = 72;
constexpr int QROWS   = 128;
constexpr int QT_F    = QROWS * PAD;           // 8704
constexpr int OFF_Q   = 0;
constexpr int OFF_K   = QT_F;                  // 8704
constexpr int KSLOT_F = 64 * PAD;              // 4352
constexpr int OFF_V   = OFF_K + 2 * KSLOT_F;   // 17408
constexpr int VSLOT_F = 64 * VPAD;             // 4608
#define FT_SMEM ((OFF_V + 2 * VSLOT_F) * 4)    // 106496 bytes

__device__ __forceinline__ void loadK1(uint32_t dst, const float* Kh,
                                       int b, int m0, int tid) {
    const size_t row0 = (size_t)(b * NHW + m0);
#pragma unroll
    for (int j = 0; j < 8; j++) {
        int idx = j * 128 + tid;
        int r = idx >> 4, c4 = idx & 15;
        cp16(dst + (uint32_t)(r * PAD * 4 + c4 * 16), Kh + (row0 + r) * 64 + c4 * 4);
    }
}
__device__ __forceinline__ void loadV1(uint32_t dst, const float* Vg, int b, int m0, int tid) {
    const size_t row0 = (size_t)(b * NHW + m0);
#pragma unroll
    for (int j = 0; j < 8; j++) {
        int idx = j * 128 + tid;
        int r = idx >> 4, c4 = idx & 15;
        cp16(dst + (uint32_t)(r * VPAD * 4 + c4 * 16), Vg + (row0 + r) * 64 + c4 * 4);
    }
}

__global__ __launch_bounds__(128, 2) void flash_mma_kernel(
    const float* __restrict__ Qg, const float* __restrict__ Kg,
    const float* __restrict__ Vg, float* __restrict__ Og)
{
    float* smem = (float*)dyn_smem;
    const uint32_t sb = smem_u32(dyn_smem);
    const int tid  = threadIdx.x;
    const int warp = tid >> 5;        // 0..3
    const int lane = tid & 31;
    const int g    = lane >> 2;
    const int tig  = lane & 3;
    const int b  = blockIdx.y;
    const int n0 = blockIdx.x * QROWS;
    const int NT = 64;

    {
        const size_t qr0 = (size_t)(b * NHW + n0);
#pragma unroll
        for (int j = 0; j < 16; j++) {
            int idx = j * 128 + tid;           // 0..2047
            int r = idx >> 4, c4 = idx & 15;
            cp16(sb + OFF_Q * 4 + (uint32_t)(r * PAD * 4 + c4 * 16),
                 Qg + (qr0 + r) * 64 + c4 * 4);
        }
        loadK1(sb + OFF_K * 4, Kg, b, 0, tid);
        loadV1(sb + OFF_V * 4, Vg, b, 0, tid);
        CP_COMMIT();                          // group 0
    }

    const uint32_t* Qh = (const uint32_t*)(smem + OFF_Q);

    float Oa[2][8][4];
    float lsum[2][2];
#pragma unroll
    for (int m = 0; m < 2; m++) {
        lsum[m][0] = 0.f; lsum[m][1] = 0.f;
#pragma unroll
        for (int c = 0; c < 8; c++)
#pragma unroll
            for (int r = 0; r < 4; r++) Oa[m][c][r] = 0.f;
    }

    const int q0 = warp * 32;

    for (int i = 0; i < NT; i++) {
        if (i + 1 < NT) {
            const int s = (i + 1) & 1;
            loadK1(sb + (uint32_t)(OFF_K + s * KSLOT_F) * 4, Kg, b, (i + 1) * 64, tid);
            loadV1(sb + (uint32_t)(OFF_V + s * VSLOT_F) * 4, Vg, b, (i + 1) * 64, tid);
        }
        CP_COMMIT();
        CP_WAIT(1);                            // group i complete
        __syncthreads();

        const int sc = i & 1;
        const uint32_t* Kh = (const uint32_t*)(smem + OFF_K + sc * KSLOT_F);
        const uint32_t* Vt = (const uint32_t*)(smem + OFF_V + sc * VSLOT_F);

        // ---- S = Q K^T, 1x tf32 ----
        float S[2][8][4];
#pragma unroll
        for (int m = 0; m < 2; m++)
#pragma unroll
            for (int n = 0; n < 8; n++)
#pragma unroll
                for (int r = 0; r < 4; r++) S[m][n][r] = 0.f;

#pragma unroll
        for (int k = 0; k < 8; k++) {
            uint32_t Ah[2][4];
#pragma unroll
            for (int m = 0; m < 2; m++) {
                const int qr = q0 + 16 * m;
                Ah[m][0] = Qh[(qr + g) * PAD + 8 * k + tig];
                Ah[m][1] = Qh[(qr + 8 + g) * PAD + 8 * k + tig];
                Ah[m][2] = Qh[(qr + g) * PAD + 8 * k + tig + 4];
                Ah[m][3] = Qh[(qr + 8 + g) * PAD + 8 * k + tig + 4];
            }
#pragma unroll
            for (int n = 0; n < 8; n++) {
                const int krow = 8 * n + g;
                uint32_t bh0 = Kh[krow * PAD + 8 * k + tig];
                uint32_t bh1 = Kh[krow * PAD + 8 * k + tig + 4];
                mma168(S[0][n], Ah[0], bh0, bh1);
                mma168(S[1][n], Ah[1], bh0, bh1);
            }
        }

        // ---- P = exp(S) ----
#pragma unroll
        for (int m = 0; m < 2; m++) {
            float s0 = 0.f, s1 = 0.f;
#pragma unroll
            for (int n = 0; n < 8; n++) {
                float p0 = __expf(S[m][n][0]);
                float p1 = __expf(S[m][n][1]);
                float p2 = __expf(S[m][n][2]);
                float p3 = __expf(S[m][n][3]);
                S[m][n][0] = p0; S[m][n][1] = p1;
                S[m][n][2] = p2; S[m][n][3] = p3;
                s0 += p0 + p1; s1 += p2 + p3;
            }
            lsum[m][0] += s0; lsum[m][1] += s1;
        }

        // ---- O += P V ----
        const int base = lane & ~3;
        const int srcA = base | (tig >> 1);
        const int srcB = srcA + 2;
        const bool odd = (tig & 1);
#pragma unroll
        for (int n = 0; n < 8; n++) {
            uint32_t Ap[2][4];
#pragma unroll
            for (int m = 0; m < 2; m++) {
                float e0  = __shfl_sync(0xffffffffu, S[m][n][0], srcA);
                float e1  = __shfl_sync(0xffffffffu, S[m][n][1], srcA);
                float e2  = __shfl_sync(0xffffffffu, S[m][n][2], srcA);
                float e3  = __shfl_sync(0xffffffffu, S[m][n][3], srcA);
                float f0  = __shfl_sync(0xffffffffu, S[m][n][0], srcB);
                float f1  = __shfl_sync(0xffffffffu, S[m][n][1], srcB);
                float f2  = __shfl_sync(0xffffffffu, S[m][n][2], srcB);
                float f3  = __shfl_sync(0xffffffffu, S[m][n][3], srcB);
                Ap[m][0] = __float_as_uint(odd ? e1 : e0);
                Ap[m][1] = __float_as_uint(odd ? e3 : e2);
                Ap[m][2] = __float_as_uint(odd ? f1 : f0);
                Ap[m][3] = __float_as_uint(odd ? f3 : f2);
            }
#pragma unroll
            for (int c = 0; c < 8; c++) {
                uint32_t b0 = Vt[(8 * n + tig) * VPAD + 8 * c + g];
                uint32_t b1 = Vt[(8 * n + tig + 4) * VPAD + 8 * c + g];
                mma168(Oa[0][c], Ap[0], b0, b1);
                mma168(Oa[1][c], Ap[1], b0, b1);
            }
        }
    }

    // ---- epilogue ----
#pragma unroll
    for (int m = 0; m < 2; m++)
#pragma unroll
        for (int h = 0; h < 2; h++) {
            lsum[m][h] += __shfl_xor_sync(0xffffffffu, lsum[m][h], 1);
            lsum[m][h] += __shfl_xor_sync(0xffffffffu, lsum[m][h], 2);
            lsum[m][h] = 1.f / lsum[m][h];
        }

#pragma unroll
    for (int m = 0; m < 2; m++) {
        const int r0 = n0 + q0 + 16 * m + g;
#pragma unroll
        for (int c = 0; c < 8; c++) {
            float2 v0 = make_float2(Oa[m][c][0] * lsum[m][0], Oa[m][c][1] * lsum[m][0]);
            float2 v1 = make_float2(Oa[m][c][2] * lsum[m][1], Oa[m][c][3] * lsum[m][1]);
            *(float2*)&Og[((size_t)(b * NHW) + r0)     * 64 + 8 * c + 2 * tig] = v0;
            *(float2*)&Og[((size_t)(b * NHW) + r0 + 8) * 64 + 8 * c + 2 * tig] = v1;
        }
    }
}

// ============================================================
// fused theta+phi+g projection, weights PRE-ROUNDED in global.
// ============================================================
constexpr int QK_WCH = 64 * 68;
constexpr int QK_XCH = 64 * 132;
constexpr int QKV_XOFF = 6 * QK_WCH;
#define QKV_SMEM ((6 * QK_WCH + 2 * QK_XCH) * 4)

__device__ __forceinline__ void qkv_load_chunk(
    uint32_t sb, int s, const float* X, const float* wr,
    int b, int n0, int c0, int tid)
{
#pragma unroll
    for (int j = 0; j < 4; j++) {
        int idx = tid + j * 256;
        int o = idx >> 4, c4 = (idx & 15) << 2;
        uint32_t doff = (uint32_t)(o * 68 + c4) * 4;
        const int soff = o * CC + c0 + c4;
        cp16(sb + (uint32_t)((0 + s) * QK_WCH) * 4 + doff, wr + soff);
        cp16(sb + (uint32_t)((2 + s) * QK_WCH) * 4 + doff, wr + LL * CC + soff);
        cp16(sb + (uint32_t)((4 + s) * QK_WCH) * 4 + doff, wr + 2 * LL * CC + soff);
    }
    const uint32_t xd = sb + (uint32_t)(QKV_XOFF + s * QK_XCH) * 4;
#pragma unroll
    for (int j = 0; j < 8; j++) {
        int idx = tid + j * 256;
        int cl = idx >> 5, n4 = (idx & 31) << 2;
        cp16(xd + (uint32_t)(cl * 132 + n4) * 4,
             X + ((size_t)(b * CC + c0 + cl)) * NHW + n0 + n4);
    }
}

__global__ __launch_bounds__(256) void proj_qkv_kernel(
    const float* __restrict__ X, const float* __restrict__ wr,
    float* __restrict__ oq, float* __restrict__ ok, float* __restrict__ ov, float gain)
{
    float* smem = (float*)dyn_smem;
    const uint32_t sb = smem_u32(dyn_smem);
    const int tid  = threadIdx.x;
    const int warp = tid >> 5;
    const int lane = tid & 31;
    const int g    = lane >> 2;
    const int tig  = lane & 3;
    const int b  = blockIdx.y;
    const int n0 = blockIdx.x * 128;
    const int m0 = 16 * warp;

    qkv_load_chunk(sb, 0, X, wr, b, n0, 0, tid);
    CP_COMMIT();

    float aq[8][4], ak[8][4], av[8][4];
#pragma unroll
    for (int nc = 0; nc < 8; nc++)
#pragma unroll
        for (int r = 0; r < 4; r++) { aq[nc][r] = 0.f; ak[nc][r] = 0.f; av[nc][r] = 0.f; }

    for (int kc = 0; kc < 8; kc++) {
        __syncthreads();
        if (kc + 1 < 8) qkv_load_chunk(sb, (kc + 1) & 1, X, wr, b, n0, (kc + 1) * 64, tid);
        CP_COMMIT();
        if (kc + 1 < 8) { CP_WAIT(1); } else { CP_WAIT(0); }
        __syncthreads();

        const uint32_t* Wtu = (const uint32_t*)(smem + (0 + (kc & 1)) * QK_WCH);
        const uint32_t* Wpu = (const uint32_t*)(smem + (2 + (kc & 1)) * QK_WCH);
        const uint32_t* Wgu = (const uint32_t*)(smem + (4 + (kc & 1)) * QK_WCH);
        const float* Xc = smem + QKV_XOFF + (kc & 1) * QK_XCH;

#pragma unroll
        for (int kk = 0; kk < 8; kk++) {
            float x0 = Xc[(8 * kk + tig) * 132 + m0 + g];
            float x1 = Xc[(8 * kk + tig) * 132 + m0 + 8 + g];
            float x2 = Xc[(8 * kk + tig + 4) * 132 + m0 + g];
            float x3 = Xc[(8 * kk + tig + 4) * 132 + m0 + 8 + g];
            float h0 = tf32hi(x0), h1 = tf32hi(x1), h2 = tf32hi(x2), h3 = tf32hi(x3);
            uint32_t Ah[4] = {__float_as_uint(h0), __float_as_uint(h1),
                              __float_as_uint(h2), __float_as_uint(h3)};
            uint32_t Al[4] = {__float_as_uint(x0 - h0), __float_as_uint(x1 - h1),
                              __float_as_uint(x2 - h2), __float_as_uint(x3 - h3)};
#pragma unroll
            for (int nc = 0; nc < 8; nc++) {
                const int wrow = (8 * nc + g) * 68 + 8 * kk + tig;
                uint32_t tb0 = Wtu[wrow], tb1 = Wtu[wrow + 4];
                mma168(aq[nc], Ah, tb0, tb1);
                mma168(aq[nc], Al, tb0, tb1);
                uint32_t pb0 = Wpu[wrow], pb1 = Wpu[wrow + 4];
                mma168(ak[nc], Ah, pb0, pb1);
                mma168(ak[nc], Al, pb0, pb1);
                uint32_t gb0 = Wgu[wrow], gb1 = Wgu[wrow + 4];
                mma168(av[nc], Ah, gb0, gb1);
                mma168(av[nc], Al, gb0, gb1);
            }
        }
    }

#pragma unroll
    for (int nc = 0; nc < 8; nc++) {
        const int o = 8 * nc + 2 * tig;
        const size_t r0 = (size_t)(b * NHW + n0 + m0 + g);
        const size_t r1 = r0 + 8;
        *(float2*)&oq[r0 * 64 + o] = make_float2(tf32hi(aq[nc][0] * gain), tf32hi(aq[nc][1] * gain));
        *(float2*)&oq[r1 * 64 + o] = make_float2(tf32hi(aq[nc][2] * gain), tf32hi(aq[nc][3] * gain));
        *(float2*)&ok[r0 * 64 + o] = make_float2(tf32hi(ak[nc][0] * gain), tf32hi(ak[nc][1] * gain));
        *(float2*)&ok[r1 * 64 + o] = make_float2(tf32hi(ak[nc][2] * gain), tf32hi(ak[nc][3] * gain));
        *(float2*)&ov[r0 * 64 + o] = make_float2(av[nc][0] * gain, av[nc][1] * gain);
        *(float2*)&ov[r1 * 64 + o] = make_float2(av[nc][2] * gain, av[nc][3] * gain);
    }
}

// ============================================================
// mmat (unchanged)
// ============================================================
__global__ __launch_bounds__(256) void mmat_kernel(
    const float* __restrict__ Wt, const float* __restrict__ Wo, float* __restrict__ M)
{
    const int gid = blockIdx.x * 256 + threadIdx.x;
    const int o = gid >> 6, l = gid & 63;
    float acc = 0.f;
    for (int c = 0; c < CC; c++)
        acc += Wt[o * CC + c] * Wo[c * LL + l];
    M[o * LL + l] = GAIN_IN * acc;
}

// ============================================================
// enc via mma (unchanged from R13)
// ============================================================
constexpr int ELPAD = 260;
#define ENC_SMEM ((64 * 68 + 64 * ELPAD) * 4)

__global__ __launch_bounds__(256, 1) void enc_mma_kernel(
    const float* __restrict__ qh, const float* __restrict__ lat,
    const float* __restrict__ M, const float* __restrict__ gamma_sa,
    float* __restrict__ enc)
{
    float* smem = (float*)dyn_smem;
    const uint32_t sb = smem_u32(dyn_smem);
    float* Ls = smem + 64 * 68;

    const int tid  = threadIdx.x;
    const int warp = tid >> 5;
    const int lane = tid & 31;
    const int g    = lane >> 2;
    const int tig  = lane & 3;
    const int b  = blockIdx.y;
    const int n0 = blockIdx.x * 256;
    const int nb = warp * 32;

#pragma unroll
    for (int j = 0; j < 4; j++) {
        int idx = tid + j * 256;
        int o = idx >> 4, c4 = (idx & 15) << 2;
        cp16(sb + (uint32_t)(o * 68 + c4) * 4, M + o * 64 + c4);
    }
#pragma unroll
    for (int j = 0; j < 16; j++) {
        int idx = tid + j * 256;
        int l = idx >> 6, n4 = (idx & 63) << 2;
        cp16(sb + (uint32_t)(64 * 68 + l * ELPAD + n4) * 4,
             lat + (size_t)b * (NHW * 64) + l * NHW + n0 + n4);
    }
    CP_COMMIT();
    CP_WAIT(0);
    __syncthreads();

    float acc[4][4][4];
#pragma unroll
    for (int m = 0; m < 4; m++)
#pragma unroll
        for (int nc = 0; nc < 4; nc++)
#pragma unroll
            for (int r = 0; r < 4; r++) acc[m][nc][r] = 0.f;

    const uint32_t* Mu = (const uint32_t*)smem;
    const uint32_t* Lu = (const uint32_t*)Ls;

#pragma unroll
    for (int kk = 0; kk < 8; kk++) {
        uint32_t A[4][4];
#pragma unroll
        for (int m = 0; m < 4; m++) {
            const int oc = 16 * m;
            A[m][0] = Mu[(oc + g) * 68 + 8 * kk + tig];
            A[m][1] = Mu[(oc + 8 + g) * 68 + 8 * kk + tig];
            A[m][2] = Mu[(oc + g) * 68 + 8 * kk + tig + 4];
            A[m][3] = Mu[(oc + 8 + g) * 68 + 8 * kk + tig + 4];
        }
#pragma unroll
        for (int nc = 0; nc < 4; nc++) {
            const int col = nb + 8 * nc + g;
            uint32_t b0 = Lu[(8 * kk + tig) * ELPAD + col];
            uint32_t b1 = Lu[(8 * kk + tig + 4) * ELPAD + col];
#pragma unroll
            for (int m = 0; m < 4; m++) mma168(acc[m][nc], A[m], b0, b1);
        }
    }

    const float coeff = gamma_sa[0] * GAIN_O;
#pragma unroll
    for (int m = 0; m < 4; m++)
#pragma unroll
        for (int nc = 0; nc < 4; nc++) {
            const int oc = 16 * m + g;
            const int n  = n0 + nb + 8 * nc + 2 * tig;
            const size_t r = ((size_t)(b * NHW) + n) * 64;
            enc[r + oc]           = qh[r + oc]           + coeff * acc[m][nc][0];
            enc[r + 64 + oc]      = qh[r + 64 + oc]      + coeff * acc[m][nc][1];
            enc[r + oc + 8]       = qh[r + oc + 8]       + coeff * acc[m][nc][2];
            enc[r + 64 + oc + 8]  = qh[r + 64 + oc + 8]  + coeff * acc[m][nc][3];
        }
}

// ============================================================
// MoCA via mma.sync (unchanged)
// ============================================================
constexpr int MC68_OFF = 0;
constexpr int MC72_OFF = 256 * 68;
constexpr int MES_OFF  = MC72_OFF + 256 * 72;
#define MOCA_SMEM ((MES_OFF + 256 * 68) * 4)

__global__ __launch_bounds__(256, 1) void moca_mma_kernel(
    const float* __restrict__ E, const float* __restrict__ Cpt, float* __restrict__ O)
{
    float* smem = (float*)dyn_smem;
    const uint32_t sb = smem_u32(dyn_smem);
    const int tid  = threadIdx.x;
    const int warp = tid >> 5;
    const int lane = tid & 31;
    const int g    = lane >> 2;
    const int tig  = lane & 3;
    const int b  = blockIdx.y;
    const int n0 = blockIdx.x * 256;

    {
        const size_t er0 = (size_t)(b * NHW + n0);
#pragma unroll
        for (int j = 0; j < 16; j++) {
            int idx = j * 256 + tid;
            int r = idx >> 4, c4 = idx & 15;
            const float* csrc = Cpt + r * 64 + c4 * 4;
            cp16(sb + (uint32_t)(MC68_OFF + r * 68 + c4 * 4) * 4, csrc);
            cp16(sb + (uint32_t)(MC72_OFF + r * 72 + c4 * 4) * 4, csrc);
            cp16(sb + (uint32_t)(MES_OFF + r * 68 + c4 * 4) * 4,
                 E + (er0 + r) * 64 + c4 * 4);
        }
        CP_COMMIT();
        CP_WAIT(0);
        __syncthreads();
    }

    const uint32_t* Cs68 = (const uint32_t*)(smem + MC68_OFF);
    const uint32_t* Cs72 = (const uint32_t*)(smem + MC72_OFF);
    const uint32_t* Es   = (const uint32_t*)(smem + MES_OFF);

    float Oa[2][8][4];
    float lsum[2][2];
#pragma unroll
    for (int m = 0; m < 2; m++) {
        lsum[m][0] = 0.f; lsum[m][1] = 0.f;
#pragma unroll
        for (int c = 0; c < 8; c++)
#pragma unroll
            for (int r = 0; r < 4; r++) Oa[m][c][r] = 0.f;
    }

    const int q0 = warp * 32;

#pragma unroll
    for (int pt = 0; pt < 4; pt++) {
        const int p0 = pt * 64;

        float S[2][8][4];
#pragma unroll
        for (int m = 0; m < 2; m++)
#pragma unroll
            for (int n = 0; n < 8; n++)
#pragma unroll
                for (int r = 0; r < 4; r++) S[m][n][r] = 0.f;

#pragma unroll
        for (int k = 0; k < 8; k++) {
            uint32_t Ah[2][4];
#pragma unroll
            for (int m = 0; m < 2; m++) {
                const int qr = q0 + 16 * m;
                Ah[m][0] = Es[(qr + g) * PAD + 8 * k + tig];
                Ah[m][1] = Es[(qr + 8 + g) * PAD + 8 * k + tig];
                Ah[m][2] = Es[(qr + g) * PAD + 8 * k + tig + 4];
                Ah[m][3] = Es[(qr + 8 + g) * PAD + 8 * k + tig + 4];
            }
#pragma unroll
            for (int n = 0; n < 8; n++) {
                const int prow = p0 + 8 * n + g;
                uint32_t bh0 = Cs68[prow * PAD + 8 * k + tig];
                uint32_t bh1 = Cs68[prow * PAD + 8 * k + tig + 4];
                mma168(S[0][n], Ah[0], bh0, bh1);
                mma168(S[1][n], Ah[1], bh0, bh1);
            }
        }

#pragma unroll
        for (int m = 0; m < 2; m++) {
            float s0 = 0.f, s1 = 0.f;
#pragma unroll
            for (int n = 0; n < 8; n++) {
                float p0f = __expf(S[m][n][0]);
                float p1f = __expf(S[m][n][1]);
                float p2f = __expf(S[m][n][2]);
                float p3f = __expf(S[m][n][3]);
                S[m][n][0] = p0f; S[m][n][1] = p1f;
                S[m][n][2] = p2f; S[m][n][3] = p3f;
                s0 += p0f + p1f; s1 += p2f + p3f;
            }
            lsum[m][0] += s0; lsum[m][1] += s1;
        }

        const int base = lane & ~3;
        const int srcA = base | (tig >> 1);
        const int srcB = srcA + 2;
        const bool odd = (tig & 1);
#pragma unroll
        for (int n = 0; n < 8; n++) {
            uint32_t Ap[2][4];
#pragma unroll
            for (int m = 0; m < 2; m++) {
                float e0  = __shfl_sync(0xffffffffu, S[m][n][0], srcA);
                float e1  = __shfl_sync(0xffffffffu, S[m][n][1], srcA);
                float e2  = __shfl_sync(0xffffffffu, S[m][n][2], srcA);
                float e3  = __shfl_sync(0xffffffffu, S[m][n][3], srcA);
                float f0  = __shfl_sync(0xffffffffu, S[m][n][0], srcB);
                float f1  = __shfl_sync(0xffffffffu, S[m][n][1], srcB);
                float f2  = __shfl_sync(0xffffffffu, S[m][n][2], srcB);
                float f3  = __shfl_sync(0xffffffffu, S[m][n][3], srcB);
                Ap[m][0] = __float_as_uint(odd ? e1 : e0);
                Ap[m][1] = __float_as_uint(odd ? e3 : e2);
                Ap[m][2] = __float_as_uint(odd ? f1 : f0);
                Ap[m][3] = __float_as_uint(odd ? f3 : f2);
            }
#pragma unroll
            for (int c = 0; c < 8; c++) {
                uint32_t b0 = Cs72[(p0 + 8 * n + tig) * VPAD + 8 * c + g];
                uint32_t b1 = Cs72[(p0 + 8 * n + tig + 4) * VPAD + 8 * c + g];
                mma168(Oa[0][c], Ap[0], b0, b1);
                mma168(Oa[1][c], Ap[1], b0, b1);
            }
        }
    }

#pragma unroll
    for (int m = 0; m < 2; m++)
#pragma unroll
        for (int h = 0; h < 2; h++) {
            lsum[m][h] += __shfl_xor_sync(0xffffffffu, lsum[m][h], 1);
            lsum[m][h] += __shfl_xor_sync(0xffffffffu, lsum[m][h], 2);
            lsum[m][h] = 1.f / lsum[m][h];
        }

#pragma unroll
    for (int m = 0; m < 2; m++) {
        const int r0 = n0 + q0 + 16 * m + g;
#pragma unroll
        for (int c = 0; c < 8; c++) {
            float2 v0 = make_float2(Oa[m][c][0] * lsum[m][0], Oa[m][c][1] * lsum[m][0]);
            float2 v1 = make_float2(Oa[m][c][2] * lsum[m][1], Oa[m][c][3] * lsum[m][1]);
            *(float2*)&O[((size_t)(b * NHW) + r0)     * 64 + 8 * c + 2 * tig] = v0;
            *(float2*)&O[((size_t)(b * NHW) + r0 + 8) * 64 + 8 * c + 2 * tig] = v1;
        }
    }
}

// ============================================================
// fused output conv (unchanged)
// ============================================================
#define CONV_SMEM ((512 * 68 + 2 * 64 * 68) * 4)
__global__ __launch_bounds__(256, 1) void conv_fused_kernel(
    const float* __restrict__ lat, const float* __restrict__ lat2,
    const float* __restrict__ Wo, const float* __restrict__ fm,
    const float* __restrict__ gsa, const float* __restrict__ gmoca,
    float* __restrict__ out)
{
    float* smem = (float*)dyn_smem;
    const uint32_t sb = smem_u32(dyn_smem);

    const int tid  = threadIdx.x;
    const int warp = tid >> 5;
    const int lane = tid & 31;
    const int g    = lane >> 2;
    const int tig  = lane & 3;
    const int b  = blockIdx.y;
    const int n0 = blockIdx.x * 64;

#pragma unroll
    for (int j = 0; j < 32; j++) {
        int idx = tid + j * 256;
        int oc = idx >> 4, l4 = (idx & 15) << 2;
        cp16(sb + (uint32_t)(oc * 68 + l4) * 4, Wo + oc * LL + l4);
    }
#pragma unroll
    for (int j = 0; j < 4; j++) {
        int idx = tid + j * 256;
        int cl = idx >> 4, n4 = (idx & 15) << 2;
        const size_t src = (size_t)b * (NHW * 64) + cl * NHW + n0 + n4;
        cp16(sb + (uint32_t)((512 + cl) * 68 + n4) * 4, lat + src);
        cp16(sb + (uint32_t)((576 + cl) * 68 + n4) * 4, lat2 + src);
    }
    CP_COMMIT();
    CP_WAIT(0);
    __syncthreads();

    float acc[4][8][4];
#pragma unroll
    for (int m = 0; m < 4; m++)
#pragma unroll
        for (int nc = 0; nc < 8; nc++)
#pragma unroll
            for (int r = 0; r < 4; r++) acc[m][nc][r] = 0.f;

    const uint32_t* Wu = (const uint32_t*)smem;
    const float* L1 = smem + 512 * 68;
    const float* L2 = smem + 576 * 68;
    const float cs = gsa[0], cm = gmoca[0];

#pragma unroll
    for (int kk = 0; kk < 8; kk++) {
        uint32_t A[4][4];
#pragma unroll
        for (int m = 0; m < 4; m++) {
            const int oc = 64 * warp + 16 * m;
            A[m][0] = Wu[(oc + g) * 68 + 8 * kk + tig];
            A[m][1] = Wu[(oc + 8 + g) * 68 + 8 * kk + tig];
            A[m][2] = Wu[(oc + g) * 68 + 8 * kk + tig + 4];
            A[m][3] = Wu[(oc + 8 + g) * 68 + 8 * kk + tig + 4];
        }
#pragma unroll
        for (int nc = 0; nc < 8; nc++) {
            const int i0 = (8 * kk + tig) * 68 + 8 * nc + g;
            const int i1 = (8 * kk + tig + 4) * 68 + 8 * nc + g;
            uint32_t b0 = __float_as_uint(cs * L1[i0] + cm * L2[i0]);
            uint32_t b1 = __float_as_uint(cs * L1[i1] + cm * L2[i1]);
#pragma unroll
            for (int m = 0; m < 4; m++) mma168(acc[m][nc], A[m], b0, b1);
        }
    }

#pragma unroll
    for (int m = 0; m < 4; m++)
#pragma unroll
        for (int nc = 0; nc < 8; nc++) {
            const int oc = 64 * warp + 16 * m + g;
            const int n  = n0 + 8 * nc + 2 * tig;
            const size_t base0 = ((size_t)(b * CC + oc)) * NHW + n;
            const size_t base1 = base0 + (size_t)8 * NHW;
            float2 a0 = *(const float2*)&fm[base0];
            float2 a1 = *(const float2*)&fm[base1];
            *(float2*)&out[base0] = make_float2(GAIN_O * acc[m][nc][0] + a0.x,
                                                GAIN_O * acc[m][nc][1] + a0.y);
            *(float2*)&out[base1] = make_float2(GAIN_O * acc[m][nc][2] + a1.x,
                                                GAIN_O * acc[m][nc][3] + a1.y);
        }
}

// ============================================================
extern "C" void kernel_launch(void* const* d_in, const int* in_sizes, int n_in,
                              void* d_out, int out_size)
{
    (void)in_sizes; (void)n_in; (void)out_size;
    const float* fm         = (const float*)d_in[0];
    const float* concepts   = (const float*)d_in[1];
    const float* w_theta    = (const float*)d_in[2];
    const float* w_phi      = (const float*)d_in[3];
    const float* w_g        = (const float*)d_in[4];
    const float* w_o        = (const float*)d_in[5];
    const float* gamma_sa   = (const float*)d_in[6];
    const float* gamma_moca = (const float*)d_in[7];
    float* out = (float*)d_out;

    float *qh, *kh, *vv, *lat, *enc, *lat2, *Mb, *wr;
    cudaGetSymbolAddress((void**)&qh,  g_qh);
    cudaGetSymbolAddress((void**)&kh,  g_kh);
    cudaGetSymbolAddress((void**)&vv,  g_vv);
    cudaGetSymbolAddress((void**)&lat, g_lat);
    cudaGetSymbolAddress((void**)&enc, g_enc);
    cudaGetSymbolAddress((void**)&lat2, g_lat2);
    cudaGetSymbolAddress((void**)&Mb,  g_M);
    cudaGetSymbolAddress((void**)&wr,  g_wr);

    cudaFuncSetAttribute(flash_mma_kernel, cudaFuncAttributeMaxDynamicSharedMemorySize, FT_SMEM);
    cudaFuncSetAttribute(proj_qkv_kernel,  cudaFuncAttributeMaxDynamicSharedMemorySize, QKV_SMEM);
    cudaFuncSetAttribute(enc_mma_kernel,   cudaFuncAttributeMaxDynamicSharedMemorySize, ENC_SMEM);
    cudaFuncSetAttribute(conv_fused_kernel, cudaFuncAttributeMaxDynamicSharedMemorySize, CONV_SMEM);
    cudaFuncSetAttribute(moca_mma_kernel,  cudaFuncAttributeMaxDynamicSharedMemorySize, MOCA_SMEM);

    wround_kernel<<<128, 256>>>(w_theta, w_phi, w_g, wr);
    mmat_kernel<<<16, 256>>>(w_theta, w_o, Mb);
    proj_qkv_kernel<<<dim3(32, 8), 256, QKV_SMEM>>>(fm, wr, qh, kh, vv, GAIN_IN);
    flash_mma_kernel<<<dim3(32, 8), 128, FT_SMEM>>>(qh, kh, vv, lat);
    enc_mma_kernel<<<dim3(16, 8), 256, ENC_SMEM>>>(qh, lat, Mb, gamma_sa, enc);
    moca_mma_kernel<<<dim3(16, 8), 256, MOCA_SMEM>>>(enc, concepts, lat2);
    conv_fused_kernel<<<dim3(64, 8), 256, CONV_SMEM>>>(lat, lat2, w_o, fm, gamma_sa, gamma_moca, out);
}

// round 15
// speedup vs baseline: 2.5781x; 1.1409x over previous
#include <cuda_runtime.h>
#include <cuda_bf16.h>
#include <cstdint>

constexpr int BB  = 8;
constexpr int CC  = 512;
constexpr int LL  = 64;
constexpr int NHW = 4096;

#define GAIN_IN 0.04419417382415922f
#define GAIN_O  0.125f

// -------- device scratch --------
__device__ float g_qh [BB * NHW * LL];
__device__ float g_kh [BB * NHW * LL];
__device__ __nv_bfloat16 g_vb [BB * LL * NHW];   // V, bf16, [b][c][n]
__device__ float g_lat[BB * NHW * LL];
__device__ float g_enc[BB * NHW * LL];
__device__ float g_lat2[BB * NHW * LL];
__device__ float g_M  [LL * LL];
__device__ float g_wr [3 * LL * CC];

extern __shared__ char dyn_smem[];

// ============================================================
// helpers
// ============================================================
__device__ __forceinline__ uint32_t smem_u32(const void* p) {
    uint32_t r;
    asm("{ .reg .u64 t; cvta.to.shared.u64 t, %1; cvt.u32.u64 %0, t; }" : "=r"(r) : "l"(p));
    return r;
}
__device__ __forceinline__ void cp16(uint32_t dst, const void* src) {
    asm volatile("cp.async.cg.shared.global [%0], [%1], 16;" :: "r"(dst), "l"(src));
}
#define CP_COMMIT() asm volatile("cp.async.commit_group;" ::: "memory")
#define CP_WAIT(n)  asm volatile("cp.async.wait_group %0;" :: "n"(n) : "memory")

__device__ __forceinline__ float tf32hi(float v) {
    float h;
    asm("cvt.rna.tf32.f32 %0, %1;" : "=f"(h) : "f"(v));
    return h;
}
__device__ __forceinline__ uint32_t pack_bf16(float lo, float hi) {
    uint32_t r;
    asm("cvt.rn.bf16x2.f32 %0, %1, %2;" : "=r"(r) : "f"(hi), "f"(lo));
    return r;
}
__device__ __forceinline__ void mma168(float* d, const uint32_t* a, uint32_t b0, uint32_t b1) {
    asm volatile(
        "mma.sync.aligned.m16n8k8.row.col.f32.tf32.tf32.f32 "
        "{%0,%1,%2,%3}, {%4,%5,%6,%7}, {%8,%9}, {%0,%1,%2,%3};"
        : "+f"(d[0]), "+f"(d[1]), "+f"(d[2]), "+f"(d[3])
        : "r"(a[0]), "r"(a[1]), "r"(a[2]), "r"(a[3]), "r"(b0), "r"(b1));
}
__device__ __forceinline__ void mmabf(float* d, const uint32_t* a, uint32_t b0, uint32_t b1) {
    asm volatile(
        "mma.sync.aligned.m16n8k16.row.col.f32.bf16.bf16.f32 "
        "{%0,%1,%2,%3}, {%4,%5,%6,%7}, {%8,%9}, {%0,%1,%2,%3};"
        : "+f"(d[0]), "+f"(d[1]), "+f"(d[2]), "+f"(d[3])
        : "r"(a[0]), "r"(a[1]), "r"(a[2]), "r"(a[3]), "r"(b0), "r"(b1));
}

// ============================================================
// w_round (unchanged)
// ============================================================
__global__ __launch_bounds__(256) void wround_kernel(
    const float* __restrict__ Wt, const float* __restrict__ Wp,
    const float* __restrict__ Wg, float* __restrict__ wr)
{
    const int i = blockIdx.x * 256 + threadIdx.x;
    wr[i]                = tf32hi(Wt[i]);
    wr[LL * CC + i]      = tf32hi(Wp[i]);
    wr[2 * LL * CC + i]  = tf32hi(Wg[i]);
}

// ============================================================
// flash v8: S 1x tf32, PV bf16 m16n8k16 (no shuffles).
// 128 thr / 4 warps / 128 q rows, 2 CTAs/SM, K/V double-buffered.
// V smem: [c][key] bf16, 72 bf16/row (conflict-free word = lane).
// ============================================================
constexpr int PAD  = 68;
constexpr int QROWS   = 128;
constexpr uint32_t OFF_Q_B   = 0;
constexpr uint32_t OFF_K_B   = 128 * PAD * 4;            // 34816
constexpr uint32_t KSLOT_B   = 64 * PAD * 4;             // 17408
constexpr uint32_t OFF_V_B   = OFF_K_B + 2 * KSLOT_B;    // 69632
constexpr uint32_t VSLOT_B   = 64 * 72 * 2;              // 9216 (64 c rows x 72 bf16)
#define FT_SMEM (OFF_V_B + 2 * VSLOT_B)                  // 88064 bytes

__device__ __forceinline__ void loadK1(uint32_t dst, const float* Kh,
                                       int b, int m0, int tid) {
    const size_t row0 = (size_t)(b * NHW + m0);
#pragma unroll
    for (int j = 0; j < 8; j++) {
        int idx = j * 128 + tid;
        int r = idx >> 4, c4 = idx & 15;
        cp16(dst + (uint32_t)(r * PAD * 4 + c4 * 16), Kh + (row0 + r) * 64 + c4 * 4);
    }
}
// V: global bf16 [b][c][n]; smem row c: 64 keys = 128 B -> 8 cp16 per row
__device__ __forceinline__ void loadVb(uint32_t dst, const __nv_bfloat16* Vb,
                                       int b, int m0, int tid) {
#pragma unroll
    for (int j = 0; j < 4; j++) {
        int idx = j * 128 + tid;           // 0..511
        int r = idx >> 3, seg = idx & 7;   // c row, 16B segment (8 keys)
        cp16(dst + (uint32_t)(r * 144 + seg * 16),
             Vb + ((size_t)(b * LL + r)) * NHW + m0 + seg * 8);
    }
}

__global__ __launch_bounds__(128, 2) void flash_mma_kernel(
    const float* __restrict__ Qg, const float* __restrict__ Kg,
    const __nv_bfloat16* __restrict__ Vb, float* __restrict__ Og)
{
    float* smem = (float*)dyn_smem;
    const uint32_t sb = smem_u32(dyn_smem);
    const int tid  = threadIdx.x;
    const int warp = tid >> 5;
    const int lane = tid & 31;
    const int g    = lane >> 2;
    const int tig  = lane & 3;
    const int b  = blockIdx.y;
    const int n0 = blockIdx.x * QROWS;
    const int NT = 64;

    {
        const size_t qr0 = (size_t)(b * NHW + n0);
#pragma unroll
        for (int j = 0; j < 16; j++) {
            int idx = j * 128 + tid;
            int r = idx >> 4, c4 = idx & 15;
            cp16(sb + OFF_Q_B + (uint32_t)(r * PAD * 4 + c4 * 16),
                 Qg + (qr0 + r) * 64 + c4 * 4);
        }
        loadK1(sb + OFF_K_B, Kg, b, 0, tid);
        loadVb(sb + OFF_V_B, Vb, b, 0, tid);
        CP_COMMIT();
    }

    const uint32_t* Qh = (const uint32_t*)(smem);

    float Oa[2][8][4];
    float lsum[2][2];
#pragma unroll
    for (int m = 0; m < 2; m++) {
        lsum[m][0] = 0.f; lsum[m][1] = 0.f;
#pragma unroll
        for (int c = 0; c < 8; c++)
#pragma unroll
            for (int r = 0; r < 4; r++) Oa[m][c][r] = 0.f;
    }

    const int q0 = warp * 32;

    for (int i = 0; i < NT; i++) {
        if (i + 1 < NT) {
            const int s = (i + 1) & 1;
            loadK1(sb + OFF_K_B + (uint32_t)s * KSLOT_B, Kg, b, (i + 1) * 64, tid);
            loadVb(sb + OFF_V_B + (uint32_t)s * VSLOT_B, Vb, b, (i + 1) * 64, tid);
        }
        CP_COMMIT();
        CP_WAIT(1);
        __syncthreads();

        const int sc = i & 1;
        const uint32_t* Kh = (const uint32_t*)(dyn_smem + OFF_K_B + sc * KSLOT_B);
        const uint32_t* Vs = (const uint32_t*)(dyn_smem + OFF_V_B + sc * VSLOT_B);

        // ---- S = Q K^T, 1x tf32 ----
        float S[2][8][4];
#pragma unroll
        for (int m = 0; m < 2; m++)
#pragma unroll
            for (int n = 0; n < 8; n++)
#pragma unroll
                for (int r = 0; r < 4; r++) S[m][n][r] = 0.f;

#pragma unroll
        for (int k = 0; k < 8; k++) {
            uint32_t Ah[2][4];
#pragma unroll
            for (int m = 0; m < 2; m++) {
                const int qr = q0 + 16 * m;
                Ah[m][0] = Qh[(qr + g) * PAD + 8 * k + tig];
                Ah[m][1] = Qh[(qr + 8 + g) * PAD + 8 * k + tig];
                Ah[m][2] = Qh[(qr + g) * PAD + 8 * k + tig + 4];
                Ah[m][3] = Qh[(qr + 8 + g) * PAD + 8 * k + tig + 4];
            }
#pragma unroll
            for (int n = 0; n < 8; n++) {
                const int krow = 8 * n + g;
                uint32_t bh0 = Kh[krow * PAD + 8 * k + tig];
                uint32_t bh1 = Kh[krow * PAD + 8 * k + tig + 4];
                mma168(S[0][n], Ah[0], bh0, bh1);
                mma168(S[1][n], Ah[1], bh0, bh1);
            }
        }

        // ---- P = exp(S), row sums (fp32) ----
#pragma unroll
        for (int m = 0; m < 2; m++) {
            float s0 = 0.f, s1 = 0.f;
#pragma unroll
            for (int n = 0; n < 8; n++) {
                float p0 = __expf(S[m][n][0]);
                float p1 = __expf(S[m][n][1]);
                float p2 = __expf(S[m][n][2]);
                float p3 = __expf(S[m][n][3]);
                S[m][n][0] = p0; S[m][n][1] = p1;
                S[m][n][2] = p2; S[m][n][3] = p3;
                s0 += p0 + p1; s1 += p2 + p3;
            }
            lsum[m][0] += s0; lsum[m][1] += s1;
        }

        // ---- O += P V, bf16 m16n8k16: D-frag == A-frag, no shuffles ----
#pragma unroll
        for (int kk = 0; kk < 4; kk++) {
            uint32_t Ap[2][4];
#pragma unroll
            for (int m = 0; m < 2; m++) {
                Ap[m][0] = pack_bf16(S[m][2 * kk][0],     S[m][2 * kk][1]);
                Ap[m][1] = pack_bf16(S[m][2 * kk][2],     S[m][2 * kk][3]);
                Ap[m][2] = pack_bf16(S[m][2 * kk + 1][0], S[m][2 * kk + 1][1]);
                Ap[m][3] = pack_bf16(S[m][2 * kk + 1][2], S[m][2 * kk + 1][3]);
            }
#pragma unroll
            for (int c = 0; c < 8; c++) {
                const int row = (8 * c + g) * 36;     // V smem row c, 36 words
                uint32_t b0 = Vs[row + 8 * kk + tig];        // keys 16kk+2tig,+1
                uint32_t b1 = Vs[row + 8 * kk + tig + 4];    // keys 16kk+8+2tig,+1
                mmabf(Oa[0][c], Ap[0], b0, b1);
                mmabf(Oa[1][c], Ap[1], b0, b1);
            }
        }
    }

    // ---- epilogue ----
#pragma unroll
    for (int m = 0; m < 2; m++)
#pragma unroll
        for (int h = 0; h < 2; h++) {
            lsum[m][h] += __shfl_xor_sync(0xffffffffu, lsum[m][h], 1);
            lsum[m][h] += __shfl_xor_sync(0xffffffffu, lsum[m][h], 2);
            lsum[m][h] = 1.f / lsum[m][h];
        }

#pragma unroll
    for (int m = 0; m < 2; m++) {
        const int r0 = n0 + q0 + 16 * m + g;
#pragma unroll
        for (int c = 0; c < 8; c++) {
            float2 v0 = make_float2(Oa[m][c][0] * lsum[m][0], Oa[m][c][1] * lsum[m][0]);
            float2 v1 = make_float2(Oa[m][c][2] * lsum[m][1], Oa[m][c][3] * lsum[m][1]);
            *(float2*)&Og[((size_t)(b * NHW) + r0)     * 64 + 8 * c + 2 * tig] = v0;
            *(float2*)&Og[((size_t)(b * NHW) + r0 + 8) * 64 + 8 * c + 2 * tig] = v1;
        }
    }
}

// ============================================================
// fused theta+phi+g projection; V written bf16 [b][c][n]
// ============================================================
constexpr int QK_WCH = 64 * 68;
constexpr int QK_XCH = 64 * 132;
constexpr int QKV_XOFF = 6 * QK_WCH;
#define QKV_SMEM ((6 * QK_WCH + 2 * QK_XCH) * 4)

__device__ __forceinline__ void qkv_load_chunk(
    uint32_t sb, int s, const float* X, const float* wr,
    int b, int n0, int c0, int tid)
{
#pragma unroll
    for (int j = 0; j < 4; j++) {
        int idx = tid + j * 256;
        int o = idx >> 4, c4 = (idx & 15) << 2;
        uint32_t doff = (uint32_t)(o * 68 + c4) * 4;
        const int soff = o * CC + c0 + c4;
        cp16(sb + (uint32_t)((0 + s) * QK_WCH) * 4 + doff, wr + soff);
        cp16(sb + (uint32_t)((2 + s) * QK_WCH) * 4 + doff, wr + LL * CC + soff);
        cp16(sb + (uint32_t)((4 + s) * QK_WCH) * 4 + doff, wr + 2 * LL * CC + soff);
    }
    const uint32_t xd = sb + (uint32_t)(QKV_XOFF + s * QK_XCH) * 4;
#pragma unroll
    for (int j = 0; j < 8; j++) {
        int idx = tid + j * 256;
        int cl = idx >> 5, n4 = (idx & 31) << 2;
        cp16(xd + (uint32_t)(cl * 132 + n4) * 4,
             X + ((size_t)(b * CC + c0 + cl)) * NHW + n0 + n4);
    }
}

__global__ __launch_bounds__(256) void proj_qkv_kernel(
    const float* __restrict__ X, const float* __restrict__ wr,
    float* __restrict__ oq, float* __restrict__ ok,
    __nv_bfloat16* __restrict__ ov, float gain)
{
    float* smem = (float*)dyn_smem;
    const uint32_t sb = smem_u32(dyn_smem);
    const int tid  = threadIdx.x;
    const int warp = tid >> 5;
    const int lane = tid & 31;
    const int g    = lane >> 2;
    const int tig  = lane & 3;
    const int b  = blockIdx.y;
    const int n0 = blockIdx.x * 128;
    const int m0 = 16 * warp;

    qkv_load_chunk(sb, 0, X, wr, b, n0, 0, tid);
    CP_COMMIT();

    float aq[8][4], ak[8][4], av[8][4];
#pragma unroll
    for (int nc = 0; nc < 8; nc++)
#pragma unroll
        for (int r = 0; r < 4; r++) { aq[nc][r] = 0.f; ak[nc][r] = 0.f; av[nc][r] = 0.f; }

    for (int kc = 0; kc < 8; kc++) {
        __syncthreads();
        if (kc + 1 < 8) qkv_load_chunk(sb, (kc + 1) & 1, X, wr, b, n0, (kc + 1) * 64, tid);
        CP_COMMIT();
        if (kc + 1 < 8) { CP_WAIT(1); } else { CP_WAIT(0); }
        __syncthreads();

        const uint32_t* Wtu = (const uint32_t*)(smem + (0 + (kc & 1)) * QK_WCH);
        const uint32_t* Wpu = (const uint32_t*)(smem + (2 + (kc & 1)) * QK_WCH);
        const uint32_t* Wgu = (const uint32_t*)(smem + (4 + (kc & 1)) * QK_WCH);
        const float* Xc = smem + QKV_XOFF + (kc & 1) * QK_XCH;

#pragma unroll
        for (int kk = 0; kk < 8; kk++) {
            float x0 = Xc[(8 * kk + tig) * 132 + m0 + g];
            float x1 = Xc[(8 * kk + tig) * 132 + m0 + 8 + g];
            float x2 = Xc[(8 * kk + tig + 4) * 132 + m0 + g];
            float x3 = Xc[(8 * kk + tig + 4) * 132 + m0 + 8 + g];
            float h0 = tf32hi(x0), h1 = tf32hi(x1), h2 = tf32hi(x2), h3 = tf32hi(x3);
            uint32_t Ah[4] = {__float_as_uint(h0), __float_as_uint(h1),
                              __float_as_uint(h2), __float_as_uint(h3)};
            uint32_t Al[4] = {__float_as_uint(x0 - h0), __float_as_uint(x1 - h1),
                              __float_as_uint(x2 - h2), __float_as_uint(x3 - h3)};
#pragma unroll
            for (int nc = 0; nc < 8; nc++) {
                const int wrow = (8 * nc + g) * 68 + 8 * kk + tig;
                uint32_t tb0 = Wtu[wrow], tb1 = Wtu[wrow + 4];
                mma168(aq[nc], Ah, tb0, tb1);
                mma168(aq[nc], Al, tb0, tb1);
                uint32_t pb0 = Wpu[wrow], pb1 = Wpu[wrow + 4];
                mma168(ak[nc], Ah, pb0, pb1);
                mma168(ak[nc], Al, pb0, pb1);
                uint32_t gb0 = Wgu[wrow], gb1 = Wgu[wrow + 4];
                mma168(av[nc], Ah, gb0, gb1);
                mma168(av[nc], Al, gb0, gb1);
            }
        }
    }

#pragma unroll
    for (int nc = 0; nc < 8; nc++) {
        const int o = 8 * nc + 2 * tig;
        const size_t r0 = (size_t)(b * NHW + n0 + m0 + g);
        const size_t r1 = r0 + 8;
        *(float2*)&oq[r0 * 64 + o] = make_float2(tf32hi(aq[nc][0] * gain), tf32hi(aq[nc][1] * gain));
        *(float2*)&oq[r1 * 64 + o] = make_float2(tf32hi(aq[nc][2] * gain), tf32hi(aq[nc][3] * gain));
        *(float2*)&ok[r0 * 64 + o] = make_float2(tf32hi(ak[nc][0] * gain), tf32hi(ak[nc][1] * gain));
        *(float2*)&ok[r1 * 64 + o] = make_float2(tf32hi(ak[nc][2] * gain), tf32hi(ak[nc][3] * gain));
        // V bf16 [b][c][n]: c = o/o+1, n = row
        const int nrow0 = n0 + m0 + g;
        ov[((size_t)(b * LL + o))     * NHW + nrow0]     = __float2bfloat16(av[nc][0] * gain);
        ov[((size_t)(b * LL + o + 1)) * NHW + nrow0]     = __float2bfloat16(av[nc][1] * gain);
        ov[((size_t)(b * LL + o))     * NHW + nrow0 + 8] = __float2bfloat16(av[nc][2] * gain);
        ov[((size_t)(b * LL + o + 1)) * NHW + nrow0 + 8] = __float2bfloat16(av[nc][3] * gain);
    }
}

// ============================================================
// mmat (unchanged)
// ============================================================
__global__ __launch_bounds__(256) void mmat_kernel(
    const float* __restrict__ Wt, const float* __restrict__ Wo, float* __restrict__ M)
{
    const int gid = blockIdx.x * 256 + threadIdx.x;
    const int o = gid >> 6, l = gid & 63;
    float acc = 0.f;
    for (int c = 0; c < CC; c++)
        acc += Wt[o * CC + c] * Wo[c * LL + l];
    M[o * LL + l] = GAIN_IN * acc;
}

// ============================================================
// enc via mma (unchanged)
// ============================================================
constexpr int ELPAD = 260;
#define ENC_SMEM ((64 * 68 + 64 * ELPAD) * 4)

__global__ __launch_bounds__(256, 1) void enc_mma_kernel(
    const float* __restrict__ qh, const float* __restrict__ lat,
    const float* __restrict__ M, const float* __restrict__ gamma_sa,
    float* __restrict__ enc)
{
    float* smem = (float*)dyn_smem;
    const uint32_t sb = smem_u32(dyn_smem);
    float* Ls = smem + 64 * 68;

    const int tid  = threadIdx.x;
    const int warp = tid >> 5;
    const int lane = tid & 31;
    const int g    = lane >> 2;
    const int tig  = lane & 3;
    const int b  = blockIdx.y;
    const int n0 = blockIdx.x * 256;
    const int nb = warp * 32;

#pragma unroll
    for (int j = 0; j < 4; j++) {
        int idx = tid + j * 256;
        int o = idx >> 4, c4 = (idx & 15) << 2;
        cp16(sb + (uint32_t)(o * 68 + c4) * 4, M + o * 64 + c4);
    }
#pragma unroll
    for (int j = 0; j < 16; j++) {
        int idx = tid + j * 256;
        int l = idx >> 6, n4 = (idx & 63) << 2;
        cp16(sb + (uint32_t)(64 * 68 + l * ELPAD + n4) * 4,
             lat + (size_t)b * (NHW * 64) + l * NHW + n0 + n4);
    }
    CP_COMMIT();
    CP_WAIT(0);
    __syncthreads();

    float acc[4][4][4];
#pragma unroll
    for (int m = 0; m < 4; m++)
#pragma unroll
        for (int nc = 0; nc < 4; nc++)
#pragma unroll
            for (int r = 0; r < 4; r++) acc[m][nc][r] = 0.f;

    const uint32_t* Mu = (const uint32_t*)smem;
    const uint32_t* Lu = (const uint32_t*)Ls;

#pragma unroll
    for (int kk = 0; kk < 8; kk++) {
        uint32_t A[4][4];
#pragma unroll
        for (int m = 0; m < 4; m++) {
            const int oc = 16 * m;
            A[m][0] = Mu[(oc + g) * 68 + 8 * kk + tig];
            A[m][1] = Mu[(oc + 8 + g) * 68 + 8 * kk + tig];
            A[m][2] = Mu[(oc + g) * 68 + 8 * kk + tig + 4];
            A[m][3] = Mu[(oc + 8 + g) * 68 + 8 * kk + tig + 4];
        }
#pragma unroll
        for (int nc = 0; nc < 4; nc++) {
            const int col = nb + 8 * nc + g;
            uint32_t b0 = Lu[(8 * kk + tig) * ELPAD + col];
            uint32_t b1 = Lu[(8 * kk + tig + 4) * ELPAD + col];
#pragma unroll
            for (int m = 0; m < 4; m++) mma168(acc[m][nc], A[m], b0, b1);
        }
    }

    const float coeff = gamma_sa[0] * GAIN_O;
#pragma unroll
    for (int m = 0; m < 4; m++)
#pragma unroll
        for (int nc = 0; nc < 4; nc++) {
            const int oc = 16 * m + g;
            const int n  = n0 + nb + 8 * nc + 2 * tig;
            const size_t r = ((size_t)(b * NHW) + n) * 64;
            enc[r + oc]           = qh[r + oc]           + coeff * acc[m][nc][0];
            enc[r + 64 + oc]      = qh[r + 64 + oc]      + coeff * acc[m][nc][1];
            enc[r + oc + 8]       = qh[r + oc + 8]       + coeff * acc[m][nc][2];
            enc[r + 64 + oc + 8]  = qh[r + 64 + oc + 8]  + coeff * acc[m][nc][3];
        }
}

// ============================================================
// MoCA via mma.sync (unchanged)
// ============================================================
constexpr int VPAD = 72;
constexpr int MC68_OFF = 0;
constexpr int MC72_OFF = 256 * 68;
constexpr int MES_OFF  = MC72_OFF + 256 * 72;
#define MOCA_SMEM ((MES_OFF + 256 * 68) * 4)

__global__ __launch_bounds__(256, 1) void moca_mma_kernel(
    const float* __restrict__ E, const float* __restrict__ Cpt, float* __restrict__ O)
{
    float* smem = (float*)dyn_smem;
    const uint32_t sb = smem_u32(dyn_smem);
    const int tid  = threadIdx.x;
    const int warp = tid >> 5;
    const int lane = tid & 31;
    const int g    = lane >> 2;
    const int tig  = lane & 3;
    const int b  = blockIdx.y;
    const int n0 = blockIdx.x * 256;

    {
        const size_t er0 = (size_t)(b * NHW + n0);
#pragma unroll
        for (int j = 0; j < 16; j++) {
            int idx = j * 256 + tid;
            int r = idx >> 4, c4 = idx & 15;
            const float* csrc = Cpt + r * 64 + c4 * 4;
            cp16(sb + (uint32_t)(MC68_OFF + r * 68 + c4 * 4) * 4, csrc);
            cp16(sb + (uint32_t)(MC72_OFF + r * 72 + c4 * 4) * 4, csrc);
            cp16(sb + (uint32_t)(MES_OFF + r * 68 + c4 * 4) * 4,
                 E + (er0 + r) * 64 + c4 * 4);
        }
        CP_COMMIT();
        CP_WAIT(0);
        __syncthreads();
    }

    const uint32_t* Cs68 = (const uint32_t*)(smem + MC68_OFF);
    const uint32_t* Cs72 = (const uint32_t*)(smem + MC72_OFF);
    const uint32_t* Es   = (const uint32_t*)(smem + MES_OFF);

    float Oa[2][8][4];
    float lsum[2][2];
#pragma unroll
    for (int m = 0; m < 2; m++) {
        lsum[m][0] = 0.f; lsum[m][1] = 0.f;
#pragma unroll
        for (int c = 0; c < 8; c++)
#pragma unroll
            for (int r = 0; r < 4; r++) Oa[m][c][r] = 0.f;
    }

    const int q0 = warp * 32;

#pragma unroll
    for (int pt = 0; pt < 4; pt++) {
        const int p0 = pt * 64;

        float S[2][8][4];
#pragma unroll
        for (int m = 0; m < 2; m++)
#pragma unroll
            for (int n = 0; n < 8; n++)
#pragma unroll
                for (int r = 0; r < 4; r++) S[m][n][r] = 0.f;

#pragma unroll
        for (int k = 0; k < 8; k++) {
            uint32_t Ah[2][4];
#pragma unroll
            for (int m = 0; m < 2; m++) {
                const int qr = q0 + 16 * m;
                Ah[m][0] = Es[(qr + g) * PAD + 8 * k + tig];
                Ah[m][1] = Es[(qr + 8 + g) * PAD + 8 * k + tig];
                Ah[m][2] = Es[(qr + g) * PAD + 8 * k + tig + 4];
                Ah[m][3] = Es[(qr + 8 + g) * PAD + 8 * k + tig + 4];
            }
#pragma unroll
            for (int n = 0; n < 8; n++) {
                const int prow = p0 + 8 * n + g;
                uint32_t bh0 = Cs68[prow * PAD + 8 * k + tig];
                uint32_t bh1 = Cs68[prow * PAD + 8 * k + tig + 4];
                mma168(S[0][n], Ah[0], bh0, bh1);
                mma168(S[1][n], Ah[1], bh0, bh1);
            }
        }

#pragma unroll
        for (int m = 0; m < 2; m++) {
            float s0 = 0.f, s1 = 0.f;
#pragma unroll
            for (int n = 0; n < 8; n++) {
                float p0f = __expf(S[m][n][0]);
                float p1f = __expf(S[m][n][1]);
                float p2f = __expf(S[m][n][2]);
                float p3f = __expf(S[m][n][3]);
                S[m][n][0] = p0f; S[m][n][1] = p1f;
                S[m][n][2] = p2f; S[m][n][3] = p3f;
                s0 += p0f + p1f; s1 += p2f + p3f;
            }
            lsum[m][0] += s0; lsum[m][1] += s1;
        }

        const int base = lane & ~3;
        const int srcA = base | (tig >> 1);
        const int srcB = srcA + 2;
        const bool odd = (tig & 1);
#pragma unroll
        for (int n = 0; n < 8; n++) {
            uint32_t Ap[2][4];
#pragma unroll
            for (int m = 0; m < 2; m++) {
                float e0  = __shfl_sync(0xffffffffu, S[m][n][0], srcA);
                float e1  = __shfl_sync(0xffffffffu, S[m][n][1], srcA);
                float e2  = __shfl_sync(0xffffffffu, S[m][n][2], srcA);
                float e3  = __shfl_sync(0xffffffffu, S[m][n][3], srcA);
                float f0  = __shfl_sync(0xffffffffu, S[m][n][0], srcB);
                float f1  = __shfl_sync(0xffffffffu, S[m][n][1], srcB);
                float f2  = __shfl_sync(0xffffffffu, S[m][n][2], srcB);
                float f3  = __shfl_sync(0xffffffffu, S[m][n][3], srcB);
                Ap[m][0] = __float_as_uint(odd ? e1 : e0);
                Ap[m][1] = __float_as_uint(odd ? e3 : e2);
                Ap[m][2] = __float_as_uint(odd ? f1 : f0);
                Ap[m][3] = __float_as_uint(odd ? f3 : f2);
            }
#pragma unroll
            for (int c = 0; c < 8; c++) {
                uint32_t b0 = Cs72[(p0 + 8 * n + tig) * VPAD + 8 * c + g];
                uint32_t b1 = Cs72[(p0 + 8 * n + tig + 4) * VPAD + 8 * c + g];
                mma168(Oa[0][c], Ap[0], b0, b1);
                mma168(Oa[1][c], Ap[1], b0, b1);
            }
        }
    }

#pragma unroll
    for (int m = 0; m < 2; m++)
#pragma unroll
        for (int h = 0; h < 2; h++) {
            lsum[m][h] += __shfl_xor_sync(0xffffffffu, lsum[m][h], 1);
            lsum[m][h] += __shfl_xor_sync(0xffffffffu, lsum[m][h], 2);
            lsum[m][h] = 1.f / lsum[m][h];
        }

#pragma unroll
    for (int m = 0; m < 2; m++) {
        const int r0 = n0 + q0 + 16 * m + g;
#pragma unroll
        for (int c = 0; c < 8; c++) {
            float2 v0 = make_float2(Oa[m][c][0] * lsum[m][0], Oa[m][c][1] * lsum[m][0]);
            float2 v1 = make_float2(Oa[m][c][2] * lsum[m][1], Oa[m][c][3] * lsum[m][1]);
            *(float2*)&O[((size_t)(b * NHW) + r0)     * 64 + 8 * c + 2 * tig] = v0;
            *(float2*)&O[((size_t)(b * NHW) + r0 + 8) * 64 + 8 * c + 2 * tig] = v1;
        }
    }
}

// ============================================================
// fused output conv (unchanged)
// ============================================================
#define CONV_SMEM ((512 * 68 + 2 * 64 * 68) * 4)
__global__ __launch_bounds__(256, 1) void conv_fused_kernel(
    const float* __restrict__ lat, const float* __restrict__ lat2,
    const float* __restrict__ Wo, const float* __restrict__ fm,
    const float* __restrict__ gsa, const float* __restrict__ gmoca,
    float* __restrict__ out)
{
    float* smem = (float*)dyn_smem;
    const uint32_t sb = smem_u32(dyn_smem);

    const int tid  = threadIdx.x;
    const int warp = tid >> 5;
    const int lane = tid & 31;
    const int g    = lane >> 2;
    const int tig  = lane & 3;
    const int b  = blockIdx.y;
    const int n0 = blockIdx.x * 64;

#pragma unroll
    for (int j = 0; j < 32; j++) {
        int idx = tid + j * 256;
        int oc = idx >> 4, l4 = (idx & 15) << 2;
        cp16(sb + (uint32_t)(oc * 68 + l4) * 4, Wo + oc * LL + l4);
    }
#pragma unroll
    for (int j = 0; j < 4; j++) {
        int idx = tid + j * 256;
        int cl = idx >> 4, n4 = (idx & 15) << 2;
        const size_t src = (size_t)b * (NHW * 64) + cl * NHW + n0 + n4;
        cp16(sb + (uint32_t)((512 + cl) * 68 + n4) * 4, lat + src);
        cp16(sb + (uint32_t)((576 + cl) * 68 + n4) * 4, lat2 + src);
    }
    CP_COMMIT();
    CP_WAIT(0);
    __syncthreads();

    float acc[4][8][4];
#pragma unroll
    for (int m = 0; m < 4; m++)
#pragma unroll
        for (int nc = 0; nc < 8; nc++)
#pragma unroll
            for (int r = 0; r < 4; r++) acc[m][nc][r] = 0.f;

    const uint32_t* Wu = (const uint32_t*)smem;
    const float* L1 = smem + 512 * 68;
    const float* L2 = smem + 576 * 68;
    const float cs = gsa[0], cm = gmoca[0];

#pragma unroll
    for (int kk = 0; kk < 8; kk++) {
        uint32_t A[4][4];
#pragma unroll
        for (int m = 0; m < 4; m++) {
            const int oc = 64 * warp + 16 * m;
            A[m][0] = Wu[(oc + g) * 68 + 8 * kk + tig];
            A[m][1] = Wu[(oc + 8 + g) * 68 + 8 * kk + tig];
            A[m][2] = Wu[(oc + g) * 68 + 8 * kk + tig + 4];
            A[m][3] = Wu[(oc + 8 + g) * 68 + 8 * kk + tig + 4];
        }
#pragma unroll
        for (int nc = 0; nc < 8; nc++) {
            const int i0 = (8 * kk + tig) * 68 + 8 * nc + g;
            const int i1 = (8 * kk + tig + 4) * 68 + 8 * nc + g;
            uint32_t b0 = __float_as_uint(cs * L1[i0] + cm * L2[i0]);
            uint32_t b1 = __float_as_uint(cs * L1[i1] + cm * L2[i1]);
#pragma unroll
            for (int m = 0; m < 4; m++) mma168(acc[m][nc], A[m], b0, b1);
        }
    }

#pragma unroll
    for (int m = 0; m < 4; m++)
#pragma unroll
        for (int nc = 0; nc < 8; nc++) {
            const int oc = 64 * warp + 16 * m + g;
            const int n  = n0 + 8 * nc + 2 * tig;
            const size_t base0 = ((size_t)(b * CC + oc)) * NHW + n;
            const size_t base1 = base0 + (size_t)8 * NHW;
            float2 a0 = *(const float2*)&fm[base0];
            float2 a1 = *(const float2*)&fm[base1];
            *(float2*)&out[base0] = make_float2(GAIN_O * acc[m][nc][0] + a0.x,
                                                GAIN_O * acc[m][nc][1] + a0.y);
            *(float2*)&out[base1] = make_float2(GAIN_O * acc[m][nc][2] + a1.x,
                                                GAIN_O * acc[m][nc][3] + a1.y);
        }
}

// ============================================================
extern "C" void kernel_launch(void* const* d_in, const int* in_sizes, int n_in,
                              void* d_out, int out_size)
{
    (void)in_sizes; (void)n_in; (void)out_size;
    const float* fm         = (const float*)d_in[0];
    const float* concepts   = (const float*)d_in[1];
    const float* w_theta    = (const float*)d_in[2];
    const float* w_phi      = (const float*)d_in[3];
    const float* w_g        = (const float*)d_in[4];
    const float* w_o        = (const float*)d_in[5];
    const float* gamma_sa   = (const float*)d_in[6];
    const float* gamma_moca = (const float*)d_in[7];
    float* out = (float*)d_out;

    float *qh, *kh, *lat, *enc, *lat2, *Mb, *wr;
    __nv_bfloat16* vb;
    cudaGetSymbolAddress((void**)&qh,  g_qh);
    cudaGetSymbolAddress((void**)&kh,  g_kh);
    cudaGetSymbolAddress((void**)&vb,  g_vb);
    cudaGetSymbolAddress((void**)&lat, g_lat);
    cudaGetSymbolAddress((void**)&enc, g_enc);
    cudaGetSymbolAddress((void**)&lat2, g_lat2);
    cudaGetSymbolAddress((void**)&Mb,  g_M);
    cudaGetSymbolAddress((void**)&wr,  g_wr);

    cudaFuncSetAttribute(flash_mma_kernel, cudaFuncAttributeMaxDynamicSharedMemorySize, FT_SMEM);
    cudaFuncSetAttribute(proj_qkv_kernel,  cudaFuncAttributeMaxDynamicSharedMemorySize, QKV_SMEM);
    cudaFuncSetAttribute(enc_mma_kernel,   cudaFuncAttributeMaxDynamicSharedMemorySize, ENC_SMEM);
    cudaFuncSetAttribute(conv_fused_kernel, cudaFuncAttributeMaxDynamicSharedMemorySize, CONV_SMEM);
    cudaFuncSetAttribute(moca_mma_kernel,  cudaFuncAttributeMaxDynamicSharedMemorySize, MOCA_SMEM);

    wround_kernel<<<128, 256>>>(w_theta, w_phi, w_g, wr);
    mmat_kernel<<<16, 256>>>(w_theta, w_o, Mb);
    proj_qkv_kernel<<<dim3(32, 8), 256, QKV_SMEM>>>(fm, wr, qh, kh, vb, GAIN_IN);
    flash_mma_kernel<<<dim3(32, 8), 128, FT_SMEM>>>(qh, kh, vb, lat);
    enc_mma_kernel<<<dim3(16, 8), 256, ENC_SMEM>>>(qh, lat, Mb, gamma_sa, enc);
    moca_mma_kernel<<<dim3(16, 8), 256, MOCA_SMEM>>>(enc, concepts, lat2);
    conv_fused_kernel<<<dim3(64, 8), 256, CONV_SMEM>>>(lat, lat2, w_o, fm, gamma_sa, gamma_moca, out);
}

// round 16
// speedup vs baseline: 3.0233x; 1.1727x over previous
#include <cuda_runtime.h>
#include <cuda_bf16.h>
#include <cstdint>

constexpr int BB  = 8;
constexpr int CC  = 512;
constexpr int LL  = 64;
constexpr int NHW = 4096;

#define GAIN_IN 0.04419417382415922f
#define GAIN_O  0.125f

// -------- device scratch --------
__device__ float g_qh [BB * NHW * LL];            // raw fp32 q (enc residual)
__device__ __nv_bfloat16 g_qb [BB * NHW * LL];    // q bf16 [b][n][c]
__device__ __nv_bfloat16 g_kb [BB * NHW * LL];    // k bf16 [b][n][c]
__device__ __nv_bfloat16 g_vb [BB * LL * NHW];    // v bf16 [b][c][n]
__device__ float g_lat[BB * NHW * LL];
__device__ float g_enc[BB * NHW * LL];
__device__ float g_lat2[BB * NHW * LL];
__device__ float g_M  [LL * LL];
__device__ float g_wr [3 * LL * CC];

extern __shared__ char dyn_smem[];

// ============================================================
// helpers
// ============================================================
__device__ __forceinline__ uint32_t smem_u32(const void* p) {
    uint32_t r;
    asm("{ .reg .u64 t; cvta.to.shared.u64 t, %1; cvt.u32.u64 %0, t; }" : "=r"(r) : "l"(p));
    return r;
}
__device__ __forceinline__ void cp16(uint32_t dst, const void* src) {
    asm volatile("cp.async.cg.shared.global [%0], [%1], 16;" :: "r"(dst), "l"(src));
}
#define CP_COMMIT() asm volatile("cp.async.commit_group;" ::: "memory")
#define CP_WAIT(n)  asm volatile("cp.async.wait_group %0;" :: "n"(n) : "memory")

__device__ __forceinline__ float tf32hi(float v) {
    float h;
    asm("cvt.rna.tf32.f32 %0, %1;" : "=f"(h) : "f"(v));
    return h;
}
__device__ __forceinline__ uint32_t pack_bf16(float lo, float hi) {
    uint32_t r;
    asm("cvt.rn.bf16x2.f32 %0, %1, %2;" : "=r"(r) : "f"(hi), "f"(lo));
    return r;
}
__device__ __forceinline__ void mma168(float* d, const uint32_t* a, uint32_t b0, uint32_t b1) {
    asm volatile(
        "mma.sync.aligned.m16n8k8.row.col.f32.tf32.tf32.f32 "
        "{%0,%1,%2,%3}, {%4,%5,%6,%7}, {%8,%9}, {%0,%1,%2,%3};"
        : "+f"(d[0]), "+f"(d[1]), "+f"(d[2]), "+f"(d[3])
        : "r"(a[0]), "r"(a[1]), "r"(a[2]), "r"(a[3]), "r"(b0), "r"(b1));
}
__device__ __forceinline__ void mmabf(float* d, const uint32_t* a, uint32_t b0, uint32_t b1) {
    asm volatile(
        "mma.sync.aligned.m16n8k16.row.col.f32.bf16.bf16.f32 "
        "{%0,%1,%2,%3}, {%4,%5,%6,%7}, {%8,%9}, {%0,%1,%2,%3};"
        : "+f"(d[0]), "+f"(d[1]), "+f"(d[2]), "+f"(d[3])
        : "r"(a[0]), "r"(a[1]), "r"(a[2]), "r"(a[3]), "r"(b0), "r"(b1));
}

// ============================================================
// w_round (unchanged)
// ============================================================
__global__ __launch_bounds__(256) void wround_kernel(
    const float* __restrict__ Wt, const float* __restrict__ Wp,
    const float* __restrict__ Wg, float* __restrict__ wr)
{
    const int i = blockIdx.x * 256 + threadIdx.x;
    wr[i]                = tf32hi(Wt[i]);
    wr[LL * CC + i]      = tf32hi(Wp[i]);
    wr[2 * LL * CC + i]  = tf32hi(Wg[i]);
}

// ============================================================
// flash v9: full bf16 (S and PV, m16n8k16). Q/K/V bf16, 72-elem rows.
// 128 thr / 4 warps / 128 q rows, 2 CTAs/SM, K/V double-buffered.
// ============================================================
constexpr uint32_t FROW_B    = 144;                      // 72 bf16 per row
constexpr uint32_t OFF_Q_B   = 0;                        // 128 rows
constexpr uint32_t OFF_K_B   = 128 * FROW_B;             // 18432
constexpr uint32_t KSLOT_B   = 64 * FROW_B;              // 9216
constexpr uint32_t OFF_V_B   = OFF_K_B + 2 * KSLOT_B;    // 36864
constexpr uint32_t VSLOT_B   = 64 * FROW_B;              // 9216
#define FT_SMEM (OFF_V_B + 2 * VSLOT_B)                  // 55296 bytes

__device__ __forceinline__ void loadQb(uint32_t dst, const __nv_bfloat16* Qb,
                                       int b, int n0, int tid) {
    const size_t row0 = (size_t)(b * NHW + n0);
#pragma unroll
    for (int j = 0; j < 8; j++) {
        int idx = j * 128 + tid;           // 0..1023 -> 128 rows x 8 segs
        int r = idx >> 3, seg = idx & 7;
        cp16(dst + (uint32_t)(r * FROW_B + seg * 16), Qb + (row0 + r) * 64 + seg * 8);
    }
}
__device__ __forceinline__ void loadKb(uint32_t dst, const __nv_bfloat16* Kb,
                                       int b, int m0, int tid) {
    const size_t row0 = (size_t)(b * NHW + m0);
#pragma unroll
    for (int j = 0; j < 4; j++) {
        int idx = j * 128 + tid;           // 0..511 -> 64 rows x 8 segs
        int r = idx >> 3, seg = idx & 7;
        cp16(dst + (uint32_t)(r * FROW_B + seg * 16), Kb + (row0 + r) * 64 + seg * 8);
    }
}
__device__ __forceinline__ void loadVb(uint32_t dst, const __nv_bfloat16* Vb,
                                       int b, int m0, int tid) {
#pragma unroll
    for (int j = 0; j < 4; j++) {
        int idx = j * 128 + tid;
        int r = idx >> 3, seg = idx & 7;
        cp16(dst + (uint32_t)(r * FROW_B + seg * 16),
             Vb + ((size_t)(b * LL + r)) * NHW + m0 + seg * 8);
    }
}

__global__ __launch_bounds__(128, 2) void flash_mma_kernel(
    const __nv_bfloat16* __restrict__ Qb, const __nv_bfloat16* __restrict__ Kb,
    const __nv_bfloat16* __restrict__ Vb, float* __restrict__ Og)
{
    const uint32_t sb = smem_u32(dyn_smem);
    const int tid  = threadIdx.x;
    const int warp = tid >> 5;
    const int lane = tid & 31;
    const int g    = lane >> 2;
    const int tig  = lane & 3;
    const int b  = blockIdx.y;
    const int n0 = blockIdx.x * 128;
    const int NT = 64;

    {
        loadQb(sb + OFF_Q_B, Qb, b, n0, tid);
        loadKb(sb + OFF_K_B, Kb, b, 0, tid);
        loadVb(sb + OFF_V_B, Vb, b, 0, tid);
        CP_COMMIT();
    }

    const uint32_t* Qw = (const uint32_t*)(dyn_smem + OFF_Q_B);

    float Oa[2][8][4];
    float lsum[2][2];
#pragma unroll
    for (int m = 0; m < 2; m++) {
        lsum[m][0] = 0.f; lsum[m][1] = 0.f;
#pragma unroll
        for (int c = 0; c < 8; c++)
#pragma unroll
            for (int r = 0; r < 4; r++) Oa[m][c][r] = 0.f;
    }

    const int q0 = warp * 32;

    for (int i = 0; i < NT; i++) {
        if (i + 1 < NT) {
            const int s = (i + 1) & 1;
            loadKb(sb + OFF_K_B + (uint32_t)s * KSLOT_B, Kb, b, (i + 1) * 64, tid);
            loadVb(sb + OFF_V_B + (uint32_t)s * VSLOT_B, Vb, b, (i + 1) * 64, tid);
        }
        CP_COMMIT();
        CP_WAIT(1);
        __syncthreads();

        const int sc = i & 1;
        const uint32_t* Kw = (const uint32_t*)(dyn_smem + OFF_K_B + sc * KSLOT_B);
        const uint32_t* Vs = (const uint32_t*)(dyn_smem + OFF_V_B + sc * VSLOT_B);

        // ---- S = Q K^T, bf16 m16n8k16, 4 k-chunks ----
        float S[2][8][4];
#pragma unroll
        for (int m = 0; m < 2; m++)
#pragma unroll
            for (int n = 0; n < 8; n++)
#pragma unroll
                for (int r = 0; r < 4; r++) S[m][n][r] = 0.f;

#pragma unroll
        for (int k = 0; k < 4; k++) {
            uint32_t Ah[2][4];
#pragma unroll
            for (int m = 0; m < 2; m++) {
                const int qr = q0 + 16 * m;
                Ah[m][0] = Qw[(qr + g) * 36 + 8 * k + tig];
                Ah[m][1] = Qw[(qr + 8 + g) * 36 + 8 * k + tig];
                Ah[m][2] = Qw[(qr + g) * 36 + 8 * k + tig + 4];
                Ah[m][3] = Qw[(qr + 8 + g) * 36 + 8 * k + tig + 4];
            }
#pragma unroll
            for (int n = 0; n < 8; n++) {
                const int krow = 8 * n + g;
                uint32_t b0 = Kw[krow * 36 + 8 * k + tig];
                uint32_t b1 = Kw[krow * 36 + 8 * k + tig + 4];
                mmabf(S[0][n], Ah[0], b0, b1);
                mmabf(S[1][n], Ah[1], b0, b1);
            }
        }

        // ---- P = exp(S), row sums (fp32) ----
#pragma unroll
        for (int m = 0; m < 2; m++) {
            float s0 = 0.f, s1 = 0.f;
#pragma unroll
            for (int n = 0; n < 8; n++) {
                float p0 = __expf(S[m][n][0]);
                float p1 = __expf(S[m][n][1]);
                float p2 = __expf(S[m][n][2]);
                float p3 = __expf(S[m][n][3]);
                S[m][n][0] = p0; S[m][n][1] = p1;
                S[m][n][2] = p2; S[m][n][3] = p3;
                s0 += p0 + p1; s1 += p2 + p3;
            }
            lsum[m][0] += s0; lsum[m][1] += s1;
        }

        // ---- O += P V, bf16 m16n8k16 (D-frag == A-frag) ----
#pragma unroll
        for (int kk = 0; kk < 4; kk++) {
            uint32_t Ap[2][4];
#pragma unroll
            for (int m = 0; m < 2; m++) {
                Ap[m][0] = pack_bf16(S[m][2 * kk][0],     S[m][2 * kk][1]);
                Ap[m][1] = pack_bf16(S[m][2 * kk][2],     S[m][2 * kk][3]);
                Ap[m][2] = pack_bf16(S[m][2 * kk + 1][0], S[m][2 * kk + 1][1]);
                Ap[m][3] = pack_bf16(S[m][2 * kk + 1][2], S[m][2 * kk + 1][3]);
            }
#pragma unroll
            for (int c = 0; c < 8; c++) {
                const int row = (8 * c + g) * 36;
                uint32_t b0 = Vs[row + 8 * kk + tig];
                uint32_t b1 = Vs[row + 8 * kk + tig + 4];
                mmabf(Oa[0][c], Ap[0], b0, b1);
                mmabf(Oa[1][c], Ap[1], b0, b1);
            }
        }
    }

    // ---- epilogue ----
#pragma unroll
    for (int m = 0; m < 2; m++)
#pragma unroll
        for (int h = 0; h < 2; h++) {
            lsum[m][h] += __shfl_xor_sync(0xffffffffu, lsum[m][h], 1);
            lsum[m][h] += __shfl_xor_sync(0xffffffffu, lsum[m][h], 2);
            lsum[m][h] = 1.f / lsum[m][h];
        }

#pragma unroll
    for (int m = 0; m < 2; m++) {
        const int r0 = n0 + q0 + 16 * m + g;
#pragma unroll
        for (int c = 0; c < 8; c++) {
            float2 v0 = make_float2(Oa[m][c][0] * lsum[m][0], Oa[m][c][1] * lsum[m][0]);
            float2 v1 = make_float2(Oa[m][c][2] * lsum[m][1], Oa[m][c][3] * lsum[m][1]);
            *(float2*)&Og[((size_t)(b * NHW) + r0)     * 64 + 8 * c + 2 * tig] = v0;
            *(float2*)&Og[((size_t)(b * NHW) + r0 + 8) * 64 + 8 * c + 2 * tig] = v1;
        }
    }
}

// ============================================================
// fused theta+phi+g projection; outputs:
//   qh fp32 [b][n][c] (enc residual), qb/kb bf16 [b][n][c], vb bf16 [b][c][n]
// ============================================================
constexpr int QK_WCH = 64 * 68;
constexpr int QK_XCH = 64 * 132;
constexpr int QKV_XOFF = 6 * QK_WCH;
#define QKV_SMEM ((6 * QK_WCH + 2 * QK_XCH) * 4)

__device__ __forceinline__ void qkv_load_chunk(
    uint32_t sb, int s, const float* X, const float* wr,
    int b, int n0, int c0, int tid)
{
#pragma unroll
    for (int j = 0; j < 4; j++) {
        int idx = tid + j * 256;
        int o = idx >> 4, c4 = (idx & 15) << 2;
        uint32_t doff = (uint32_t)(o * 68 + c4) * 4;
        const int soff = o * CC + c0 + c4;
        cp16(sb + (uint32_t)((0 + s) * QK_WCH) * 4 + doff, wr + soff);
        cp16(sb + (uint32_t)((2 + s) * QK_WCH) * 4 + doff, wr + LL * CC + soff);
        cp16(sb + (uint32_t)((4 + s) * QK_WCH) * 4 + doff, wr + 2 * LL * CC + soff);
    }
    const uint32_t xd = sb + (uint32_t)(QKV_XOFF + s * QK_XCH) * 4;
#pragma unroll
    for (int j = 0; j < 8; j++) {
        int idx = tid + j * 256;
        int cl = idx >> 5, n4 = (idx & 31) << 2;
        cp16(xd + (uint32_t)(cl * 132 + n4) * 4,
             X + ((size_t)(b * CC + c0 + cl)) * NHW + n0 + n4);
    }
}

__global__ __launch_bounds__(256) void proj_qkv_kernel(
    const float* __restrict__ X, const float* __restrict__ wr,
    float* __restrict__ oqh, __nv_bfloat16* __restrict__ oqb,
    __nv_bfloat16* __restrict__ okb, __nv_bfloat16* __restrict__ ov, float gain)
{
    float* smem = (float*)dyn_smem;
    const uint32_t sb = smem_u32(dyn_smem);
    const int tid  = threadIdx.x;
    const int warp = tid >> 5;
    const int lane = tid & 31;
    const int g    = lane >> 2;
    const int tig  = lane & 3;
    const int b  = blockIdx.y;
    const int n0 = blockIdx.x * 128;
    const int m0 = 16 * warp;

    qkv_load_chunk(sb, 0, X, wr, b, n0, 0, tid);
    CP_COMMIT();

    float aq[8][4], ak[8][4], av[8][4];
#pragma unroll
    for (int nc = 0; nc < 8; nc++)
#pragma unroll
        for (int r = 0; r < 4; r++) { aq[nc][r] = 0.f; ak[nc][r] = 0.f; av[nc][r] = 0.f; }

    for (int kc = 0; kc < 8; kc++) {
        __syncthreads();
        if (kc + 1 < 8) qkv_load_chunk(sb, (kc + 1) & 1, X, wr, b, n0, (kc + 1) * 64, tid);
        CP_COMMIT();
        if (kc + 1 < 8) { CP_WAIT(1); } else { CP_WAIT(0); }
        __syncthreads();

        const uint32_t* Wtu = (const uint32_t*)(smem + (0 + (kc & 1)) * QK_WCH);
        const uint32_t* Wpu = (const uint32_t*)(smem + (2 + (kc & 1)) * QK_WCH);
        const uint32_t* Wgu = (const uint32_t*)(smem + (4 + (kc & 1)) * QK_WCH);
        const float* Xc = smem + QKV_XOFF + (kc & 1) * QK_XCH;

#pragma unroll
        for (int kk = 0; kk < 8; kk++) {
            float x0 = Xc[(8 * kk + tig) * 132 + m0 + g];
            float x1 = Xc[(8 * kk + tig) * 132 + m0 + 8 + g];
            float x2 = Xc[(8 * kk + tig + 4) * 132 + m0 + g];
            float x3 = Xc[(8 * kk + tig + 4) * 132 + m0 + 8 + g];
            float h0 = tf32hi(x0), h1 = tf32hi(x1), h2 = tf32hi(x2), h3 = tf32hi(x3);
            uint32_t Ah[4] = {__float_as_uint(h0), __float_as_uint(h1),
                              __float_as_uint(h2), __float_as_uint(h3)};
            uint32_t Al[4] = {__float_as_uint(x0 - h0), __float_as_uint(x1 - h1),
                              __float_as_uint(x2 - h2), __float_as_uint(x3 - h3)};
#pragma unroll
            for (int nc = 0; nc < 8; nc++) {
                const int wrow = (8 * nc + g) * 68 + 8 * kk + tig;
                uint32_t tb0 = Wtu[wrow], tb1 = Wtu[wrow + 4];
                mma168(aq[nc], Ah, tb0, tb1);
                mma168(aq[nc], Al, tb0, tb1);
                uint32_t pb0 = Wpu[wrow], pb1 = Wpu[wrow + 4];
                mma168(ak[nc], Ah, pb0, pb1);
                mma168(ak[nc], Al, pb0, pb1);
                uint32_t gb0 = Wgu[wrow], gb1 = Wgu[wrow + 4];
                mma168(av[nc], Ah, gb0, gb1);
                mma168(av[nc], Al, gb0, gb1);
            }
        }
    }

#pragma unroll
    for (int nc = 0; nc < 8; nc++) {
        const int o = 8 * nc + 2 * tig;
        const size_t r0 = (size_t)(b * NHW + n0 + m0 + g);
        const size_t r1 = r0 + 8;
        float q0 = aq[nc][0] * gain, q1 = aq[nc][1] * gain;
        float q2 = aq[nc][2] * gain, q3 = aq[nc][3] * gain;
        float k0 = ak[nc][0] * gain, k1 = ak[nc][1] * gain;
        float k2 = ak[nc][2] * gain, k3 = ak[nc][3] * gain;
        // fp32 q for enc residual
        *(float2*)&oqh[r0 * 64 + o] = make_float2(q0, q1);
        *(float2*)&oqh[r1 * 64 + o] = make_float2(q2, q3);
        // bf16 q, k for flash
        *(uint32_t*)&oqb[r0 * 64 + o] = pack_bf16(q0, q1);
        *(uint32_t*)&oqb[r1 * 64 + o] = pack_bf16(q2, q3);
        *(uint32_t*)&okb[r0 * 64 + o] = pack_bf16(k0, k1);
        *(uint32_t*)&okb[r1 * 64 + o] = pack_bf16(k2, k3);
        // V bf16 [b][c][n]
        const int nrow0 = n0 + m0 + g;
        ov[((size_t)(b * LL + o))     * NHW + nrow0]     = __float2bfloat16(av[nc][0] * gain);
        ov[((size_t)(b * LL + o + 1)) * NHW + nrow0]     = __float2bfloat16(av[nc][1] * gain);
        ov[((size_t)(b * LL + o))     * NHW + nrow0 + 8] = __float2bfloat16(av[nc][2] * gain);
        ov[((size_t)(b * LL + o + 1)) * NHW + nrow0 + 8] = __float2bfloat16(av[nc][3] * gain);
    }
}

// ============================================================
// mmat (unchanged)
// ============================================================
__global__ __launch_bounds__(256) void mmat_kernel(
    const float* __restrict__ Wt, const float* __restrict__ Wo, float* __restrict__ M)
{
    const int gid = blockIdx.x * 256 + threadIdx.x;
    const int o = gid >> 6, l = gid & 63;
    float acc = 0.f;
    for (int c = 0; c < CC; c++)
        acc += Wt[o * CC + c] * Wo[c * LL + l];
    M[o * LL + l] = GAIN_IN * acc;
}

// ============================================================
// enc via mma (unchanged)
// ============================================================
constexpr int ELPAD = 260;
#define ENC_SMEM ((64 * 68 + 64 * ELPAD) * 4)

__global__ __launch_bounds__(256, 1) void enc_mma_kernel(
    const float* __restrict__ qh, const float* __restrict__ lat,
    const float* __restrict__ M, const float* __restrict__ gamma_sa,
    float* __restrict__ enc)
{
    float* smem = (float*)dyn_smem;
    const uint32_t sb = smem_u32(dyn_smem);
    float* Ls = smem + 64 * 68;

    const int tid  = threadIdx.x;
    const int warp = tid >> 5;
    const int lane = tid & 31;
    const int g    = lane >> 2;
    const int tig  = lane & 3;
    const int b  = blockIdx.y;
    const int n0 = blockIdx.x * 256;
    const int nb = warp * 32;

#pragma unroll
    for (int j = 0; j < 4; j++) {
        int idx = tid + j * 256;
        int o = idx >> 4, c4 = (idx & 15) << 2;
        cp16(sb + (uint32_t)(o * 68 + c4) * 4, M + o * 64 + c4);
    }
#pragma unroll
    for (int j = 0; j < 16; j++) {
        int idx = tid + j * 256;
        int l = idx >> 6, n4 = (idx & 63) << 2;
        cp16(sb + (uint32_t)(64 * 68 + l * ELPAD + n4) * 4,
             lat + (size_t)b * (NHW * 64) + l * NHW + n0 + n4);
    }
    CP_COMMIT();
    CP_WAIT(0);
    __syncthreads();

    float acc[4][4][4];
#pragma unroll
    for (int m = 0; m < 4; m++)
#pragma unroll
        for (int nc = 0; nc < 4; nc++)
#pragma unroll
            for (int r = 0; r < 4; r++) acc[m][nc][r] = 0.f;

    const uint32_t* Mu = (const uint32_t*)smem;
    const uint32_t* Lu = (const uint32_t*)Ls;

#pragma unroll
    for (int kk = 0; kk < 8; kk++) {
        uint32_t A[4][4];
#pragma unroll
        for (int m = 0; m < 4; m++) {
            const int oc = 16 * m;
            A[m][0] = Mu[(oc + g) * 68 + 8 * kk + tig];
            A[m][1] = Mu[(oc + 8 + g) * 68 + 8 * kk + tig];
            A[m][2] = Mu[(oc + g) * 68 + 8 * kk + tig + 4];
            A[m][3] = Mu[(oc + 8 + g) * 68 + 8 * kk + tig + 4];
        }
#pragma unroll
        for (int nc = 0; nc < 4; nc++) {
            const int col = nb + 8 * nc + g;
            uint32_t b0 = Lu[(8 * kk + tig) * ELPAD + col];
            uint32_t b1 = Lu[(8 * kk + tig + 4) * ELPAD + col];
#pragma unroll
            for (int m = 0; m < 4; m++) mma168(acc[m][nc], A[m], b0, b1);
        }
    }

    const float coeff = gamma_sa[0] * GAIN_O;
#pragma unroll
    for (int m = 0; m < 4; m++)
#pragma unroll
        for (int nc = 0; nc < 4; nc++) {
            const int oc = 16 * m + g;
            const int n  = n0 + nb + 8 * nc + 2 * tig;
            const size_t r = ((size_t)(b * NHW) + n) * 64;
            enc[r + oc]           = qh[r + oc]           + coeff * acc[m][nc][0];
            enc[r + 64 + oc]      = qh[r + 64 + oc]      + coeff * acc[m][nc][1];
            enc[r + oc + 8]       = qh[r + oc + 8]       + coeff * acc[m][nc][2];
            enc[r + 64 + oc + 8]  = qh[r + 64 + oc + 8]  + coeff * acc[m][nc][3];
        }
}

// ============================================================
// MoCA via mma.sync (unchanged)
// ============================================================
constexpr int PAD  = 68;
constexpr int VPAD = 72;
constexpr int MC68_OFF = 0;
constexpr int MC72_OFF = 256 * 68;
constexpr int MES_OFF  = MC72_OFF + 256 * 72;
#define MOCA_SMEM ((MES_OFF + 256 * 68) * 4)

__global__ __launch_bounds__(256, 1) void moca_mma_kernel(
    const float* __restrict__ E, const float* __restrict__ Cpt, float* __restrict__ O)
{
    float* smem = (float*)dyn_smem;
    const uint32_t sb = smem_u32(dyn_smem);
    const int tid  = threadIdx.x;
    const int warp = tid >> 5;
    const int lane = tid & 31;
    const int g    = lane >> 2;
    const int tig  = lane & 3;
    const int b  = blockIdx.y;
    const int n0 = blockIdx.x * 256;

    {
        const size_t er0 = (size_t)(b * NHW + n0);
#pragma unroll
        for (int j = 0; j < 16; j++) {
            int idx = j * 256 + tid;
            int r = idx >> 4, c4 = idx & 15;
            const float* csrc = Cpt + r * 64 + c4 * 4;
            cp16(sb + (uint32_t)(MC68_OFF + r * 68 + c4 * 4) * 4, csrc);
            cp16(sb + (uint32_t)(MC72_OFF + r * 72 + c4 * 4) * 4, csrc);
            cp16(sb + (uint32_t)(MES_OFF + r * 68 + c4 * 4) * 4,
                 E + (er0 + r) * 64 + c4 * 4);
        }
        CP_COMMIT();
        CP_WAIT(0);
        __syncthreads();
    }

    const uint32_t* Cs68 = (const uint32_t*)(smem + MC68_OFF);
    const uint32_t* Cs72 = (const uint32_t*)(smem + MC72_OFF);
    const uint32_t* Es   = (const uint32_t*)(smem + MES_OFF);

    float Oa[2][8][4];
    float lsum[2][2];
#pragma unroll
    for (int m = 0; m < 2; m++) {
        lsum[m][0] = 0.f; lsum[m][1] = 0.f;
#pragma unroll
        for (int c = 0; c < 8; c++)
#pragma unroll
            for (int r = 0; r < 4; r++) Oa[m][c][r] = 0.f;
    }

    const int q0 = warp * 32;

#pragma unroll
    for (int pt = 0; pt < 4; pt++) {
        const int p0 = pt * 64;

        float S[2][8][4];
#pragma unroll
        for (int m = 0; m < 2; m++)
#pragma unroll
            for (int n = 0; n < 8; n++)
#pragma unroll
                for (int r = 0; r < 4; r++) S[m][n][r] = 0.f;

#pragma unroll
        for (int k = 0; k < 8; k++) {
            uint32_t Ah[2][4];
#pragma unroll
            for (int m = 0; m < 2; m++) {
                const int qr = q0 + 16 * m;
                Ah[m][0] = Es[(qr + g) * PAD + 8 * k + tig];
                Ah[m][1] = Es[(qr + 8 + g) * PAD + 8 * k + tig];
                Ah[m][2] = Es[(qr + g) * PAD + 8 * k + tig + 4];
                Ah[m][3] = Es[(qr + 8 + g) * PAD + 8 * k + tig + 4];
            }
#pragma unroll
            for (int n = 0; n < 8; n++) {
                const int prow = p0 + 8 * n + g;
                uint32_t bh0 = Cs68[prow * PAD + 8 * k + tig];
                uint32_t bh1 = Cs68[prow * PAD + 8 * k + tig + 4];
                mma168(S[0][n], Ah[0], bh0, bh1);
                mma168(S[1][n], Ah[1], bh0, bh1);
            }
        }

#pragma unroll
        for (int m = 0; m < 2; m++) {
            float s0 = 0.f, s1 = 0.f;
#pragma unroll
            for (int n = 0; n < 8; n++) {
                float p0f = __expf(S[m][n][0]);
                float p1f = __expf(S[m][n][1]);
                float p2f = __expf(S[m][n][2]);
                float p3f = __expf(S[m][n][3]);
                S[m][n][0] = p0f; S[m][n][1] = p1f;
                S[m][n][2] = p2f; S[m][n][3] = p3f;
                s0 += p0f + p1f; s1 += p2f + p3f;
            }
            lsum[m][0] += s0; lsum[m][1] += s1;
        }

        const int base = lane & ~3;
        const int srcA = base | (tig >> 1);
        const int srcB = srcA + 2;
        const bool odd = (tig & 1);
#pragma unroll
        for (int n = 0; n < 8; n++) {
            uint32_t Ap[2][4];
#pragma unroll
            for (int m = 0; m < 2; m++) {
                float e0  = __shfl_sync(0xffffffffu, S[m][n][0], srcA);
                float e1  = __shfl_sync(0xffffffffu, S[m][n][1], srcA);
                float e2  = __shfl_sync(0xffffffffu, S[m][n][2], srcA);
                float e3  = __shfl_sync(0xffffffffu, S[m][n][3], srcA);
                float f0  = __shfl_sync(0xffffffffu, S[m][n][0], srcB);
                float f1  = __shfl_sync(0xffffffffu, S[m][n][1], srcB);
                float f2  = __shfl_sync(0xffffffffu, S[m][n][2], srcB);
                float f3  = __shfl_sync(0xffffffffu, S[m][n][3], srcB);
                Ap[m][0] = __float_as_uint(odd ? e1 : e0);
                Ap[m][1] = __float_as_uint(odd ? e3 : e2);
                Ap[m][2] = __float_as_uint(odd ? f1 : f0);
                Ap[m][3] = __float_as_uint(odd ? f3 : f2);
            }
#pragma unroll
            for (int c = 0; c < 8; c++) {
                uint32_t b0 = Cs72[(p0 + 8 * n + tig) * VPAD + 8 * c + g];
                uint32_t b1 = Cs72[(p0 + 8 * n + tig + 4) * VPAD + 8 * c + g];
                mma168(Oa[0][c], Ap[0], b0, b1);
                mma168(Oa[1][c], Ap[1], b0, b1);
            }
        }
    }

#pragma unroll
    for (int m = 0; m < 2; m++)
#pragma unroll
        for (int h = 0; h < 2; h++) {
            lsum[m][h] += __shfl_xor_sync(0xffffffffu, lsum[m][h], 1);
            lsum[m][h] += __shfl_xor_sync(0xffffffffu, lsum[m][h], 2);
            lsum[m][h] = 1.f / lsum[m][h];
        }

#pragma unroll
    for (int m = 0; m < 2; m++) {
        const int r0 = n0 + q0 + 16 * m + g;
#pragma unroll
        for (int c = 0; c < 8; c++) {
            float2 v0 = make_float2(Oa[m][c][0] * lsum[m][0], Oa[m][c][1] * lsum[m][0]);
            float2 v1 = make_float2(Oa[m][c][2] * lsum[m][1], Oa[m][c][3] * lsum[m][1]);
            *(float2*)&O[((size_t)(b * NHW) + r0)     * 64 + 8 * c + 2 * tig] = v0;
            *(float2*)&O[((size_t)(b * NHW) + r0 + 8) * 64 + 8 * c + 2 * tig] = v1;
        }
    }
}

// ============================================================
// fused output conv (unchanged)
// ============================================================
#define CONV_SMEM ((512 * 68 + 2 * 64 * 68) * 4)
__global__ __launch_bounds__(256, 1) void conv_fused_kernel(
    const float* __restrict__ lat, const float* __restrict__ lat2,
    const float* __restrict__ Wo, const float* __restrict__ fm,
    const float* __restrict__ gsa, const float* __restrict__ gmoca,
    float* __restrict__ out)
{
    float* smem = (float*)dyn_smem;
    const uint32_t sb = smem_u32(dyn_smem);

    const int tid  = threadIdx.x;
    const int warp = tid >> 5;
    const int lane = tid & 31;
    const int g    = lane >> 2;
    const int tig  = lane & 3;
    const int b  = blockIdx.y;
    const int n0 = blockIdx.x * 64;

#pragma unroll
    for (int j = 0; j < 32; j++) {
        int idx = tid + j * 256;
        int oc = idx >> 4, l4 = (idx & 15) << 2;
        cp16(sb + (uint32_t)(oc * 68 + l4) * 4, Wo + oc * LL + l4);
    }
#pragma unroll
    for (int j = 0; j < 4; j++) {
        int idx = tid + j * 256;
        int cl = idx >> 4, n4 = (idx & 15) << 2;
        const size_t src = (size_t)b * (NHW * 64) + cl * NHW + n0 + n4;
        cp16(sb + (uint32_t)((512 + cl) * 68 + n4) * 4, lat + src);
        cp16(sb + (uint32_t)((576 + cl) * 68 + n4) * 4, lat2 + src);
    }
    CP_COMMIT();
    CP_WAIT(0);
    __syncthreads();

    float acc[4][8][4];
#pragma unroll
    for (int m = 0; m < 4; m++)
#pragma unroll
        for (int nc = 0; nc < 8; nc++)
#pragma unroll
            for (int r = 0; r < 4; r++) acc[m][nc][r] = 0.f;

    const uint32_t* Wu = (const uint32_t*)smem;
    const float* L1 = smem + 512 * 68;
    const float* L2 = smem + 576 * 68;
    const float cs = gsa[0], cm = gmoca[0];

#pragma unroll
    for (int kk = 0; kk < 8; kk++) {
        uint32_t A[4][4];
#pragma unroll
        for (int m = 0; m < 4; m++) {
            const int oc = 64 * warp + 16 * m;
            A[m][0] = Wu[(oc + g) * 68 + 8 * kk + tig];
            A[m][1] = Wu[(oc + 8 + g) * 68 + 8 * kk + tig];
            A[m][2] = Wu[(oc + g) * 68 + 8 * kk + tig + 4];
            A[m][3] = Wu[(oc + 8 + g) * 68 + 8 * kk + tig + 4];
        }
#pragma unroll
        for (int nc = 0; nc < 8; nc++) {
            const int i0 = (8 * kk + tig) * 68 + 8 * nc + g;
            const int i1 = (8 * kk + tig + 4) * 68 + 8 * nc + g;
            uint32_t b0 = __float_as_uint(cs * L1[i0] + cm * L2[i0]);
            uint32_t b1 = __float_as_uint(cs * L1[i1] + cm * L2[i1]);
#pragma unroll
            for (int m = 0; m < 4; m++) mma168(acc[m][nc], A[m], b0, b1);
        }
    }

#pragma unroll
    for (int m = 0; m < 4; m++)
#pragma unroll
        for (int nc = 0; nc < 8; nc++) {
            const int oc = 64 * warp + 16 * m + g;
            const int n  = n0 + 8 * nc + 2 * tig;
            const size_t base0 = ((size_t)(b * CC + oc)) * NHW + n;
            const size_t base1 = base0 + (size_t)8 * NHW;
            float2 a0 = *(const float2*)&fm[base0];
            float2 a1 = *(const float2*)&fm[base1];
            *(float2*)&out[base0] = make_float2(GAIN_O * acc[m][nc][0] + a0.x,
                                                GAIN_O * acc[m][nc][1] + a0.y);
            *(float2*)&out[base1] = make_float2(GAIN_O * acc[m][nc][2] + a1.x,
                                                GAIN_O * acc[m][nc][3] + a1.y);
        }
}

// ============================================================
extern "C" void kernel_launch(void* const* d_in, const int* in_sizes, int n_in,
                              void* d_out, int out_size)
{
    (void)in_sizes; (void)n_in; (void)out_size;
    const float* fm         = (const float*)d_in[0];
    const float* concepts   = (const float*)d_in[1];
    const float* w_theta    = (const float*)d_in[2];
    const float* w_phi      = (const float*)d_in[3];
    const float* w_g        = (const float*)d_in[4];
    const float* w_o        = (const float*)d_in[5];
    const float* gamma_sa   = (const float*)d_in[6];
    const float* gamma_moca = (const float*)d_in[7];
    float* out = (float*)d_out;

    float *qh, *lat, *enc, *lat2, *Mb, *wr;
    __nv_bfloat16 *qb, *kb, *vb;
    cudaGetSymbolAddress((void**)&qh,  g_qh);
    cudaGetSymbolAddress((void**)&qb,  g_qb);
    cudaGetSymbolAddress((void**)&kb,  g_kb);
    cudaGetSymbolAddress((void**)&vb,  g_vb);
    cudaGetSymbolAddress((void**)&lat, g_lat);
    cudaGetSymbolAddress((void**)&enc, g_enc);
    cudaGetSymbolAddress((void**)&lat2, g_lat2);
    cudaGetSymbolAddress((void**)&Mb,  g_M);
    cudaGetSymbolAddress((void**)&wr,  g_wr);

    cudaFuncSetAttribute(flash_mma_kernel, cudaFuncAttributeMaxDynamicSharedMemorySize, FT_SMEM);
    cudaFuncSetAttribute(proj_qkv_kernel,  cudaFuncAttributeMaxDynamicSharedMemorySize, QKV_SMEM);
    cudaFuncSetAttribute(enc_mma_kernel,   cudaFuncAttributeMaxDynamicSharedMemorySize, ENC_SMEM);
    cudaFuncSetAttribute(conv_fused_kernel, cudaFuncAttributeMaxDynamicSharedMemorySize, CONV_SMEM);
    cudaFuncSetAttribute(moca_mma_kernel,  cudaFuncAttributeMaxDynamicSharedMemorySize, MOCA_SMEM);

    wround_kernel<<<128, 256>>>(w_theta, w_phi, w_g, wr);
    mmat_kernel<<<16, 256>>>(w_theta, w_o, Mb);
    proj_qkv_kernel<<<dim3(32, 8), 256, QKV_SMEM>>>(fm, wr, qh, qb, kb, vb, GAIN_IN);
    flash_mma_kernel<<<dim3(32, 8), 128, FT_SMEM>>>(qb, kb, vb, lat);
    enc_mma_kernel<<<dim3(16, 8), 256, ENC_SMEM>>>(qh, lat, Mb, gamma_sa, enc);
    moca_mma_kernel<<<dim3(16, 8), 256, MOCA_SMEM>>>(enc, concepts, lat2);
    conv_fused_kernel<<<dim3(64, 8), 256, CONV_SMEM>>>(lat, lat2, w_o, fm, gamma_sa, gamma_moca, out);
}